// round 1
// baseline (speedup 1.0000x reference)
#include <cuda_runtime.h>
#include <math.h>

#define BB     8
#define TT     1024
#define DMODEL 512
#define NH     8
#define DHEAD  64
#define HDIM   512
#define LPOS   2047   // 2T-1

// ------------------------- scratch (static device memory) -------------------------
__device__ float g_qu[BB*NH*TT*DHEAD];   // q + u_bias, layout (B,H,T,dh)
__device__ float g_qv[BB*NH*TT*DHEAD];   // q + v_bias
__device__ float g_k [BB*NH*TT*DHEAD];
__device__ float g_v [BB*NH*TT*DHEAD];
__device__ float g_p [NH*LPOS*DHEAD];    // (H, L, dh)
__device__ float g_z [BB*TT*NH*DHEAD];   // (B, T, H, dh)

// ============================================================================
// QKV projection: C = xs @ W, tiles 128x128, BK=8, 8x8 micro, 256 threads.
// blockIdx.z selects Wq/Wk/Wv.  q gets u/v biases added and is written twice.
// ============================================================================
__global__ __launch_bounds__(256, 2)
void qkv_kernel(const float* __restrict__ xs,
                const float* __restrict__ Wq, const float* __restrict__ Wk,
                const float* __restrict__ Wv,
                const float* __restrict__ ub, const float* __restrict__ vb)
{
    __shared__ float As[8][132];   // [kk][m] transposed
    __shared__ float Bs[8][128];   // [kk][n]
    const int which = blockIdx.z;
    const float* W = (which == 0) ? Wq : (which == 1) ? Wk : Wv;
    const int m0 = blockIdx.x * 128;
    const int n0 = blockIdx.y * 128;
    const int tid = threadIdx.x;
    const int ty = tid >> 4, tx = tid & 15;

    float acc[8][8];
#pragma unroll
    for (int i = 0; i < 8; i++)
#pragma unroll
        for (int j = 0; j < 8; j++) acc[i][j] = 0.f;

    const int arow = tid >> 1;
    const int akk  = (tid & 1) * 4;
    const int bkk  = tid >> 5;
    const int bn   = (tid & 31) * 4;

    for (int k0 = 0; k0 < DMODEL; k0 += 8) {
        float4 av = *(const float4*)(xs + (size_t)(m0 + arow) * DMODEL + k0 + akk);
        float4 bv = *(const float4*)(W  + (size_t)(k0 + bkk) * HDIM + n0 + bn);
        As[akk+0][arow] = av.x; As[akk+1][arow] = av.y;
        As[akk+2][arow] = av.z; As[akk+3][arow] = av.w;
        *(float4*)&Bs[bkk][bn] = bv;
        __syncthreads();
#pragma unroll
        for (int kk = 0; kk < 8; kk++) {
            float4 a0 = *(const float4*)&As[kk][ty*8];
            float4 a1 = *(const float4*)&As[kk][ty*8+4];
            float4 b0 = *(const float4*)&Bs[kk][tx*8];
            float4 b1 = *(const float4*)&Bs[kk][tx*8+4];
            float a[8] = {a0.x,a0.y,a0.z,a0.w,a1.x,a1.y,a1.z,a1.w};
            float b[8] = {b0.x,b0.y,b0.z,b0.w,b1.x,b1.y,b1.z,b1.w};
#pragma unroll
            for (int i = 0; i < 8; i++)
#pragma unroll
                for (int j = 0; j < 8; j++) acc[i][j] += a[i]*b[j];
        }
        __syncthreads();
    }

#pragma unroll
    for (int i = 0; i < 8; i++) {
        int m = m0 + ty*8 + i;
        int b = m >> 10, t = m & (TT-1);
        int n = n0 + tx*8;
        int h = n >> 6, d = n & 63;
        size_t o = (((size_t)b*NH + h)*TT + t)*DHEAD + d;
        if (which == 0) {
#pragma unroll
            for (int j = 0; j < 8; j++) {
                g_qu[o+j] = acc[i][j] + ub[n+j];
                g_qv[o+j] = acc[i][j] + vb[n+j];
            }
        } else if (which == 1) {
#pragma unroll
            for (int j = 0; j < 8; j++) g_k[o+j] = acc[i][j];
        } else {
#pragma unroll
            for (int j = 0; j < 8; j++) g_v[o+j] = acc[i][j];
        }
    }
}

// ============================================================================
// Output projection: out = z @ Wout (8192x512x512), same tiling.
// ============================================================================
__global__ __launch_bounds__(256, 2)
void out_kernel(const float* __restrict__ Wout, float* __restrict__ out)
{
    __shared__ float As[8][132];
    __shared__ float Bs[8][128];
    const int m0 = blockIdx.x * 128;
    const int n0 = blockIdx.y * 128;
    const int tid = threadIdx.x;
    const int ty = tid >> 4, tx = tid & 15;

    float acc[8][8];
#pragma unroll
    for (int i = 0; i < 8; i++)
#pragma unroll
        for (int j = 0; j < 8; j++) acc[i][j] = 0.f;

    const int arow = tid >> 1;
    const int akk  = (tid & 1) * 4;
    const int bkk  = tid >> 5;
    const int bn   = (tid & 31) * 4;

    for (int k0 = 0; k0 < HDIM; k0 += 8) {
        float4 av = *(const float4*)(g_z + (size_t)(m0 + arow) * HDIM + k0 + akk);
        float4 bv = *(const float4*)(Wout + (size_t)(k0 + bkk) * DMODEL + n0 + bn);
        As[akk+0][arow] = av.x; As[akk+1][arow] = av.y;
        As[akk+2][arow] = av.z; As[akk+3][arow] = av.w;
        *(float4*)&Bs[bkk][bn] = bv;
        __syncthreads();
#pragma unroll
        for (int kk = 0; kk < 8; kk++) {
            float4 a0 = *(const float4*)&As[kk][ty*8];
            float4 a1 = *(const float4*)&As[kk][ty*8+4];
            float4 b0 = *(const float4*)&Bs[kk][tx*8];
            float4 b1 = *(const float4*)&Bs[kk][tx*8+4];
            float a[8] = {a0.x,a0.y,a0.z,a0.w,a1.x,a1.y,a1.z,a1.w};
            float b[8] = {b0.x,b0.y,b0.z,b0.w,b1.x,b1.y,b1.z,b1.w};
#pragma unroll
            for (int i = 0; i < 8; i++)
#pragma unroll
                for (int j = 0; j < 8; j++) acc[i][j] += a[i]*b[j];
        }
        __syncthreads();
    }

#pragma unroll
    for (int i = 0; i < 8; i++) {
        int m = m0 + ty*8 + i;
        float* dst = out + (size_t)m * DMODEL + n0 + tx*8;
        *(float4*)(dst)     = make_float4(acc[i][0], acc[i][1], acc[i][2], acc[i][3]);
        *(float4*)(dst + 4) = make_float4(acc[i][4], acc[i][5], acc[i][6], acc[i][7]);
    }
}

// ============================================================================
// Positional projection: p = pe @ Wpos, pe generated on the fly.
// M=2047 (guarded), 64x64 tiles, BK=16, 4x4 micro.
// ============================================================================
__global__ __launch_bounds__(256, 2)
void pos_kernel(const float* __restrict__ Wpos)
{
    __shared__ float As[16][68];
    __shared__ float Bs[16][64];
    const int m0 = blockIdx.x * 64;
    const int n0 = blockIdx.y * 64;
    const int tid = threadIdx.x;
    const int ty = tid >> 4, tx = tid & 15;

    float acc[4][4];
#pragma unroll
    for (int i = 0; i < 4; i++)
#pragma unroll
        for (int j = 0; j < 4; j++) acc[i][j] = 0.f;

    const int arow = tid >> 2;
    const int akk  = (tid & 3) * 4;
    const int bn   = tid & 63;
    const int bkk0 = tid >> 6;
    const float LN1E4 = 9.210340371976184f;

    const int m = m0 + arow;
    const float pos = (float)(m - (TT - 1));

    for (int k0 = 0; k0 < DMODEL; k0 += 16) {
#pragma unroll
        for (int j = 0; j < 4; j++) {
            int c = k0 + akk + j;
            float freq = expf(-LN1E4 * (float)(c & ~1) / (float)DMODEL);
            float ang = pos * freq;
            As[akk+j][arow] = (m < LPOS) ? ((c & 1) ? cosf(ang) : sinf(ang)) : 0.f;
        }
#pragma unroll
        for (int r = 0; r < 4; r++)
            Bs[bkk0 + 4*r][bn] = Wpos[(size_t)(k0 + bkk0 + 4*r) * HDIM + n0 + bn];
        __syncthreads();
#pragma unroll
        for (int kk = 0; kk < 16; kk++) {
            float4 a = *(const float4*)&As[kk][ty*4];
            float4 b = *(const float4*)&Bs[kk][tx*4];
            float av[4] = {a.x,a.y,a.z,a.w};
            float bv[4] = {b.x,b.y,b.z,b.w};
#pragma unroll
            for (int i = 0; i < 4; i++)
#pragma unroll
                for (int j = 0; j < 4; j++) acc[i][j] += av[i]*bv[j];
        }
        __syncthreads();
    }

#pragma unroll
    for (int i = 0; i < 4; i++) {
        int l = m0 + ty*4 + i;
        if (l >= LPOS) continue;
        int n = n0 + tx*4;
        int h = n >> 6, d = n & 63;
        *(float4*)&g_p[((size_t)h*LPOS + l)*DHEAD + d] =
            make_float4(acc[i][0], acc[i][1], acc[i][2], acc[i][3]);
    }
}

// ============================================================================
// Fused attention: per-CTA 64-query block, flash-style online softmax.
//   S[t,s] = (q_u[t].k[s] + q_v[t].p[s-t+T-1]) * scale   (bd via band-GEMM + shift)
// grid (T/64, B*H), 256 threads, ~151 KB dynamic smem.
// ============================================================================
#define ATTN_SMEM ((5*64*68 + 2*64*132) * 4)

__global__ __launch_bounds__(256, 1)
void attn_kernel(const int* __restrict__ mask)
{
    extern __shared__ float sm[];
    float* sQu = sm;               // [d][i]  64x68
    float* sQv = sQu + 64*68;      // [d][i]
    float* sK  = sQv + 64*68;      // [d][j]
    float* sV  = sK  + 64*68;      // [j][n]
    float* sP  = sV  + 64*68;      // [d][l]  64x132 (127 band rows + zero col)
    float* sBD = sP  + 64*132;     // [i][l]  64x132
    float* sS  = sBD + 64*132;     // [i][j]  64x68

    const int tid = threadIdx.x;
    const int ty = tid >> 4, tx = tid & 15;
    const int t0 = blockIdx.x * 64;
    const int bh = blockIdx.y;
    const int b = bh >> 3, h = bh & 7;

    const float* qu = g_qu + ((size_t)bh * TT + t0) * DHEAD;
    const float* qv = g_qv + ((size_t)bh * TT + t0) * DHEAD;
    const float* kp = g_k  + (size_t)bh * TT * DHEAD;
    const float* vp = g_v  + (size_t)bh * TT * DHEAD;
    const float* pp = g_p  + (size_t)h * LPOS * DHEAD;

    // load Q blocks (transposed [d][row])
#pragma unroll
    for (int r = 0; r < 4; r++) {
        int e = tid + r * 256;
        int row = e >> 4, d4 = (e & 15) * 4;
        float4 a = *(const float4*)(qu + row * DHEAD + d4);
        sQu[(d4+0)*68 + row] = a.x; sQu[(d4+1)*68 + row] = a.y;
        sQu[(d4+2)*68 + row] = a.z; sQu[(d4+3)*68 + row] = a.w;
        float4 c = *(const float4*)(qv + row * DHEAD + d4);
        sQv[(d4+0)*68 + row] = c.x; sQv[(d4+1)*68 + row] = c.y;
        sQv[(d4+2)*68 + row] = c.z; sQv[(d4+3)*68 + row] = c.w;
    }

    float o_acc[4][4];
    float rmax[4], rsum[4];
#pragma unroll
    for (int i = 0; i < 4; i++) {
        rmax[i] = -1e30f; rsum[i] = 0.f;
#pragma unroll
        for (int j = 0; j < 4; j++) o_acc[i][j] = 0.f;
    }

    for (int s0 = 0; s0 < TT; s0 += 64) {
        const int l0 = s0 - t0 + (TT - 64);   // base p-row of the 127-wide band

        // load K (transposed) and V (row-major)
#pragma unroll
        for (int r = 0; r < 4; r++) {
            int e = tid + r * 256;
            int row = e >> 4, d4 = (e & 15) * 4;
            float4 a = *(const float4*)(kp + (size_t)(s0 + row) * DHEAD + d4);
            sK[(d4+0)*68 + row] = a.x; sK[(d4+1)*68 + row] = a.y;
            sK[(d4+2)*68 + row] = a.z; sK[(d4+3)*68 + row] = a.w;
            float4 v4 = *(const float4*)(vp + (size_t)(s0 + row) * DHEAD + d4);
            *(float4*)&sV[row*68 + d4] = v4;
        }
        // load P band: 127 rows (transposed)
#pragma unroll
        for (int r = 0; r < 8; r++) {
            int e = tid + r * 256;
            if (e < 127 * 16) {
                int row = e >> 4, d4 = (e & 15) * 4;
                float4 a = *(const float4*)(pp + (size_t)(l0 + row) * DHEAD + d4);
                sP[(d4+0)*132 + row] = a.x; sP[(d4+1)*132 + row] = a.y;
                sP[(d4+2)*132 + row] = a.z; sP[(d4+3)*132 + row] = a.w;
            }
        }
        if (tid < 64) sP[tid*132 + 127] = 0.f;
        __syncthreads();

        // GEMM1 (ac, 64x64x64) + GEMM2 (bd band, 64x128x64)
        float acc1[4][4];
        float acc2[4][8];
#pragma unroll
        for (int i = 0; i < 4; i++) {
#pragma unroll
            for (int j = 0; j < 4; j++) acc1[i][j] = 0.f;
#pragma unroll
            for (int j = 0; j < 8; j++) acc2[i][j] = 0.f;
        }
#pragma unroll 4
        for (int d = 0; d < 64; d++) {
            float4 aU = *(const float4*)&sQu[d*68 + ty*4];
            float4 aV = *(const float4*)&sQv[d*68 + ty*4];
            float4 bK = *(const float4*)&sK [d*68 + tx*4];
            float4 p0 = *(const float4*)&sP [d*132 + tx*8];
            float4 p1 = *(const float4*)&sP [d*132 + tx*8 + 4];
            float au[4] = {aU.x,aU.y,aU.z,aU.w};
            float av[4] = {aV.x,aV.y,aV.z,aV.w};
            float bk[4] = {bK.x,bK.y,bK.z,bK.w};
            float pb[8] = {p0.x,p0.y,p0.z,p0.w,p1.x,p1.y,p1.z,p1.w};
#pragma unroll
            for (int i = 0; i < 4; i++) {
#pragma unroll
                for (int j = 0; j < 4; j++) acc1[i][j] += au[i]*bk[j];
#pragma unroll
                for (int j = 0; j < 8; j++) acc2[i][j] += av[i]*pb[j];
            }
        }
        // stage bd band to smem for the shift read
#pragma unroll
        for (int i = 0; i < 4; i++) {
            int row = ty*4 + i;
            *(float4*)&sBD[row*132 + tx*8]     = make_float4(acc2[i][0],acc2[i][1],acc2[i][2],acc2[i][3]);
            *(float4*)&sBD[row*132 + tx*8 + 4] = make_float4(acc2[i][4],acc2[i][5],acc2[i][6],acc2[i][7]);
        }
        __syncthreads();

        // combine + mask + online softmax
#pragma unroll
        for (int i = 0; i < 4; i++) {
            int irow = ty*4 + i;
            int4 mv = *(const int4*)(mask + ((size_t)b*TT + t0 + irow) * TT + s0 + tx*4);
            int mvi[4] = {mv.x, mv.y, mv.z, mv.w};
            float s[4];
#pragma unroll
            for (int j = 0; j < 4; j++) {
                int jcol = tx*4 + j;
                float val = (acc1[i][j] + sBD[irow*132 + (jcol - irow + 63)]) * 0.125f;
                s[j] = (mvi[j] == 0) ? -1e30f : val;
            }
            float tm = fmaxf(fmaxf(s[0], s[1]), fmaxf(s[2], s[3]));
#pragma unroll
            for (int off = 8; off >= 1; off >>= 1)
                tm = fmaxf(tm, __shfl_xor_sync(0xffffffffu, tm, off));
            float nm = fmaxf(rmax[i], tm);
            float corr = __expf(rmax[i] - nm);
            rmax[i] = nm;
            float ts = 0.f;
#pragma unroll
            for (int j = 0; j < 4; j++) { s[j] = __expf(s[j] - nm); ts += s[j]; }
#pragma unroll
            for (int off = 8; off >= 1; off >>= 1)
                ts += __shfl_xor_sync(0xffffffffu, ts, off);
            rsum[i] = rsum[i]*corr + ts;
#pragma unroll
            for (int j = 0; j < 4; j++) o_acc[i][j] *= corr;
            *(float4*)&sS[irow*68 + tx*4] = make_float4(s[0], s[1], s[2], s[3]);
        }
        __syncthreads();

        // PV: o += P @ V
#pragma unroll 4
        for (int j = 0; j < 64; j++) {
            float4 bv = *(const float4*)&sV[j*68 + tx*4];
            float vb4[4] = {bv.x, bv.y, bv.z, bv.w};
#pragma unroll
            for (int i = 0; i < 4; i++) {
                float a = sS[(ty*4+i)*68 + j];
#pragma unroll
                for (int n = 0; n < 4; n++) o_acc[i][n] += a * vb4[n];
            }
        }
        __syncthreads();
    }

    // normalize + write z in (B,T,H,dh)
#pragma unroll
    for (int i = 0; i < 4; i++) {
        float inv = 1.f / rsum[i];
        int t = t0 + ty*4 + i;
        *(float4*)&g_z[(((size_t)b*TT + t)*NH + h)*DHEAD + tx*4] =
            make_float4(o_acc[i][0]*inv, o_acc[i][1]*inv, o_acc[i][2]*inv, o_acc[i][3]*inv);
    }
}

// ============================================================================
extern "C" void kernel_launch(void* const* d_in, const int* in_sizes, int n_in,
                              void* d_out, int out_size)
{
    const float* xs   = (const float*)d_in[0];
    const int*   mask = (const int*)  d_in[1];
    const float* Wq   = (const float*)d_in[2];
    const float* Wk   = (const float*)d_in[3];
    const float* Wv   = (const float*)d_in[4];
    const float* Wpos = (const float*)d_in[5];
    const float* Wout = (const float*)d_in[6];
    const float* ub   = (const float*)d_in[7];
    const float* vb   = (const float*)d_in[8];
    float* out = (float*)d_out;

    cudaFuncSetAttribute(attn_kernel, cudaFuncAttributeMaxDynamicSharedMemorySize, ATTN_SMEM);

    qkv_kernel<<<dim3(64, 4, 3), 256>>>(xs, Wq, Wk, Wv, ub, vb);
    pos_kernel<<<dim3(32, 8), 256>>>(Wpos);
    attn_kernel<<<dim3(16, 64), 256, ATTN_SMEM>>>(mask);
    out_kernel<<<dim3(64, 4), 256>>>(Wout, out);
}

// round 2
// speedup vs baseline: 2.2764x; 2.2764x over previous
#include <cuda_runtime.h>
#include <math.h>
#include <stdint.h>

#define BB     8
#define TT     1024
#define DMODEL 512
#define NH     8
#define DHEAD  64
#define HDIM   512
#define LPOS   2047   // 2T-1

// ------------------------- scratch (static device memory) -------------------------
__device__ float g_qu[BB*NH*TT*DHEAD];   // q + u_bias, layout (B,H,T,dh)
__device__ float g_qv[BB*NH*TT*DHEAD];   // q + v_bias
__device__ float g_k [BB*NH*TT*DHEAD];
__device__ float g_v [BB*NH*TT*DHEAD];
__device__ float g_p [NH*LPOS*DHEAD];    // (H, L, dh)
__device__ float g_z [BB*TT*NH*DHEAD];   // (B, T, H, dh)

// ------------------------- tf32 mma helpers -------------------------
__device__ __forceinline__ uint32_t f2tf(float x) {
    uint32_t r;
    asm("cvt.rna.tf32.f32 %0, %1;" : "=r"(r) : "f"(x));
    return r;
}

// D = A(16x8) * B(8x8) + D, tf32 inputs, f32 accum
__device__ __forceinline__ void mma8(float* c, const uint32_t* a, uint32_t b0, uint32_t b1) {
    asm volatile(
        "mma.sync.aligned.m16n8k8.row.col.f32.tf32.tf32.f32 "
        "{%0,%1,%2,%3}, {%4,%5,%6,%7}, {%8,%9}, {%0,%1,%2,%3};"
        : "+f"(c[0]), "+f"(c[1]), "+f"(c[2]), "+f"(c[3])
        : "r"(a[0]), "r"(a[1]), "r"(a[2]), "r"(a[3]), "r"(b0), "r"(b1));
}

// ============================================================================
// QKV projection (tensor core): C = xs @ W, 128x128 tile, K-stage 32.
// 256 threads = 8 warps (2x4 warp grid: warp tile 32m x 64n).
// ============================================================================
__global__ __launch_bounds__(256, 2)
void qkv_tc(const float* __restrict__ xs,
            const float* __restrict__ Wq, const float* __restrict__ Wk,
            const float* __restrict__ Wv,
            const float* __restrict__ ub, const float* __restrict__ vb)
{
    __shared__ float sA[128*36];   // [m][k] tf32 bits
    __shared__ float sB[128*36];   // [n][k] tf32 bits (transposed)
    const int which = blockIdx.z;
    const float* W = (which == 0) ? Wq : (which == 1) ? Wk : Wv;
    const int m0 = blockIdx.x * 128;
    const int n0 = blockIdx.y * 128;
    const int tid = threadIdx.x, lane = tid & 31, warp = tid >> 5;
    const int g = lane >> 2, c = lane & 3;
    const int wm = warp >> 1, wn = warp & 1;

    float acc[2][8][4] = {};

    const int arow = tid >> 3, ac4 = (tid & 7) * 4;
    const int bk = tid >> 5, bn4 = (tid & 31) * 4;
    uint32_t* uA = (uint32_t*)sA;
    uint32_t* uB = (uint32_t*)sB;

    for (int k0 = 0; k0 < DMODEL; k0 += 32) {
        // A tile 128x32
#pragma unroll
        for (int p = 0; p < 4; p++) {
            int r = p * 32 + arow;
            float4 v = *(const float4*)(xs + (size_t)(m0 + r) * DMODEL + k0 + ac4);
            uint4 u = make_uint4(f2tf(v.x), f2tf(v.y), f2tf(v.z), f2tf(v.w));
            *(uint4*)&uA[r*36 + ac4] = u;
        }
        // B tile 32x128 -> transposed [n][k]
#pragma unroll
        for (int p = 0; p < 4; p++) {
            int k = p * 8 + bk;
            float4 v = *(const float4*)(W + (size_t)(k0 + k) * HDIM + n0 + bn4);
            uB[(bn4+0)*36 + k] = f2tf(v.x);
            uB[(bn4+1)*36 + k] = f2tf(v.y);
            uB[(bn4+2)*36 + k] = f2tf(v.z);
            uB[(bn4+3)*36 + k] = f2tf(v.w);
        }
        __syncthreads();
#pragma unroll
        for (int kk = 0; kk < 4; kk++) {
            uint32_t a[2][4], b[8][2];
#pragma unroll
            for (int mt = 0; mt < 2; mt++) {
                int r = wm*32 + mt*16 + g;
                a[mt][0] = uA[r*36 + kk*8 + c];
                a[mt][1] = uA[(r+8)*36 + kk*8 + c];
                a[mt][2] = uA[r*36 + kk*8 + c + 4];
                a[mt][3] = uA[(r+8)*36 + kk*8 + c + 4];
            }
#pragma unroll
            for (int nt = 0; nt < 8; nt++) {
                int nn = wn*64 + nt*8 + g;
                b[nt][0] = uB[nn*36 + kk*8 + c];
                b[nt][1] = uB[nn*36 + kk*8 + c + 4];
            }
#pragma unroll
            for (int mt = 0; mt < 2; mt++)
#pragma unroll
                for (int nt = 0; nt < 8; nt++) mma8(acc[mt][nt], a[mt], b[nt][0], b[nt][1]);
        }
        __syncthreads();
    }

#pragma unroll
    for (int mt = 0; mt < 2; mt++) {
#pragma unroll
        for (int nt = 0; nt < 8; nt++) {
            int n = n0 + wn*64 + nt*8 + 2*c;
            int h = n >> 6, d = n & 63;
#pragma unroll
            for (int half = 0; half < 2; half++) {
                int m = m0 + wm*32 + mt*16 + g + half*8;
                int bidx = m >> 10, t = m & (TT-1);
                size_t o = (((size_t)bidx*NH + h)*TT + t)*DHEAD + d;
                float v0 = acc[mt][nt][half*2+0], v1 = acc[mt][nt][half*2+1];
                if (which == 0) {
                    *(float2*)&g_qu[o] = make_float2(v0 + ub[n], v1 + ub[n+1]);
                    *(float2*)&g_qv[o] = make_float2(v0 + vb[n], v1 + vb[n+1]);
                } else if (which == 1) {
                    *(float2*)&g_k[o] = make_float2(v0, v1);
                } else {
                    *(float2*)&g_v[o] = make_float2(v0, v1);
                }
            }
        }
    }
}

// ============================================================================
// Output projection (tensor core): out = z @ Wout.
// ============================================================================
__global__ __launch_bounds__(256, 2)
void out_tc(const float* __restrict__ Wout, float* __restrict__ out)
{
    __shared__ float sA[128*36];
    __shared__ float sB[128*36];
    const int m0 = blockIdx.x * 128;
    const int n0 = blockIdx.y * 128;
    const int tid = threadIdx.x, lane = tid & 31, warp = tid >> 5;
    const int g = lane >> 2, c = lane & 3;
    const int wm = warp >> 1, wn = warp & 1;

    float acc[2][8][4] = {};

    const int arow = tid >> 3, ac4 = (tid & 7) * 4;
    const int bk = tid >> 5, bn4 = (tid & 31) * 4;
    uint32_t* uA = (uint32_t*)sA;
    uint32_t* uB = (uint32_t*)sB;

    for (int k0 = 0; k0 < HDIM; k0 += 32) {
#pragma unroll
        for (int p = 0; p < 4; p++) {
            int r = p * 32 + arow;
            float4 v = *(const float4*)(g_z + (size_t)(m0 + r) * HDIM + k0 + ac4);
            uint4 u = make_uint4(f2tf(v.x), f2tf(v.y), f2tf(v.z), f2tf(v.w));
            *(uint4*)&uA[r*36 + ac4] = u;
        }
#pragma unroll
        for (int p = 0; p < 4; p++) {
            int k = p * 8 + bk;
            float4 v = *(const float4*)(Wout + (size_t)(k0 + k) * DMODEL + n0 + bn4);
            uB[(bn4+0)*36 + k] = f2tf(v.x);
            uB[(bn4+1)*36 + k] = f2tf(v.y);
            uB[(bn4+2)*36 + k] = f2tf(v.z);
            uB[(bn4+3)*36 + k] = f2tf(v.w);
        }
        __syncthreads();
#pragma unroll
        for (int kk = 0; kk < 4; kk++) {
            uint32_t a[2][4], b[8][2];
#pragma unroll
            for (int mt = 0; mt < 2; mt++) {
                int r = wm*32 + mt*16 + g;
                a[mt][0] = uA[r*36 + kk*8 + c];
                a[mt][1] = uA[(r+8)*36 + kk*8 + c];
                a[mt][2] = uA[r*36 + kk*8 + c + 4];
                a[mt][3] = uA[(r+8)*36 + kk*8 + c + 4];
            }
#pragma unroll
            for (int nt = 0; nt < 8; nt++) {
                int nn = wn*64 + nt*8 + g;
                b[nt][0] = uB[nn*36 + kk*8 + c];
                b[nt][1] = uB[nn*36 + kk*8 + c + 4];
            }
#pragma unroll
            for (int mt = 0; mt < 2; mt++)
#pragma unroll
                for (int nt = 0; nt < 8; nt++) mma8(acc[mt][nt], a[mt], b[nt][0], b[nt][1]);
        }
        __syncthreads();
    }

#pragma unroll
    for (int mt = 0; mt < 2; mt++) {
#pragma unroll
        for (int nt = 0; nt < 8; nt++) {
            int n = n0 + wn*64 + nt*8 + 2*c;
#pragma unroll
            for (int half = 0; half < 2; half++) {
                int m = m0 + wm*32 + mt*16 + g + half*8;
                *(float2*)&out[(size_t)m*DMODEL + n] =
                    make_float2(acc[mt][nt][half*2+0], acc[mt][nt][half*2+1]);
            }
        }
    }
}

// ============================================================================
// Positional projection (SIMT fp32, exact): p = pe @ Wpos on the fly.
// ============================================================================
__global__ __launch_bounds__(256, 2)
void pos_kernel(const float* __restrict__ Wpos)
{
    __shared__ float As[16][68];
    __shared__ float Bs[16][64];
    const int m0 = blockIdx.x * 64;
    const int n0 = blockIdx.y * 64;
    const int tid = threadIdx.x;
    const int ty = tid >> 4, tx = tid & 15;

    float acc[4][4];
#pragma unroll
    for (int i = 0; i < 4; i++)
#pragma unroll
        for (int j = 0; j < 4; j++) acc[i][j] = 0.f;

    const int arow = tid >> 2;
    const int akk  = (tid & 3) * 4;
    const int bn   = tid & 63;
    const int bkk0 = tid >> 6;
    const float LN1E4 = 9.210340371976184f;

    const int m = m0 + arow;
    const float pos = (float)(m - (TT - 1));

    for (int k0 = 0; k0 < DMODEL; k0 += 16) {
#pragma unroll
        for (int j = 0; j < 4; j++) {
            int cc = k0 + akk + j;
            float freq = expf(-LN1E4 * (float)(cc & ~1) / (float)DMODEL);
            float ang = pos * freq;
            As[akk+j][arow] = (m < LPOS) ? ((cc & 1) ? cosf(ang) : sinf(ang)) : 0.f;
        }
#pragma unroll
        for (int r = 0; r < 4; r++)
            Bs[bkk0 + 4*r][bn] = Wpos[(size_t)(k0 + bkk0 + 4*r) * HDIM + n0 + bn];
        __syncthreads();
#pragma unroll
        for (int kk = 0; kk < 16; kk++) {
            float4 a = *(const float4*)&As[kk][ty*4];
            float4 b = *(const float4*)&Bs[kk][tx*4];
            float av[4] = {a.x,a.y,a.z,a.w};
            float bv[4] = {b.x,b.y,b.z,b.w};
#pragma unroll
            for (int i = 0; i < 4; i++)
#pragma unroll
                for (int j = 0; j < 4; j++) acc[i][j] += av[i]*bv[j];
        }
        __syncthreads();
    }

#pragma unroll
    for (int i = 0; i < 4; i++) {
        int l = m0 + ty*4 + i;
        if (l >= LPOS) continue;
        int n = n0 + tx*4;
        int h = n >> 6, d = n & 63;
        *(float4*)&g_p[((size_t)h*LPOS + l)*DHEAD + d] =
            make_float4(acc[i][0], acc[i][1], acc[i][2], acc[i][3]);
    }
}

// ============================================================================
// Fused attention (tensor core, tf32 mma): 64-q block, flash softmax.
// 128 threads = 4 warps, each warp owns 16 query rows (one m16 tile).
// smem: sK[64][68] sVt[64][68] sS[64][68] sP[128][68] sBD[64][132] sM[64][68]
// ============================================================================
#define ATTN_SMEM ((3*64*68 + 128*68 + 64*132 + 64*68) * 4)

__global__ __launch_bounds__(128, 1)
void attn_tc(const int* __restrict__ mask)
{
    extern __shared__ float sm[];
    float* sK  = sm;                  // [s][d] tf32 bits
    float* sVt = sK  + 64*68;         // [d][s] tf32 bits
    float* sS  = sVt + 64*68;         // staging / exp(S) [t][s]
    float* sP  = sS  + 64*68;         // [l][d] tf32 bits (band, 128 rows)
    float* sBD = sP  + 128*68;        // [t][l] f32
    int*   sM  = (int*)(sBD + 64*132);// [t][s]

    uint32_t* uK  = (uint32_t*)sK;
    uint32_t* uVt = (uint32_t*)sVt;
    uint32_t* uS  = (uint32_t*)sS;
    uint32_t* uP  = (uint32_t*)sP;

    const int tid = threadIdx.x, lane = tid & 31, warp = tid >> 5;
    const int g = lane >> 2, c = lane & 3;
    const int t0 = blockIdx.x * 64;
    const int bh = blockIdx.y;
    const int b = bh >> 3, h = bh & 7;
    const int rl = warp*16 + g;       // low row (block-local)
    const int rh = rl + 8;            // high row

    const float* qu = g_qu + ((size_t)bh * TT + t0) * DHEAD;
    const float* qv = g_qv + ((size_t)bh * TT + t0) * DHEAD;
    const float* kp = g_k  + (size_t)bh * TT * DHEAD;
    const float* vp = g_v  + (size_t)bh * TT * DHEAD;
    const float* pp = g_p  + (size_t)h * LPOS * DHEAD;

    // ---- stage Q fragments into registers (loop-invariant) ----
    uint32_t quf[8][4], qvf[8][4];
#pragma unroll
    for (int r = 0; r < 8; r++) {
        int e = tid + r*128, row = e >> 4, c4 = (e & 15) * 4;
        *(float4*)&sS[row*68 + c4] = *(const float4*)(qu + row*DHEAD + c4);
    }
    __syncthreads();
#pragma unroll
    for (int kk = 0; kk < 8; kk++) {
        quf[kk][0] = f2tf(sS[rl*68 + kk*8 + c]);
        quf[kk][1] = f2tf(sS[rh*68 + kk*8 + c]);
        quf[kk][2] = f2tf(sS[rl*68 + kk*8 + c + 4]);
        quf[kk][3] = f2tf(sS[rh*68 + kk*8 + c + 4]);
    }
    __syncthreads();
#pragma unroll
    for (int r = 0; r < 8; r++) {
        int e = tid + r*128, row = e >> 4, c4 = (e & 15) * 4;
        *(float4*)&sS[row*68 + c4] = *(const float4*)(qv + row*DHEAD + c4);
    }
    __syncthreads();
#pragma unroll
    for (int kk = 0; kk < 8; kk++) {
        qvf[kk][0] = f2tf(sS[rl*68 + kk*8 + c]);
        qvf[kk][1] = f2tf(sS[rh*68 + kk*8 + c]);
        qvf[kk][2] = f2tf(sS[rl*68 + kk*8 + c + 4]);
        qvf[kk][3] = f2tf(sS[rh*68 + kk*8 + c + 4]);
    }

    float o[8][4] = {};
    float rmax_lo = -1e30f, rmax_hi = -1e30f;
    float rsum_lo = 0.f, rsum_hi = 0.f;

    for (int s0 = 0; s0 < TT; s0 += 64) {
        const int l0 = s0 - t0 + (TT - 64);   // band base in p rows

        __syncthreads();   // previous iteration done with shared tiles
        // ---- load K (row-major) and V (transposed) ----
#pragma unroll
        for (int r = 0; r < 8; r++) {
            int e = tid + r*128, row = e >> 4, c4 = (e & 15) * 4;
            float4 v = *(const float4*)(kp + (size_t)(s0 + row)*DHEAD + c4);
            *(uint4*)&uK[row*68 + c4] = make_uint4(f2tf(v.x), f2tf(v.y), f2tf(v.z), f2tf(v.w));
            float4 w = *(const float4*)(vp + (size_t)(s0 + row)*DHEAD + c4);
            uVt[(c4+0)*68 + row] = f2tf(w.x);
            uVt[(c4+1)*68 + row] = f2tf(w.y);
            uVt[(c4+2)*68 + row] = f2tf(w.z);
            uVt[(c4+3)*68 + row] = f2tf(w.w);
        }
        // ---- load P band (127 rows + zero row) ----
#pragma unroll
        for (int r = 0; r < 16; r++) {
            int e = tid + r*128, row = e >> 4, c4 = (e & 15) * 4;
            uint4 u = make_uint4(0u, 0u, 0u, 0u);
            if (row < 127) {
                float4 v = *(const float4*)(pp + (size_t)(l0 + row)*DHEAD + c4);
                u = make_uint4(f2tf(v.x), f2tf(v.y), f2tf(v.z), f2tf(v.w));
            }
            *(uint4*)&uP[row*68 + c4] = u;
        }
        // ---- load mask tile ----
#pragma unroll
        for (int r = 0; r < 8; r++) {
            int e = tid + r*128, row = e >> 4, c4 = (e & 15) * 4;
            *(int4*)&sM[row*68 + c4] =
                *(const int4*)(mask + ((size_t)b*TT + t0 + row)*TT + s0 + c4);
        }
        __syncthreads();

        // ---- BD band GEMM (64 x 128 x 64), two 64-wide halves ----
#pragma unroll
        for (int half = 0; half < 2; half++) {
            float bd[8][4] = {};
#pragma unroll
            for (int kk = 0; kk < 8; kk++) {
#pragma unroll
                for (int nt = 0; nt < 8; nt++) {
                    int nn = half*64 + nt*8 + g;
                    uint32_t b0 = uP[nn*68 + kk*8 + c];
                    uint32_t b1 = uP[nn*68 + kk*8 + c + 4];
                    mma8(bd[nt], qvf[kk], b0, b1);
                }
            }
#pragma unroll
            for (int nt = 0; nt < 8; nt++) {
                int cb = half*64 + nt*8 + 2*c;
                sBD[rl*132 + cb]   = bd[nt][0];
                sBD[rl*132 + cb+1] = bd[nt][1];
                sBD[rh*132 + cb]   = bd[nt][2];
                sBD[rh*132 + cb+1] = bd[nt][3];
            }
        }
        __syncwarp();

        // ---- AC GEMM (64 x 64 x 64) ----
        float acc[8][4] = {};
#pragma unroll
        for (int kk = 0; kk < 8; kk++) {
#pragma unroll
            for (int nt = 0; nt < 8; nt++) {
                int nn = nt*8 + g;
                uint32_t b0 = uK[nn*68 + kk*8 + c];
                uint32_t b1 = uK[nn*68 + kk*8 + c + 4];
                mma8(acc[nt], quf[kk], b0, b1);
            }
        }

        // ---- combine ac + shifted bd, mask, scale ----
        float mx_lo = -1e30f, mx_hi = -1e30f;
#pragma unroll
        for (int nt = 0; nt < 8; nt++) {
            int cb = nt*8 + 2*c;
            float v;
            v = (acc[nt][0] + sBD[rl*132 + cb   - rl + 63]) * 0.125f;
            acc[nt][0] = sM[rl*68 + cb]   ? v : -1e30f;
            v = (acc[nt][1] + sBD[rl*132 + cb+1 - rl + 63]) * 0.125f;
            acc[nt][1] = sM[rl*68 + cb+1] ? v : -1e30f;
            v = (acc[nt][2] + sBD[rh*132 + cb   - rh + 63]) * 0.125f;
            acc[nt][2] = sM[rh*68 + cb]   ? v : -1e30f;
            v = (acc[nt][3] + sBD[rh*132 + cb+1 - rh + 63]) * 0.125f;
            acc[nt][3] = sM[rh*68 + cb+1] ? v : -1e30f;
            mx_lo = fmaxf(mx_lo, fmaxf(acc[nt][0], acc[nt][1]));
            mx_hi = fmaxf(mx_hi, fmaxf(acc[nt][2], acc[nt][3]));
        }
        mx_lo = fmaxf(mx_lo, __shfl_xor_sync(0xffffffffu, mx_lo, 1));
        mx_lo = fmaxf(mx_lo, __shfl_xor_sync(0xffffffffu, mx_lo, 2));
        mx_hi = fmaxf(mx_hi, __shfl_xor_sync(0xffffffffu, mx_hi, 1));
        mx_hi = fmaxf(mx_hi, __shfl_xor_sync(0xffffffffu, mx_hi, 2));

        float nm_lo = fmaxf(rmax_lo, mx_lo);
        float nm_hi = fmaxf(rmax_hi, mx_hi);
        float corr_lo = __expf(rmax_lo - nm_lo);
        float corr_hi = __expf(rmax_hi - nm_hi);
        rmax_lo = nm_lo; rmax_hi = nm_hi;

        float ts_lo = 0.f, ts_hi = 0.f;
#pragma unroll
        for (int nt = 0; nt < 8; nt++) {
            int cb = nt*8 + 2*c;
            float p0 = __expf(acc[nt][0] - nm_lo);
            float p1 = __expf(acc[nt][1] - nm_lo);
            float p2 = __expf(acc[nt][2] - nm_hi);
            float p3 = __expf(acc[nt][3] - nm_hi);
            ts_lo += p0 + p1; ts_hi += p2 + p3;
            uS[rl*68 + cb]   = f2tf(p0);
            uS[rl*68 + cb+1] = f2tf(p1);
            uS[rh*68 + cb]   = f2tf(p2);
            uS[rh*68 + cb+1] = f2tf(p3);
            o[nt][0] *= corr_lo; o[nt][1] *= corr_lo;
            o[nt][2] *= corr_hi; o[nt][3] *= corr_hi;
        }
        ts_lo += __shfl_xor_sync(0xffffffffu, ts_lo, 1);
        ts_lo += __shfl_xor_sync(0xffffffffu, ts_lo, 2);
        ts_hi += __shfl_xor_sync(0xffffffffu, ts_hi, 1);
        ts_hi += __shfl_xor_sync(0xffffffffu, ts_hi, 2);
        rsum_lo = rsum_lo * corr_lo + ts_lo;
        rsum_hi = rsum_hi * corr_hi + ts_hi;
        __syncwarp();

        // ---- PV GEMM: O += exp(S) @ V ----
#pragma unroll
        for (int kk = 0; kk < 8; kk++) {
            uint32_t a[4];
            a[0] = uS[rl*68 + kk*8 + c];
            a[1] = uS[rh*68 + kk*8 + c];
            a[2] = uS[rl*68 + kk*8 + c + 4];
            a[3] = uS[rh*68 + kk*8 + c + 4];
#pragma unroll
            for (int nt = 0; nt < 8; nt++) {
                int nn = nt*8 + g;
                uint32_t b0 = uVt[nn*68 + kk*8 + c];
                uint32_t b1 = uVt[nn*68 + kk*8 + c + 4];
                mma8(o[nt], a, b0, b1);
            }
        }
    }

    // ---- normalize + write z (B,T,H,dh) ----
    float inv_lo = 1.f / rsum_lo, inv_hi = 1.f / rsum_hi;
#pragma unroll
    for (int nt = 0; nt < 8; nt++) {
        int d = nt*8 + 2*c;
        *(float2*)&g_z[(((size_t)b*TT + (t0+rl))*NH + h)*DHEAD + d] =
            make_float2(o[nt][0]*inv_lo, o[nt][1]*inv_lo);
        *(float2*)&g_z[(((size_t)b*TT + (t0+rh))*NH + h)*DHEAD + d] =
            make_float2(o[nt][2]*inv_hi, o[nt][3]*inv_hi);
    }
}

// ============================================================================
extern "C" void kernel_launch(void* const* d_in, const int* in_sizes, int n_in,
                              void* d_out, int out_size)
{
    const float* xs   = (const float*)d_in[0];
    const int*   mask = (const int*)  d_in[1];
    const float* Wq   = (const float*)d_in[2];
    const float* Wk   = (const float*)d_in[3];
    const float* Wv   = (const float*)d_in[4];
    const float* Wpos = (const float*)d_in[5];
    const float* Wout = (const float*)d_in[6];
    const float* ub   = (const float*)d_in[7];
    const float* vb   = (const float*)d_in[8];
    float* out = (float*)d_out;

    cudaFuncSetAttribute(attn_tc, cudaFuncAttributeMaxDynamicSharedMemorySize, ATTN_SMEM);

    qkv_tc<<<dim3(64, 4, 3), 256>>>(xs, Wq, Wk, Wv, ub, vb);
    pos_kernel<<<dim3(32, 8), 256>>>(Wpos);
    attn_tc<<<dim3(16, 64), 256 / 2, ATTN_SMEM>>>(mask);
    out_tc<<<dim3(64, 4), 256>>>(Wout, out);
}

// round 3
// speedup vs baseline: 3.5596x; 1.5637x over previous
#include <cuda_runtime.h>
#include <math.h>
#include <stdint.h>

#define BB     8
#define TT     1024
#define DMODEL 512
#define NH     8
#define DHEAD  64
#define HDIM   512
#define LPOS   2047   // 2T-1
#define AST    68     // attn smem row stride (floats)

// ------------------------- scratch (static device memory) -------------------------
__device__ float g_qu[BB*NH*TT*DHEAD];   // q + u_bias, tf32-rounded, (B,H,T,dh)
__device__ float g_qv[BB*NH*TT*DHEAD];   // q + v_bias, tf32-rounded
__device__ float g_k [BB*NH*TT*DHEAD];   // tf32-rounded
__device__ float g_vt[BB*NH*DHEAD*TT];   // V transposed (B,H,dh,T), tf32-rounded
__device__ float g_p [NH*LPOS*DHEAD];    // (H, L, dh), tf32-rounded
__device__ float g_z [BB*TT*NH*DHEAD];   // (B, T, H, dh), tf32-rounded
__device__ float g_xr[BB*TT*DMODEL];     // xs tf32-rounded
__device__ float g_wq[DMODEL*HDIM];
__device__ float g_wk[DMODEL*HDIM];
__device__ float g_wv[DMODEL*HDIM];
__device__ float g_wo[HDIM*DMODEL];
__device__ unsigned g_mb[BB*TT*(TT/32)]; // bit-packed mask

// ------------------------- helpers -------------------------
__device__ __forceinline__ uint32_t f2tf(float x) {
    uint32_t r;
    asm("cvt.rna.tf32.f32 %0, %1;" : "=r"(r) : "f"(x));
    return r;
}
__device__ __forceinline__ float rnd(float x) { return __uint_as_float(f2tf(x)); }

__device__ __forceinline__ void mma8(float* c, const uint32_t* a, uint32_t b0, uint32_t b1) {
    asm volatile(
        "mma.sync.aligned.m16n8k8.row.col.f32.tf32.tf32.f32 "
        "{%0,%1,%2,%3}, {%4,%5,%6,%7}, {%8,%9}, {%0,%1,%2,%3};"
        : "+f"(c[0]), "+f"(c[1]), "+f"(c[2]), "+f"(c[3])
        : "r"(a[0]), "r"(a[1]), "r"(a[2]), "r"(a[3]), "r"(b0), "r"(b1));
}

__device__ __forceinline__ void cpa16(float* dst, const float* src) {
    uint32_t d = (uint32_t)__cvta_generic_to_shared(dst);
    asm volatile("cp.async.cg.shared.global [%0], [%1], 16;" :: "r"(d), "l"(src));
}
#define CP_COMMIT() asm volatile("cp.async.commit_group;")

// ============================================================================
// prep: round xs + 4 weight matrices to tf32 bit patterns
// grid (1024, 5), 256 threads, grid-stride.
// ============================================================================
__global__ void prep_round(const float* __restrict__ xs,
                           const float* __restrict__ Wq, const float* __restrict__ Wk,
                           const float* __restrict__ Wv, const float* __restrict__ Wo)
{
    int which = blockIdx.y;
    const float* src; float* dst; int n4;
    switch (which) {
        case 0: src = xs; dst = g_xr; n4 = BB*TT*DMODEL/4; break;
        case 1: src = Wq; dst = g_wq; n4 = DMODEL*HDIM/4;  break;
        case 2: src = Wk; dst = g_wk; n4 = DMODEL*HDIM/4;  break;
        case 3: src = Wv; dst = g_wv; n4 = DMODEL*HDIM/4;  break;
        default: src = Wo; dst = g_wo; n4 = HDIM*DMODEL/4; break;
    }
    for (int i = blockIdx.x*blockDim.x + threadIdx.x; i < n4; i += gridDim.x*blockDim.x) {
        float4 v = ((const float4*)src)[i];
        v.x = rnd(v.x); v.y = rnd(v.y); v.z = rnd(v.z); v.w = rnd(v.w);
        ((float4*)dst)[i] = v;
    }
}

// ============================================================================
// bitpack mask: one thread per 32-bit word.  8*1024*32 = 262144 words.
// ============================================================================
__global__ void bitpack(const int* __restrict__ mask)
{
    int w = blockIdx.x*256 + threadIdx.x;
    const int* src = mask + (size_t)w * 32;
    unsigned bits = 0;
#pragma unroll
    for (int j = 0; j < 32; j += 4) {
        int4 v = *(const int4*)(src + j);
        bits |= (unsigned)(v.x != 0) << j;
        bits |= (unsigned)(v.y != 0) << (j+1);
        bits |= (unsigned)(v.z != 0) << (j+2);
        bits |= (unsigned)(v.w != 0) << (j+3);
    }
    g_mb[w] = bits;
}

// ============================================================================
// QKV projection (tf32 mma, cp.async 2-stage): C = xr @ W, 128x128 tile.
// 256 threads = 8 warps (2m x 4n... actually 4m x 2n warp grid, warp 32m x 64n).
// smem: A[2][128][36] row-major [m][k], B[2][32][132] row-major [k][n].
// ============================================================================
#define QKV_SMEM ((2*128*36 + 2*32*132) * 4)

__device__ __forceinline__ void proj_prefetch(float* sm, int buf, int tid,
        const float* A, const float* B, int m0, int n0, int k0)
{
    float* bA = sm + buf*4608;
    float* bB = sm + 9216 + buf*4224;
    for (int e = tid; e < 1024; e += 256) {
        int r = e >> 3, ch = (e & 7) * 4;
        cpa16(bA + r*36 + ch, A + (size_t)(m0 + r)*DMODEL + k0 + ch);
    }
    for (int e = tid; e < 1024; e += 256) {
        int r = e >> 5, ch = (e & 31) * 4;
        cpa16(bB + r*132 + ch, B + (size_t)(k0 + r)*HDIM + n0 + ch);
    }
}

__global__ __launch_bounds__(256, 2)
void qkv_tc(const float* __restrict__ ub, const float* __restrict__ vb)
{
    extern __shared__ float sm[];
    const int which = blockIdx.z;
    const float* W = (which == 0) ? g_wq : (which == 1) ? g_wk : g_wv;
    const int m0 = blockIdx.x * 128;
    const int n0 = blockIdx.y * 128;
    const int tid = threadIdx.x, lane = tid & 31, warp = tid >> 5;
    const int g = lane >> 2, c = lane & 3;
    const int wm = warp >> 1, wn = warp & 1;

    float acc[2][8][4] = {};

    proj_prefetch(sm, 0, tid, g_xr, W, m0, n0, 0);
    CP_COMMIT();

    for (int it = 0; it < 16; it++) {
        int buf = it & 1;
        if (it < 15) { proj_prefetch(sm, buf^1, tid, g_xr, W, m0, n0, (it+1)*32); CP_COMMIT(); }
        if (it < 15) asm volatile("cp.async.wait_group 1;");
        else         asm volatile("cp.async.wait_group 0;");
        __syncthreads();

        const uint32_t* uA = (const uint32_t*)(sm + buf*4608);
        const uint32_t* uB = (const uint32_t*)(sm + 9216 + buf*4224);
#pragma unroll
        for (int kk = 0; kk < 4; kk++) {
            uint32_t a[2][4], b[8][2];
#pragma unroll
            for (int mt = 0; mt < 2; mt++) {
                int r = wm*32 + mt*16 + g;
                a[mt][0] = uA[r*36 + kk*8 + c];
                a[mt][1] = uA[(r+8)*36 + kk*8 + c];
                a[mt][2] = uA[r*36 + kk*8 + c + 4];
                a[mt][3] = uA[(r+8)*36 + kk*8 + c + 4];
            }
#pragma unroll
            for (int nt = 0; nt < 8; nt++) {
                int nn = wn*64 + nt*8 + g;
                b[nt][0] = uB[(kk*8+c)*132 + nn];
                b[nt][1] = uB[(kk*8+c+4)*132 + nn];
            }
#pragma unroll
            for (int mt = 0; mt < 2; mt++)
#pragma unroll
                for (int nt = 0; nt < 8; nt++) mma8(acc[mt][nt], a[mt], b[nt][0], b[nt][1]);
        }
        __syncthreads();
    }

#pragma unroll
    for (int mt = 0; mt < 2; mt++) {
#pragma unroll
        for (int nt = 0; nt < 8; nt++) {
            int n = n0 + wn*64 + nt*8 + 2*c;
            int h = n >> 6, d = n & 63;
#pragma unroll
            for (int half = 0; half < 2; half++) {
                int m = m0 + wm*32 + mt*16 + g + half*8;
                int bidx = m >> 10, t = m & (TT-1);
                size_t o = (((size_t)bidx*NH + h)*TT + t)*DHEAD + d;
                float v0 = acc[mt][nt][half*2+0], v1 = acc[mt][nt][half*2+1];
                if (which == 0) {
                    *(float2*)&g_qu[o] = make_float2(rnd(v0 + ub[n]), rnd(v1 + ub[n+1]));
                    *(float2*)&g_qv[o] = make_float2(rnd(v0 + vb[n]), rnd(v1 + vb[n+1]));
                } else if (which == 1) {
                    *(float2*)&g_k[o] = make_float2(rnd(v0), rnd(v1));
                } else {
                    size_t ovt = (((size_t)bidx*NH + h)*DHEAD + d)*TT + t;
                    g_vt[ovt]      = rnd(v0);
                    g_vt[ovt + TT] = rnd(v1);
                }
            }
        }
    }
}

// ============================================================================
// Output projection (same skeleton): out = z @ Wout (final, fp32 output)
// ============================================================================
__global__ __launch_bounds__(256, 2)
void out_tc(float* __restrict__ out)
{
    extern __shared__ float sm[];
    const int m0 = blockIdx.x * 128;
    const int n0 = blockIdx.y * 128;
    const int tid = threadIdx.x, lane = tid & 31, warp = tid >> 5;
    const int g = lane >> 2, c = lane & 3;
    const int wm = warp >> 1, wn = warp & 1;

    float acc[2][8][4] = {};

    proj_prefetch(sm, 0, tid, g_z, g_wo, m0, n0, 0);
    CP_COMMIT();

    for (int it = 0; it < 16; it++) {
        int buf = it & 1;
        if (it < 15) { proj_prefetch(sm, buf^1, tid, g_z, g_wo, m0, n0, (it+1)*32); CP_COMMIT(); }
        if (it < 15) asm volatile("cp.async.wait_group 1;");
        else         asm volatile("cp.async.wait_group 0;");
        __syncthreads();

        const uint32_t* uA = (const uint32_t*)(sm + buf*4608);
        const uint32_t* uB = (const uint32_t*)(sm + 9216 + buf*4224);
#pragma unroll
        for (int kk = 0; kk < 4; kk++) {
            uint32_t a[2][4], b[8][2];
#pragma unroll
            for (int mt = 0; mt < 2; mt++) {
                int r = wm*32 + mt*16 + g;
                a[mt][0] = uA[r*36 + kk*8 + c];
                a[mt][1] = uA[(r+8)*36 + kk*8 + c];
                a[mt][2] = uA[r*36 + kk*8 + c + 4];
                a[mt][3] = uA[(r+8)*36 + kk*8 + c + 4];
            }
#pragma unroll
            for (int nt = 0; nt < 8; nt++) {
                int nn = wn*64 + nt*8 + g;
                b[nt][0] = uB[(kk*8+c)*132 + nn];
                b[nt][1] = uB[(kk*8+c+4)*132 + nn];
            }
#pragma unroll
            for (int mt = 0; mt < 2; mt++)
#pragma unroll
                for (int nt = 0; nt < 8; nt++) mma8(acc[mt][nt], a[mt], b[nt][0], b[nt][1]);
        }
        __syncthreads();
    }

#pragma unroll
    for (int mt = 0; mt < 2; mt++) {
#pragma unroll
        for (int nt = 0; nt < 8; nt++) {
            int n = n0 + wn*64 + nt*8 + 2*c;
#pragma unroll
            for (int half = 0; half < 2; half++) {
                int m = m0 + wm*32 + mt*16 + g + half*8;
                *(float2*)&out[(size_t)m*DMODEL + n] =
                    make_float2(acc[mt][nt][half*2+0], acc[mt][nt][half*2+1]);
            }
        }
    }
}

// ============================================================================
// Positional projection (SIMT fp32, exact): p = pe @ Wpos, output rounded.
// ============================================================================
__global__ __launch_bounds__(256, 2)
void pos_kernel(const float* __restrict__ Wpos)
{
    __shared__ float As[16][68];
    __shared__ float Bs[16][64];
    __shared__ float fT[512];
    const int m0 = blockIdx.x * 64;
    const int n0 = blockIdx.y * 64;
    const int tid = threadIdx.x;
    const int ty = tid >> 4, tx = tid & 15;
    const float LN1E4 = 9.210340371976184f;

    for (int i = tid; i < 512; i += 256)
        fT[i] = expf(-LN1E4 * (float)(i & ~1) / (float)DMODEL);
    __syncthreads();

    float acc[4][4];
#pragma unroll
    for (int i = 0; i < 4; i++)
#pragma unroll
        for (int j = 0; j < 4; j++) acc[i][j] = 0.f;

    const int arow = tid >> 2;
    const int akk  = (tid & 3) * 4;
    const int bn   = tid & 63;
    const int bkk0 = tid >> 6;

    const int m = m0 + arow;
    const float pos = (float)(m - (TT - 1));

    for (int k0 = 0; k0 < DMODEL; k0 += 16) {
#pragma unroll
        for (int j = 0; j < 4; j++) {
            int cc = k0 + akk + j;
            float ang = pos * fT[cc];
            As[akk+j][arow] = (m < LPOS) ? ((cc & 1) ? cosf(ang) : sinf(ang)) : 0.f;
        }
#pragma unroll
        for (int r = 0; r < 4; r++)
            Bs[bkk0 + 4*r][bn] = Wpos[(size_t)(k0 + bkk0 + 4*r) * HDIM + n0 + bn];
        __syncthreads();
#pragma unroll
        for (int kk = 0; kk < 16; kk++) {
            float4 a = *(const float4*)&As[kk][ty*4];
            float4 b = *(const float4*)&Bs[kk][tx*4];
            float av[4] = {a.x,a.y,a.z,a.w};
            float bv[4] = {b.x,b.y,b.z,b.w};
#pragma unroll
            for (int i = 0; i < 4; i++)
#pragma unroll
                for (int j = 0; j < 4; j++) acc[i][j] += av[i]*bv[j];
        }
        __syncthreads();
    }

#pragma unroll
    for (int i = 0; i < 4; i++) {
        int l = m0 + ty*4 + i;
        if (l >= LPOS) continue;
        int n = n0 + tx*4;
        int h = n >> 6, d = n & 63;
        *(float4*)&g_p[((size_t)h*LPOS + l)*DHEAD + d] =
            make_float4(rnd(acc[i][0]), rnd(acc[i][1]), rnd(acc[i][2]), rnd(acc[i][3]));
    }
}

// ============================================================================
// Fused attention v3: cp.async double-buffered tiles, pre-rounded inputs,
// BD band reduction (10 n8-tiles/warp), bit-packed mask.
// 128 threads = 4 warps; each warp owns 16 query rows.
// smem floats: K[2][64*68] V[2][64*68] P[2][128*68] S[64*68] BD[64*132]
// ============================================================================
#define ATTN_SMEM ((2*64*AST + 2*64*AST + 2*128*AST + 64*AST + 64*132) * 4)

__device__ __forceinline__ void attn_prefetch(float* sm, int buf, int tid,
        const float* kp, const float* vtp, const float* pp, int s0, int l0)
{
    float* bK = sm + buf*4352;
    float* bV = sm + 8704 + buf*4352;
    float* bP = sm + 17408 + buf*8704;
    for (int e = tid; e < 1024; e += 128) {
        int r = e >> 4, ch = (e & 15) * 4;
        cpa16(bK + r*AST + ch, kp + (size_t)(s0 + r)*DHEAD + ch);
        cpa16(bV + r*AST + ch, vtp + (size_t)r*TT + s0 + ch);
    }
    for (int e = tid; e < 2032; e += 128) {
        int r = e >> 4, ch = (e & 15) * 4;
        cpa16(bP + r*AST + ch, pp + (size_t)(l0 + r)*DHEAD + ch);
    }
}

__global__ __launch_bounds__(128, 1)
void attn_tc()
{
    extern __shared__ float sm[];
    float* sS  = sm + 34816;      // [t][s] exp values (tf32-rounded)
    float* sBD = sm + 39168;      // [t][l] band, stride 132

    const int tid = threadIdx.x, lane = tid & 31, warp = tid >> 5;
    const int g = lane >> 2, c = lane & 3;
    const int t0 = blockIdx.x * 64;
    const int bh = blockIdx.y;
    const int b = bh >> 3, h = bh & 7;
    const int rl = warp*16 + g;
    const int rh = rl + 8;
    const int tb = 6 - 2*warp;    // first BD n8-tile for this warp

    const float* qu  = g_qu + ((size_t)bh * TT + t0) * DHEAD;
    const float* qv  = g_qv + ((size_t)bh * TT + t0) * DHEAD;
    const float* kp  = g_k  + (size_t)bh * TT * DHEAD;
    const float* vtp = g_vt + (size_t)bh * DHEAD * TT;
    const float* pp  = g_p  + (size_t)h * LPOS * DHEAD;

    // zero row 127 of both P buffers (never written by cp.async)
    if (tid < 128) {
        int bf = tid >> 6, col = tid & 63;
        sm[17408 + bf*8704 + 127*AST + col] = 0.f;
    }

    // Q fragments (pre-rounded in gmem)
    uint32_t quf[8][4], qvf[8][4];
#pragma unroll
    for (int kk = 0; kk < 8; kk++) {
        quf[kk][0] = __float_as_uint(qu[rl*DHEAD + kk*8 + c]);
        quf[kk][1] = __float_as_uint(qu[rh*DHEAD + kk*8 + c]);
        quf[kk][2] = __float_as_uint(qu[rl*DHEAD + kk*8 + c + 4]);
        quf[kk][3] = __float_as_uint(qu[rh*DHEAD + kk*8 + c + 4]);
        qvf[kk][0] = __float_as_uint(qv[rl*DHEAD + kk*8 + c]);
        qvf[kk][1] = __float_as_uint(qv[rh*DHEAD + kk*8 + c]);
        qvf[kk][2] = __float_as_uint(qv[rl*DHEAD + kk*8 + c + 4]);
        qvf[kk][3] = __float_as_uint(qv[rh*DHEAD + kk*8 + c + 4]);
    }

    attn_prefetch(sm, 0, tid, kp, vtp, pp, 0, 0 - t0 + (TT - 64));
    CP_COMMIT();

    float o[8][4] = {};
    float rmax_lo = -1e30f, rmax_hi = -1e30f;
    float rsum_lo = 0.f, rsum_hi = 0.f;

    for (int it = 0; it < 16; it++) {
        const int buf = it & 1;
        const int s0 = it * 64;
        if (it < 15) {
            attn_prefetch(sm, buf^1, tid, kp, vtp, pp, s0 + 64, s0 + 64 - t0 + (TT - 64));
            CP_COMMIT();
        }
        if (it < 15) asm volatile("cp.async.wait_group 1;");
        else         asm volatile("cp.async.wait_group 0;");
        __syncthreads();

        const uint32_t* uK = (const uint32_t*)(sm + buf*4352);
        const uint32_t* uV = (const uint32_t*)(sm + 8704 + buf*4352);
        const uint32_t* uP = (const uint32_t*)(sm + 17408 + buf*8704);
        uint32_t* uS = (uint32_t*)sS;

        // ---- BD band GEMM: only the 10 tiles this warp's shift window touches ----
        {
            float bd[10][4] = {};
#pragma unroll
            for (int kk = 0; kk < 8; kk++) {
#pragma unroll
                for (int j = 0; j < 10; j++) {
                    int nn = (tb + j)*8 + g;
                    mma8(bd[j], qvf[kk], uP[nn*AST + kk*8 + c], uP[nn*AST + kk*8 + c + 4]);
                }
            }
#pragma unroll
            for (int j = 0; j < 10; j++) {
                int cb = (tb + j)*8 + 2*c;
                sBD[rl*132 + cb]   = bd[j][0];
                sBD[rl*132 + cb+1] = bd[j][1];
                sBD[rh*132 + cb]   = bd[j][2];
                sBD[rh*132 + cb+1] = bd[j][3];
            }
        }
        __syncwarp();

        // ---- AC GEMM ----
        float acc[8][4] = {};
#pragma unroll
        for (int kk = 0; kk < 8; kk++) {
#pragma unroll
            for (int nt = 0; nt < 8; nt++) {
                int nn = nt*8 + g;
                mma8(acc[nt], quf[kk], uK[nn*AST + kk*8 + c], uK[nn*AST + kk*8 + c + 4]);
            }
        }

        // ---- mask bits for this tile ----
        uint2 mwl = *(const uint2*)(g_mb + ((size_t)b*TT + t0 + rl)*32 + (s0 >> 5));
        uint2 mwh = *(const uint2*)(g_mb + ((size_t)b*TT + t0 + rh)*32 + (s0 >> 5));

        // ---- combine ac + shifted bd, mask, scale, online softmax ----
        float mx_lo = -1e30f, mx_hi = -1e30f;
#pragma unroll
        for (int nt = 0; nt < 8; nt++) {
            int cb = nt*8 + 2*c;
            unsigned wl = (cb & 32) ? mwl.y : mwl.x;
            unsigned wh = (cb & 32) ? mwh.y : mwh.x;
            int sh = cb & 31;
            float v;
            v = (acc[nt][0] + sBD[rl*132 + cb   - rl + 63]) * 0.125f;
            acc[nt][0] = ((wl >> sh)     & 1) ? v : -1e30f;
            v = (acc[nt][1] + sBD[rl*132 + cb+1 - rl + 63]) * 0.125f;
            acc[nt][1] = ((wl >> (sh+1)) & 1) ? v : -1e30f;
            v = (acc[nt][2] + sBD[rh*132 + cb   - rh + 63]) * 0.125f;
            acc[nt][2] = ((wh >> sh)     & 1) ? v : -1e30f;
            v = (acc[nt][3] + sBD[rh*132 + cb+1 - rh + 63]) * 0.125f;
            acc[nt][3] = ((wh >> (sh+1)) & 1) ? v : -1e30f;
            mx_lo = fmaxf(mx_lo, fmaxf(acc[nt][0], acc[nt][1]));
            mx_hi = fmaxf(mx_hi, fmaxf(acc[nt][2], acc[nt][3]));
        }
        mx_lo = fmaxf(mx_lo, __shfl_xor_sync(0xffffffffu, mx_lo, 1));
        mx_lo = fmaxf(mx_lo, __shfl_xor_sync(0xffffffffu, mx_lo, 2));
        mx_hi = fmaxf(mx_hi, __shfl_xor_sync(0xffffffffu, mx_hi, 1));
        mx_hi = fmaxf(mx_hi, __shfl_xor_sync(0xffffffffu, mx_hi, 2));

        float nm_lo = fmaxf(rmax_lo, mx_lo);
        float nm_hi = fmaxf(rmax_hi, mx_hi);
        float corr_lo = __expf(rmax_lo - nm_lo);
        float corr_hi = __expf(rmax_hi - nm_hi);
        rmax_lo = nm_lo; rmax_hi = nm_hi;

        float ts_lo = 0.f, ts_hi = 0.f;
#pragma unroll
        for (int nt = 0; nt < 8; nt++) {
            int cb = nt*8 + 2*c;
            float p0 = __expf(acc[nt][0] - nm_lo);
            float p1 = __expf(acc[nt][1] - nm_lo);
            float p2 = __expf(acc[nt][2] - nm_hi);
            float p3 = __expf(acc[nt][3] - nm_hi);
            ts_lo += p0 + p1; ts_hi += p2 + p3;
            uS[rl*AST + cb]   = f2tf(p0);
            uS[rl*AST + cb+1] = f2tf(p1);
            uS[rh*AST + cb]   = f2tf(p2);
            uS[rh*AST + cb+1] = f2tf(p3);
            o[nt][0] *= corr_lo; o[nt][1] *= corr_lo;
            o[nt][2] *= corr_hi; o[nt][3] *= corr_hi;
        }
        ts_lo += __shfl_xor_sync(0xffffffffu, ts_lo, 1);
        ts_lo += __shfl_xor_sync(0xffffffffu, ts_lo, 2);
        ts_hi += __shfl_xor_sync(0xffffffffu, ts_hi, 1);
        ts_hi += __shfl_xor_sync(0xffffffffu, ts_hi, 2);
        rsum_lo = rsum_lo * corr_lo + ts_lo;
        rsum_hi = rsum_hi * corr_hi + ts_hi;
        __syncwarp();

        // ---- PV GEMM: O += exp(S) @ V ----
#pragma unroll
        for (int kk = 0; kk < 8; kk++) {
            uint32_t a[4];
            a[0] = uS[rl*AST + kk*8 + c];
            a[1] = uS[rh*AST + kk*8 + c];
            a[2] = uS[rl*AST + kk*8 + c + 4];
            a[3] = uS[rh*AST + kk*8 + c + 4];
#pragma unroll
            for (int nt = 0; nt < 8; nt++) {
                int nn = nt*8 + g;
                mma8(o[nt], a, uV[nn*AST + kk*8 + c], uV[nn*AST + kk*8 + c + 4]);
            }
        }
        __syncthreads();   // all warps done with buf before it is overwritten
    }

    // ---- normalize + write z (B,T,H,dh), tf32-rounded for out_tc ----
    float inv_lo = 1.f / rsum_lo, inv_hi = 1.f / rsum_hi;
#pragma unroll
    for (int nt = 0; nt < 8; nt++) {
        int d = nt*8 + 2*c;
        *(float2*)&g_z[(((size_t)b*TT + (t0+rl))*NH + h)*DHEAD + d] =
            make_float2(rnd(o[nt][0]*inv_lo), rnd(o[nt][1]*inv_lo));
        *(float2*)&g_z[(((size_t)b*TT + (t0+rh))*NH + h)*DHEAD + d] =
            make_float2(rnd(o[nt][2]*inv_hi), rnd(o[nt][3]*inv_hi));
    }
}

// ============================================================================
extern "C" void kernel_launch(void* const* d_in, const int* in_sizes, int n_in,
                              void* d_out, int out_size)
{
    const float* xs   = (const float*)d_in[0];
    const int*   mask = (const int*)  d_in[1];
    const float* Wq   = (const float*)d_in[2];
    const float* Wk   = (const float*)d_in[3];
    const float* Wv   = (const float*)d_in[4];
    const float* Wpos = (const float*)d_in[5];
    const float* Wout = (const float*)d_in[6];
    const float* ub   = (const float*)d_in[7];
    const float* vb   = (const float*)d_in[8];
    float* out = (float*)d_out;

    cudaFuncSetAttribute(attn_tc, cudaFuncAttributeMaxDynamicSharedMemorySize, ATTN_SMEM);
    cudaFuncSetAttribute(qkv_tc,  cudaFuncAttributeMaxDynamicSharedMemorySize, QKV_SMEM);
    cudaFuncSetAttribute(out_tc,  cudaFuncAttributeMaxDynamicSharedMemorySize, QKV_SMEM);

    prep_round<<<dim3(1024, 5), 256>>>(xs, Wq, Wk, Wv, Wout);
    bitpack<<<1024, 256>>>(mask);
    pos_kernel<<<dim3(32, 8), 256>>>(Wpos);
    qkv_tc<<<dim3(64, 4, 3), 256, QKV_SMEM>>>(ub, vb);
    attn_tc<<<dim3(16, 64), 128, ATTN_SMEM>>>();
    out_tc<<<dim3(64, 4), 256, QKV_SMEM>>>(out);
}

// round 4
// speedup vs baseline: 3.7599x; 1.0563x over previous
#include <cuda_runtime.h>
#include <math.h>
#include <stdint.h>

#define BB     8
#define TT     1024
#define DMODEL 512
#define NH     8
#define DHEAD  64
#define HDIM   512
#define LPOS   2047   // 2T-1
#define AST    68     // attn K/V/P smem row stride (floats)
#define BDST   84     // BD/S row stride
#define PROWS  320    // circular P window rows (5 x 64)

// ------------------------- scratch (static device memory) -------------------------
__device__ float g_qu[BB*NH*TT*DHEAD];   // q + u_bias, tf32-rounded, (B,H,T,dh)
__device__ float g_qv[BB*NH*TT*DHEAD];   // q + v_bias, tf32-rounded
__device__ float g_k [BB*NH*TT*DHEAD];   // tf32-rounded
__device__ float g_vt[BB*NH*DHEAD*TT];   // V transposed (B,H,dh,T), tf32-rounded
__device__ float g_p [NH*LPOS*DHEAD];    // (H, L, dh), tf32-rounded
__device__ float g_z [BB*TT*NH*DHEAD];   // (B, T, H, dh), tf32-rounded
__device__ float g_xr[BB*TT*DMODEL];     // xs tf32-rounded
__device__ float g_wq[DMODEL*HDIM];
__device__ float g_wk[DMODEL*HDIM];
__device__ float g_wv[DMODEL*HDIM];
__device__ float g_wo[HDIM*DMODEL];
__device__ unsigned g_mb[BB*TT*(TT/32)]; // bit-packed mask

// ------------------------- helpers -------------------------
__device__ __forceinline__ uint32_t f2tf(float x) {
    uint32_t r;
    asm("cvt.rna.tf32.f32 %0, %1;" : "=r"(r) : "f"(x));
    return r;
}
__device__ __forceinline__ float rnd(float x) { return __uint_as_float(f2tf(x)); }

__device__ __forceinline__ void mma8(float* c, const uint32_t* a, uint32_t b0, uint32_t b1) {
    asm volatile(
        "mma.sync.aligned.m16n8k8.row.col.f32.tf32.tf32.f32 "
        "{%0,%1,%2,%3}, {%4,%5,%6,%7}, {%8,%9}, {%0,%1,%2,%3};"
        : "+f"(c[0]), "+f"(c[1]), "+f"(c[2]), "+f"(c[3])
        : "r"(a[0]), "r"(a[1]), "r"(a[2]), "r"(a[3]), "r"(b0), "r"(b1));
}

__device__ __forceinline__ void cpa16(float* dst, const float* src) {
    uint32_t d = (uint32_t)__cvta_generic_to_shared(dst);
    asm volatile("cp.async.cg.shared.global [%0], [%1], 16;" :: "r"(d), "l"(src));
}
#define CP_COMMIT() asm volatile("cp.async.commit_group;")

// ============================================================================
// prep: round xs + 4 weight matrices to tf32 bit patterns
// ============================================================================
__global__ void prep_round(const float* __restrict__ xs,
                           const float* __restrict__ Wq, const float* __restrict__ Wk,
                           const float* __restrict__ Wv, const float* __restrict__ Wo)
{
    int which = blockIdx.y;
    const float* src; float* dst; int n4;
    switch (which) {
        case 0: src = xs; dst = g_xr; n4 = BB*TT*DMODEL/4; break;
        case 1: src = Wq; dst = g_wq; n4 = DMODEL*HDIM/4;  break;
        case 2: src = Wk; dst = g_wk; n4 = DMODEL*HDIM/4;  break;
        case 3: src = Wv; dst = g_wv; n4 = DMODEL*HDIM/4;  break;
        default: src = Wo; dst = g_wo; n4 = HDIM*DMODEL/4; break;
    }
    for (int i = blockIdx.x*blockDim.x + threadIdx.x; i < n4; i += gridDim.x*blockDim.x) {
        float4 v = ((const float4*)src)[i];
        v.x = rnd(v.x); v.y = rnd(v.y); v.z = rnd(v.z); v.w = rnd(v.w);
        ((float4*)dst)[i] = v;
    }
}

// ============================================================================
// bitpack mask
// ============================================================================
__global__ void bitpack(const int* __restrict__ mask)
{
    int w = blockIdx.x*256 + threadIdx.x;
    const int* src = mask + (size_t)w * 32;
    unsigned bits = 0;
#pragma unroll
    for (int j = 0; j < 32; j += 4) {
        int4 v = *(const int4*)(src + j);
        bits |= (unsigned)(v.x != 0) << j;
        bits |= (unsigned)(v.y != 0) << (j+1);
        bits |= (unsigned)(v.z != 0) << (j+2);
        bits |= (unsigned)(v.w != 0) << (j+3);
    }
    g_mb[w] = bits;
}

// ============================================================================
// Projections (tf32 mma, cp.async 3-stage): C = A @ W, 128x128 tile.
// smem per stage: A 128x36, B 32x132.
// ============================================================================
#define PROJ_STAGE (128*36 + 32*132)   // 8832 floats
#define PROJ_SMEM  (3*PROJ_STAGE*4)

__device__ __forceinline__ void proj_prefetch(float* sm, int stage, int tid,
        const float* A, const float* B, int m0, int n0, int k0)
{
    float* bA = sm + stage*PROJ_STAGE;
    float* bB = bA + 128*36;
    for (int e = tid; e < 1024; e += 256) {
        int r = e >> 3, ch = (e & 7) * 4;
        cpa16(bA + r*36 + ch, A + (size_t)(m0 + r)*DMODEL + k0 + ch);
    }
    for (int e = tid; e < 1024; e += 256) {
        int r = e >> 5, ch = (e & 31) * 4;
        cpa16(bB + r*132 + ch, B + (size_t)(k0 + r)*HDIM + n0 + ch);
    }
}

__device__ __forceinline__ void proj_core(float* sm, int tid,
        const float* A, const float* B, int m0, int n0, float acc[2][8][4])
{
    const int lane = tid & 31, warp = tid >> 5;
    const int g = lane >> 2, c = lane & 3;
    const int wm = warp >> 1, wn = warp & 1;

    proj_prefetch(sm, 0, tid, A, B, m0, n0, 0);  CP_COMMIT();
    proj_prefetch(sm, 1, tid, A, B, m0, n0, 32); CP_COMMIT();

    for (int it = 0; it < 16; it++) {
        if (it + 2 < 16) { proj_prefetch(sm, (it+2)%3, tid, A, B, m0, n0, (it+2)*32); CP_COMMIT(); }
        if (it < 14)      asm volatile("cp.async.wait_group 2;");
        else if (it == 14) asm volatile("cp.async.wait_group 1;");
        else               asm volatile("cp.async.wait_group 0;");
        __syncthreads();

        const uint32_t* uA = (const uint32_t*)(sm + (it%3)*PROJ_STAGE);
        const uint32_t* uB = uA + 128*36;
#pragma unroll
        for (int kk = 0; kk < 4; kk++) {
            uint32_t a[2][4], b[8][2];
#pragma unroll
            for (int mt = 0; mt < 2; mt++) {
                int r = wm*32 + mt*16 + g;
                a[mt][0] = uA[r*36 + kk*8 + c];
                a[mt][1] = uA[(r+8)*36 + kk*8 + c];
                a[mt][2] = uA[r*36 + kk*8 + c + 4];
                a[mt][3] = uA[(r+8)*36 + kk*8 + c + 4];
            }
#pragma unroll
            for (int nt = 0; nt < 8; nt++) {
                int nn = wn*64 + nt*8 + g;
                b[nt][0] = uB[(kk*8+c)*132 + nn];
                b[nt][1] = uB[(kk*8+c+4)*132 + nn];
            }
#pragma unroll
            for (int mt = 0; mt < 2; mt++)
#pragma unroll
                for (int nt = 0; nt < 8; nt++) mma8(acc[mt][nt], a[mt], b[nt][0], b[nt][1]);
        }
        __syncthreads();
    }
}

__global__ __launch_bounds__(256, 2)
void qkv_tc(const float* __restrict__ ub, const float* __restrict__ vb)
{
    extern __shared__ float sm[];
    const int which = blockIdx.z;
    const float* W = (which == 0) ? g_wq : (which == 1) ? g_wk : g_wv;
    const int m0 = blockIdx.x * 128;
    const int n0 = blockIdx.y * 128;
    const int tid = threadIdx.x, lane = tid & 31, warp = tid >> 5;
    const int g = lane >> 2, c = lane & 3;
    const int wm = warp >> 1, wn = warp & 1;

    float acc[2][8][4] = {};
    proj_core(sm, tid, g_xr, W, m0, n0, acc);

#pragma unroll
    for (int mt = 0; mt < 2; mt++) {
#pragma unroll
        for (int nt = 0; nt < 8; nt++) {
            int n = n0 + wn*64 + nt*8 + 2*c;
            int h = n >> 6, d = n & 63;
#pragma unroll
            for (int half = 0; half < 2; half++) {
                int m = m0 + wm*32 + mt*16 + g + half*8;
                int bidx = m >> 10, t = m & (TT-1);
                size_t o = (((size_t)bidx*NH + h)*TT + t)*DHEAD + d;
                float v0 = acc[mt][nt][half*2+0], v1 = acc[mt][nt][half*2+1];
                if (which == 0) {
                    *(float2*)&g_qu[o] = make_float2(rnd(v0 + ub[n]), rnd(v1 + ub[n+1]));
                    *(float2*)&g_qv[o] = make_float2(rnd(v0 + vb[n]), rnd(v1 + vb[n+1]));
                } else if (which == 1) {
                    *(float2*)&g_k[o] = make_float2(rnd(v0), rnd(v1));
                } else {
                    size_t ovt = (((size_t)bidx*NH + h)*DHEAD + d)*TT + t;
                    g_vt[ovt]      = rnd(v0);
                    g_vt[ovt + TT] = rnd(v1);
                }
            }
        }
    }
}

__global__ __launch_bounds__(256, 2)
void out_tc(float* __restrict__ out)
{
    extern __shared__ float sm[];
    const int m0 = blockIdx.x * 128;
    const int n0 = blockIdx.y * 128;
    const int tid = threadIdx.x, lane = tid & 31, warp = tid >> 5;
    const int g = lane >> 2, c = lane & 3;
    const int wm = warp >> 1, wn = warp & 1;

    float acc[2][8][4] = {};
    proj_core(sm, tid, g_z, g_wo, m0, n0, acc);

#pragma unroll
    for (int mt = 0; mt < 2; mt++) {
#pragma unroll
        for (int nt = 0; nt < 8; nt++) {
            int n = n0 + wn*64 + nt*8 + 2*c;
#pragma unroll
            for (int half = 0; half < 2; half++) {
                int m = m0 + wm*32 + mt*16 + g + half*8;
                *(float2*)&out[(size_t)m*DMODEL + n] =
                    make_float2(acc[mt][nt][half*2+0], acc[mt][nt][half*2+1]);
            }
        }
    }
}

// ============================================================================
// Positional projection (SIMT fp32, exact)
// ============================================================================
__global__ __launch_bounds__(256, 2)
void pos_kernel(const float* __restrict__ Wpos)
{
    __shared__ float As[16][68];
    __shared__ float Bs[16][64];
    __shared__ float fT[512];
    const int m0 = blockIdx.x * 64;
    const int n0 = blockIdx.y * 64;
    const int tid = threadIdx.x;
    const int ty = tid >> 4, tx = tid & 15;
    const float LN1E4 = 9.210340371976184f;

    for (int i = tid; i < 512; i += 256)
        fT[i] = expf(-LN1E4 * (float)(i & ~1) / (float)DMODEL);
    __syncthreads();

    float acc[4][4];
#pragma unroll
    for (int i = 0; i < 4; i++)
#pragma unroll
        for (int j = 0; j < 4; j++) acc[i][j] = 0.f;

    const int arow = tid >> 2;
    const int akk  = (tid & 3) * 4;
    const int bn   = tid & 63;
    const int bkk0 = tid >> 6;

    const int m = m0 + arow;
    const float pos = (float)(m - (TT - 1));

    for (int k0 = 0; k0 < DMODEL; k0 += 16) {
#pragma unroll
        for (int j = 0; j < 4; j++) {
            int cc = k0 + akk + j;
            float ang = pos * fT[cc];
            As[akk+j][arow] = (m < LPOS) ? ((cc & 1) ? cosf(ang) : sinf(ang)) : 0.f;
        }
#pragma unroll
        for (int r = 0; r < 4; r++)
            Bs[bkk0 + 4*r][bn] = Wpos[(size_t)(k0 + bkk0 + 4*r) * HDIM + n0 + bn];
        __syncthreads();
#pragma unroll
        for (int kk = 0; kk < 16; kk++) {
            float4 a = *(const float4*)&As[kk][ty*4];
            float4 b = *(const float4*)&Bs[kk][tx*4];
            float av[4] = {a.x,a.y,a.z,a.w};
            float bv[4] = {b.x,b.y,b.z,b.w};
#pragma unroll
            for (int i = 0; i < 4; i++)
#pragma unroll
                for (int j = 0; j < 4; j++) acc[i][j] += av[i]*bv[j];
        }
        __syncthreads();
    }

#pragma unroll
    for (int i = 0; i < 4; i++) {
        int l = m0 + ty*4 + i;
        if (l >= LPOS) continue;
        int n = n0 + tx*4;
        int h = n >> 6, d = n & 63;
        *(float4*)&g_p[((size_t)h*LPOS + l)*DHEAD + d] =
            make_float4(rnd(acc[i][0]), rnd(acc[i][1]), rnd(acc[i][2]), rnd(acc[i][3]));
    }
}

// ============================================================================
// Fused attention v4: 128-query block, 8 warps (256 thr), circular P window,
// BD/S overlay at stride 84, bit-packed mask, cp.async double-buffered K/V.
// smem floats: K 2x64x68, V 2x64x68, P 320x68, BD/S 128x84  (=199,680 B)
// ============================================================================
#define ATTN_SMEM ((2*64*AST + 2*64*AST + PROWS*AST + 128*BDST) * 4)

__global__ __launch_bounds__(256, 1)
void attn_tc()
{
    extern __shared__ float sm[];
    float* sP  = sm + 17408;          // circular P window [PROWS][AST]
    float* sBD = sm + 17408 + PROWS*AST;  // BD band / exp(S) overlay [128][BDST]

    const int tid = threadIdx.x, lane = tid & 31, warp = tid >> 5;
    const int g = lane >> 2, c = lane & 3;
    const int t0 = blockIdx.x * 128;
    const int bh = blockIdx.y;
    const int b = bh >> 3, h = bh & 7;
    const int rl = warp*16 + g;       // low row (block-local, 0..127)
    const int rh = rl + 8;
    const int tb = 14 - 2*warp;       // first BD n8-tile for this warp

    const float* qu  = g_qu + ((size_t)bh * TT + t0) * DHEAD;
    const float* qv  = g_qv + ((size_t)bh * TT + t0) * DHEAD;
    const float* kp  = g_k  + (size_t)bh * TT * DHEAD;
    const float* vtp = g_vt + (size_t)bh * DHEAD * TT;
    const float* pp  = g_p  + (size_t)h * LPOS * DHEAD;
    const int l00 = 896 - t0;         // p row of band origin at tile 0

    // ---- prefill: P rows l00..l00+254 -> slots 0..254, K/V tile 0 ----
    for (int e = tid; e < 255*16; e += 256) {
        int r = e >> 4, ch = (e & 15) * 4;
        cpa16(sP + r*AST + ch, pp + (size_t)(l00 + r)*DHEAD + ch);
    }
    for (int e = tid; e < 1024; e += 256) {
        int r = e >> 4, ch = (e & 15) * 4;
        cpa16(sm + r*AST + ch, kp + (size_t)r*DHEAD + ch);
        cpa16(sm + 8704 + r*AST + ch, vtp + (size_t)r*TT + ch);
    }
    CP_COMMIT();

    // ---- Q fragments (pre-rounded in gmem) ----
    uint32_t quf[8][4], qvf[8][4];
#pragma unroll
    for (int kk = 0; kk < 8; kk++) {
        quf[kk][0] = __float_as_uint(qu[rl*DHEAD + kk*8 + c]);
        quf[kk][1] = __float_as_uint(qu[rh*DHEAD + kk*8 + c]);
        quf[kk][2] = __float_as_uint(qu[rl*DHEAD + kk*8 + c + 4]);
        quf[kk][3] = __float_as_uint(qu[rh*DHEAD + kk*8 + c + 4]);
        qvf[kk][0] = __float_as_uint(qv[rl*DHEAD + kk*8 + c]);
        qvf[kk][1] = __float_as_uint(qv[rh*DHEAD + kk*8 + c]);
        qvf[kk][2] = __float_as_uint(qv[rl*DHEAD + kk*8 + c + 4]);
        qvf[kk][3] = __float_as_uint(qv[rh*DHEAD + kk*8 + c + 4]);
    }

    float o[8][4] = {};
    float rmax_lo = -1e30f, rmax_hi = -1e30f;
    float rsum_lo = 0.f, rsum_hi = 0.f;

    for (int it = 0; it < 16; it++) {
        const int buf = it & 1;
        const int s0 = it * 64;

        // ---- prefetch next tile ----
        if (it < 15) {
            float* bK = sm + (buf^1)*4352;
            float* bV = sm + 8704 + (buf^1)*4352;
            for (int e = tid; e < 1024; e += 256) {
                int r = e >> 4, ch = (e & 15) * 4;
                cpa16(bK + r*AST + ch, kp + (size_t)(s0 + 64 + r)*DHEAD + ch);
                cpa16(bV + r*AST + ch, vtp + (size_t)r*TT + s0 + 64 + ch);
            }
            if (it <= 13) {
                int start = (it*64 + 255) % PROWS;
                for (int e = tid; e < 1024; e += 256) {
                    int r = e >> 4, ch = (e & 15) * 4;
                    int slot = start + r; if (slot >= PROWS) slot -= PROWS;
                    cpa16(sP + slot*AST + ch,
                          pp + (size_t)(l00 + it*64 + 255 + r)*DHEAD + ch);
                }
            }
            CP_COMMIT();
        }
        if (it < 15) asm volatile("cp.async.wait_group 1;");
        else         asm volatile("cp.async.wait_group 0;");
        __syncthreads();

        const uint32_t* uK = (const uint32_t*)(sm + buf*4352);
        const uint32_t* uV = (const uint32_t*)(sm + 8704 + buf*4352);
        const uint32_t* uP = (const uint32_t*)sP;
        uint32_t* uS = (uint32_t*)sBD;

        // ---- BD band GEMM: 10 n8-tiles per warp, circular P rows ----
        {
            int rowb[10];
            const int p5 = (it % 5) * 64;
#pragma unroll
            for (int j = 0; j < 10; j++) {
                int rb = p5 + (tb + j)*8;
                if (rb >= PROWS) rb -= PROWS;
                rowb[j] = rb;
            }
            float bd[10][4] = {};
#pragma unroll
            for (int kk = 0; kk < 8; kk++) {
#pragma unroll
                for (int j = 0; j < 10; j++) {
                    int nn = rowb[j] + g;
                    mma8(bd[j], qvf[kk], uP[nn*AST + kk*8 + c], uP[nn*AST + kk*8 + c + 4]);
                }
            }
#pragma unroll
            for (int j = 0; j < 10; j++) {
                int cb = j*8 + 2*c;
                sBD[rl*BDST + cb]   = bd[j][0];
                sBD[rl*BDST + cb+1] = bd[j][1];
                sBD[rh*BDST + cb]   = bd[j][2];
                sBD[rh*BDST + cb+1] = bd[j][3];
            }
        }
        __syncwarp();

        // ---- AC GEMM ----
        float acc[8][4] = {};
#pragma unroll
        for (int kk = 0; kk < 8; kk++) {
#pragma unroll
            for (int nt = 0; nt < 8; nt++) {
                int nn = nt*8 + g;
                mma8(acc[nt], quf[kk], uK[nn*AST + kk*8 + c], uK[nn*AST + kk*8 + c + 4]);
            }
        }

        // ---- mask bits ----
        uint2 mwl = *(const uint2*)(g_mb + ((size_t)b*TT + t0 + rl)*32 + (s0 >> 5));
        uint2 mwh = *(const uint2*)(g_mb + ((size_t)b*TT + t0 + rh)*32 + (s0 >> 5));

        // ---- combine ac + shifted bd, mask, scale, online softmax ----
        const int baseL = rl*BDST - g + 15;   // local col = jcol - g + 15
        const int baseH = rh*BDST - g + 7;    // local col = jcol - (g+8) + 15
        float mx_lo = -1e30f, mx_hi = -1e30f;
#pragma unroll
        for (int nt = 0; nt < 8; nt++) {
            int cb = nt*8 + 2*c;
            unsigned wl = (cb & 32) ? mwl.y : mwl.x;
            unsigned wh = (cb & 32) ? mwh.y : mwh.x;
            int sh = cb & 31;
            float v;
            v = (acc[nt][0] + sBD[baseL + cb])   * 0.125f;
            acc[nt][0] = ((wl >> sh)     & 1) ? v : -1e30f;
            v = (acc[nt][1] + sBD[baseL + cb+1]) * 0.125f;
            acc[nt][1] = ((wl >> (sh+1)) & 1) ? v : -1e30f;
            v = (acc[nt][2] + sBD[baseH + cb])   * 0.125f;
            acc[nt][2] = ((wh >> sh)     & 1) ? v : -1e30f;
            v = (acc[nt][3] + sBD[baseH + cb+1]) * 0.125f;
            acc[nt][3] = ((wh >> (sh+1)) & 1) ? v : -1e30f;
            mx_lo = fmaxf(mx_lo, fmaxf(acc[nt][0], acc[nt][1]));
            mx_hi = fmaxf(mx_hi, fmaxf(acc[nt][2], acc[nt][3]));
        }
        mx_lo = fmaxf(mx_lo, __shfl_xor_sync(0xffffffffu, mx_lo, 1));
        mx_lo = fmaxf(mx_lo, __shfl_xor_sync(0xffffffffu, mx_lo, 2));
        mx_hi = fmaxf(mx_hi, __shfl_xor_sync(0xffffffffu, mx_hi, 1));
        mx_hi = fmaxf(mx_hi, __shfl_xor_sync(0xffffffffu, mx_hi, 2));

        float nm_lo = fmaxf(rmax_lo, mx_lo);
        float nm_hi = fmaxf(rmax_hi, mx_hi);
        float corr_lo = __expf(rmax_lo - nm_lo);
        float corr_hi = __expf(rmax_hi - nm_hi);
        rmax_lo = nm_lo; rmax_hi = nm_hi;

        float ts_lo = 0.f, ts_hi = 0.f;
#pragma unroll
        for (int nt = 0; nt < 8; nt++) {
            int cb = nt*8 + 2*c;
            float p0 = __expf(acc[nt][0] - nm_lo);
            float p1 = __expf(acc[nt][1] - nm_lo);
            float p2 = __expf(acc[nt][2] - nm_hi);
            float p3 = __expf(acc[nt][3] - nm_hi);
            ts_lo += p0 + p1; ts_hi += p2 + p3;
            uS[rl*BDST + cb]   = f2tf(p0);
            uS[rl*BDST + cb+1] = f2tf(p1);
            uS[rh*BDST + cb]   = f2tf(p2);
            uS[rh*BDST + cb+1] = f2tf(p3);
            o[nt][0] *= corr_lo; o[nt][1] *= corr_lo;
            o[nt][2] *= corr_hi; o[nt][3] *= corr_hi;
        }
        ts_lo += __shfl_xor_sync(0xffffffffu, ts_lo, 1);
        ts_lo += __shfl_xor_sync(0xffffffffu, ts_lo, 2);
        ts_hi += __shfl_xor_sync(0xffffffffu, ts_hi, 1);
        ts_hi += __shfl_xor_sync(0xffffffffu, ts_hi, 2);
        rsum_lo = rsum_lo * corr_lo + ts_lo;
        rsum_hi = rsum_hi * corr_hi + ts_hi;
        __syncwarp();

        // ---- PV GEMM: O += exp(S) @ V ----
#pragma unroll
        for (int kk = 0; kk < 8; kk++) {
            uint32_t a[4];
            a[0] = uS[rl*BDST + kk*8 + c];
            a[1] = uS[rh*BDST + kk*8 + c];
            a[2] = uS[rl*BDST + kk*8 + c + 4];
            a[3] = uS[rh*BDST + kk*8 + c + 4];
#pragma unroll
            for (int nt = 0; nt < 8; nt++) {
                int nn = nt*8 + g;
                mma8(o[nt], a, uV[nn*AST + kk*8 + c], uV[nn*AST + kk*8 + c + 4]);
            }
        }
        __syncthreads();   // all warps done with K/V buf + P window before overwrite
    }

    // ---- normalize + write z (B,T,H,dh), tf32-rounded for out_tc ----
    float inv_lo = 1.f / rsum_lo, inv_hi = 1.f / rsum_hi;
#pragma unroll
    for (int nt = 0; nt < 8; nt++) {
        int d = nt*8 + 2*c;
        *(float2*)&g_z[(((size_t)b*TT + (t0+rl))*NH + h)*DHEAD + d] =
            make_float2(rnd(o[nt][0]*inv_lo), rnd(o[nt][1]*inv_lo));
        *(float2*)&g_z[(((size_t)b*TT + (t0+rh))*NH + h)*DHEAD + d] =
            make_float2(rnd(o[nt][2]*inv_hi), rnd(o[nt][3]*inv_hi));
    }
}

// ============================================================================
extern "C" void kernel_launch(void* const* d_in, const int* in_sizes, int n_in,
                              void* d_out, int out_size)
{
    const float* xs   = (const float*)d_in[0];
    const int*   mask = (const int*)  d_in[1];
    const float* Wq   = (const float*)d_in[2];
    const float* Wk   = (const float*)d_in[3];
    const float* Wv   = (const float*)d_in[4];
    const float* Wpos = (const float*)d_in[5];
    const float* Wout = (const float*)d_in[6];
    const float* ub   = (const float*)d_in[7];
    const float* vb   = (const float*)d_in[8];
    float* out = (float*)d_out;

    cudaFuncSetAttribute(attn_tc, cudaFuncAttributeMaxDynamicSharedMemorySize, ATTN_SMEM);
    cudaFuncSetAttribute(qkv_tc,  cudaFuncAttributeMaxDynamicSharedMemorySize, PROJ_SMEM);
    cudaFuncSetAttribute(out_tc,  cudaFuncAttributeMaxDynamicSharedMemorySize, PROJ_SMEM);

    prep_round<<<dim3(1024, 5), 256>>>(xs, Wq, Wk, Wv, Wout);
    bitpack<<<1024, 256>>>(mask);
    pos_kernel<<<dim3(32, 8), 256>>>(Wpos);
    qkv_tc<<<dim3(64, 4, 3), 256, PROJ_SMEM>>>(ub, vb);
    attn_tc<<<dim3(8, 64), 256, ATTN_SMEM>>>();
    out_tc<<<dim3(64, 4), 256, PROJ_SMEM>>>(out);
}

// round 6
// speedup vs baseline: 5.8109x; 1.5455x over previous
#include <cuda_runtime.h>
#include <cuda_fp16.h>
#include <math.h>
#include <stdint.h>

#define BB     8
#define TT     1024
#define DMODEL 512
#define NH     8
#define DHEAD  64
#define HDIM   512
#define LPOS   2047   // 2T-1
#define BDST   84     // BD f32 row stride
#define PROWS  320    // circular P window rows (5 x 64)

// ------------------------- scratch (static device memory, fp16) -------------------------
__device__ __half g_qu[BB*NH*TT*DHEAD];   // q + u_bias, (B,H,T,dh)
__device__ __half g_qv[BB*NH*TT*DHEAD];   // q + v_bias
__device__ __half g_k [BB*NH*TT*DHEAD];
__device__ __half g_vt[BB*NH*DHEAD*TT];   // V transposed (B,H,dh,T)
__device__ __half g_p [NH*LPOS*DHEAD];    // (H, L, dh)
__device__ __half g_z [BB*TT*NH*DHEAD];   // (B, T, H, dh)
__device__ __half g_xr[BB*TT*DMODEL];     // xs
__device__ __half g_wq[HDIM*DMODEL];      // W^T [n][k]
__device__ __half g_wk[HDIM*DMODEL];
__device__ __half g_wv[HDIM*DMODEL];
__device__ __half g_wo[DMODEL*HDIM];      // Wout^T [n][k]
__device__ unsigned g_mb[BB*TT*(TT/32)];  // bit-packed mask

// ------------------------- helpers -------------------------
// D(16x8,f32) += A(16x16,f16) * B(16x8,f16)
__device__ __forceinline__ void mma16(float* c, const uint32_t* a, uint32_t b0, uint32_t b1) {
    asm volatile(
        "mma.sync.aligned.m16n8k16.row.col.f32.f16.f16.f32 "
        "{%0,%1,%2,%3}, {%4,%5,%6,%7}, {%8,%9}, {%0,%1,%2,%3};"
        : "+f"(c[0]), "+f"(c[1]), "+f"(c[2]), "+f"(c[3])
        : "r"(a[0]), "r"(a[1]), "r"(a[2]), "r"(a[3]), "r"(b0), "r"(b1));
}

__device__ __forceinline__ void cpa16(void* dst, const void* src) {
    uint32_t d = (uint32_t)__cvta_generic_to_shared(dst);
    asm volatile("cp.async.cg.shared.global [%0], [%1], 16;" :: "r"(d), "l"(src));
}
#define CP_COMMIT() asm volatile("cp.async.commit_group;")

// ============================================================================
// prep: xs -> fp16
// ============================================================================
__global__ void prep_x(const float* __restrict__ xs)
{
    int n4 = BB*TT*DMODEL/4;
    for (int i = blockIdx.x*blockDim.x + threadIdx.x; i < n4; i += gridDim.x*blockDim.x) {
        float4 v = ((const float4*)xs)[i];
        ((__half2*)g_xr)[i*2]   = __floats2half2_rn(v.x, v.y);
        ((__half2*)g_xr)[i*2+1] = __floats2half2_rn(v.z, v.w);
    }
}

// ============================================================================
// prep: transpose + cvt the 4 weight matrices to fp16 [n][k]
// ============================================================================
__global__ void prep_wT(const float* __restrict__ Wq, const float* __restrict__ Wk,
                        const float* __restrict__ Wv, const float* __restrict__ Wo)
{
    __shared__ float tile[32][33];
    int which = blockIdx.z;
    const float* src = (which == 0) ? Wq : (which == 1) ? Wk : (which == 2) ? Wv : Wo;
    __half* dst = (which == 0) ? g_wq : (which == 1) ? g_wk : (which == 2) ? g_wv : g_wo;
    int x0 = blockIdx.x*32, y0 = blockIdx.y*32;
    int tx = threadIdx.x, ty = threadIdx.y;
#pragma unroll
    for (int i = 0; i < 4; i++)
        tile[ty + 8*i][tx] = src[(size_t)(y0 + ty + 8*i)*512 + x0 + tx];
    __syncthreads();
#pragma unroll
    for (int i = 0; i < 4; i++)
        dst[(size_t)(x0 + ty + 8*i)*512 + y0 + tx] = __float2half_rn(tile[tx][ty + 8*i]);
}

// ============================================================================
// bitpack mask
// ============================================================================
__global__ void bitpack(const int* __restrict__ mask)
{
    int w = blockIdx.x*256 + threadIdx.x;
    const int* src = mask + (size_t)w * 32;
    unsigned bits = 0;
#pragma unroll
    for (int j = 0; j < 32; j += 4) {
        int4 v = *(const int4*)(src + j);
        bits |= (unsigned)(v.x != 0) << j;
        bits |= (unsigned)(v.y != 0) << (j+1);
        bits |= (unsigned)(v.z != 0) << (j+2);
        bits |= (unsigned)(v.w != 0) << (j+3);
    }
    g_mb[w] = bits;
}

// ============================================================================
// Projections (fp16 mma, cp.async 2-stage): C = A @ Bt^T, 128x128 tile, K=512.
// A [m][k] half, Bt [n][k] half.  Stage K=64: A tile 128x64, B tile 128x64.
// smem rows: 64 halfs + pad = 144 B (36 u32).  8 warps, warp 32m x 64n.
// Layout (bytes): A0@0, A1@18432, B0@36864, B1@55296  (total 73728)
// ============================================================================
#define PROJ_SMEM 73728

__device__ __forceinline__ void proj_prefetch(char* smc, int buf, int tid,
        const __half* Ag, const __half* Bg, int m0, int n0, int k0)
{
    char* aB = smc + buf*18432;
    char* bB = smc + 36864 + buf*18432;
    for (int e = tid; e < 1024; e += 256) {
        int r = e >> 3, ch = (e & 7) * 8;
        cpa16(aB + r*144 + ch*2, Ag + (size_t)(m0 + r)*512 + k0 + ch);
        cpa16(bB + r*144 + ch*2, Bg + (size_t)(n0 + r)*512 + k0 + ch);
    }
}

__device__ __forceinline__ void proj_core(char* smc, int tid,
        const __half* Ag, const __half* Bg, int m0, int n0, float acc[2][8][4])
{
    const int lane = tid & 31, warp = tid >> 5;
    const int g = lane >> 2, c = lane & 3;
    const int wm = warp >> 1, wn = warp & 1;

    proj_prefetch(smc, 0, tid, Ag, Bg, m0, n0, 0); CP_COMMIT();

    for (int it = 0; it < 8; it++) {
        int buf = it & 1;
        if (it < 7) { proj_prefetch(smc, buf^1, tid, Ag, Bg, m0, n0, (it+1)*64); CP_COMMIT(); }
        if (it < 7) asm volatile("cp.async.wait_group 1;");
        else        asm volatile("cp.async.wait_group 0;");
        __syncthreads();

        const uint32_t* uA = (const uint32_t*)(smc + buf*18432);
        const uint32_t* uB = (const uint32_t*)(smc + 36864 + buf*18432);
#pragma unroll
        for (int kk = 0; kk < 4; kk++) {
            uint32_t a[2][4], b[8][2];
#pragma unroll
            for (int mt = 0; mt < 2; mt++) {
                int r = wm*32 + mt*16 + g;
                a[mt][0] = uA[r*36 + kk*8 + c];
                a[mt][1] = uA[(r+8)*36 + kk*8 + c];
                a[mt][2] = uA[r*36 + kk*8 + c + 4];
                a[mt][3] = uA[(r+8)*36 + kk*8 + c + 4];
            }
#pragma unroll
            for (int nt = 0; nt < 8; nt++) {
                int nn = wn*64 + nt*8 + g;
                b[nt][0] = uB[nn*36 + kk*8 + c];
                b[nt][1] = uB[nn*36 + kk*8 + c + 4];
            }
#pragma unroll
            for (int mt = 0; mt < 2; mt++)
#pragma unroll
                for (int nt = 0; nt < 8; nt++) mma16(acc[mt][nt], a[mt], b[nt][0], b[nt][1]);
        }
        __syncthreads();
    }
}

__global__ __launch_bounds__(256, 2)
void qkv_h(const float* __restrict__ ub, const float* __restrict__ vb)
{
    extern __shared__ char smc[];
    const int which = blockIdx.z;
    const __half* W = (which == 0) ? g_wq : (which == 1) ? g_wk : g_wv;
    const int m0 = blockIdx.x * 128;
    const int n0 = blockIdx.y * 128;
    const int tid = threadIdx.x, lane = tid & 31, warp = tid >> 5;
    const int g = lane >> 2, c = lane & 3;
    const int wm = warp >> 1, wn = warp & 1;

    float acc[2][8][4] = {};
    proj_core(smc, tid, g_xr, W, m0, n0, acc);

#pragma unroll
    for (int mt = 0; mt < 2; mt++) {
#pragma unroll
        for (int nt = 0; nt < 8; nt++) {
            int n = n0 + wn*64 + nt*8 + 2*c;
            int h = n >> 6, d = n & 63;
#pragma unroll
            for (int half = 0; half < 2; half++) {
                int m = m0 + wm*32 + mt*16 + g + half*8;
                int bidx = m >> 10, t = m & (TT-1);
                float v0 = acc[mt][nt][half*2+0], v1 = acc[mt][nt][half*2+1];
                if (which == 0) {
                    size_t o = (((size_t)bidx*NH + h)*TT + t)*DHEAD + d;
                    *(__half2*)&g_qu[o] = __floats2half2_rn(v0 + ub[n], v1 + ub[n+1]);
                    *(__half2*)&g_qv[o] = __floats2half2_rn(v0 + vb[n], v1 + vb[n+1]);
                } else if (which == 1) {
                    size_t o = (((size_t)bidx*NH + h)*TT + t)*DHEAD + d;
                    *(__half2*)&g_k[o] = __floats2half2_rn(v0, v1);
                } else {
                    size_t ob = (((size_t)bidx*NH + h)*DHEAD + d)*TT + t;
                    g_vt[ob]      = __float2half_rn(v0);
                    g_vt[ob + TT] = __float2half_rn(v1);
                }
            }
        }
    }
}

__global__ __launch_bounds__(256, 2)
void out_h(float* __restrict__ out)
{
    extern __shared__ char smc[];
    const int m0 = blockIdx.x * 128;
    const int n0 = blockIdx.y * 128;
    const int tid = threadIdx.x, lane = tid & 31, warp = tid >> 5;
    const int g = lane >> 2, c = lane & 3;
    const int wm = warp >> 1, wn = warp & 1;

    float acc[2][8][4] = {};
    proj_core(smc, tid, g_z, g_wo, m0, n0, acc);

#pragma unroll
    for (int mt = 0; mt < 2; mt++) {
#pragma unroll
        for (int nt = 0; nt < 8; nt++) {
            int n = n0 + wn*64 + nt*8 + 2*c;
#pragma unroll
            for (int half = 0; half < 2; half++) {
                int m = m0 + wm*32 + mt*16 + g + half*8;
                *(float2*)&out[(size_t)m*DMODEL + n] =
                    make_float2(acc[mt][nt][half*2+0], acc[mt][nt][half*2+1]);
            }
        }
    }
}

// ============================================================================
// Positional projection (SIMT fp32, output fp16)
// ============================================================================
__global__ __launch_bounds__(256, 2)
void pos_kernel(const float* __restrict__ Wpos)
{
    __shared__ float As[16][68];
    __shared__ float Bs[16][64];
    __shared__ float fT[512];
    const int m0 = blockIdx.x * 64;
    const int n0 = blockIdx.y * 64;
    const int tid = threadIdx.x;
    const int ty = tid >> 4, tx = tid & 15;
    const float LN1E4 = 9.210340371976184f;

    for (int i = tid; i < 512; i += 256)
        fT[i] = expf(-LN1E4 * (float)(i & ~1) / (float)DMODEL);
    __syncthreads();

    float acc[4][4];
#pragma unroll
    for (int i = 0; i < 4; i++)
#pragma unroll
        for (int j = 0; j < 4; j++) acc[i][j] = 0.f;

    const int arow = tid >> 2;
    const int akk  = (tid & 3) * 4;
    const int bn   = tid & 63;
    const int bkk0 = tid >> 6;

    const int m = m0 + arow;
    const float pos = (float)(m - (TT - 1));

    for (int k0 = 0; k0 < DMODEL; k0 += 16) {
#pragma unroll
        for (int j = 0; j < 4; j++) {
            int cc = k0 + akk + j;
            float ang = pos * fT[cc];
            As[akk+j][arow] = (m < LPOS) ? ((cc & 1) ? cosf(ang) : sinf(ang)) : 0.f;
        }
#pragma unroll
        for (int r = 0; r < 4; r++)
            Bs[bkk0 + 4*r][bn] = Wpos[(size_t)(k0 + bkk0 + 4*r) * HDIM + n0 + bn];
        __syncthreads();
#pragma unroll
        for (int kk = 0; kk < 16; kk++) {
            float4 a = *(const float4*)&As[kk][ty*4];
            float4 b = *(const float4*)&Bs[kk][tx*4];
            float av[4] = {a.x,a.y,a.z,a.w};
            float bv[4] = {b.x,b.y,b.z,b.w};
#pragma unroll
            for (int i = 0; i < 4; i++)
#pragma unroll
                for (int j = 0; j < 4; j++) acc[i][j] += av[i]*bv[j];
        }
        __syncthreads();
    }

#pragma unroll
    for (int i = 0; i < 4; i++) {
        int l = m0 + ty*4 + i;
        if (l >= LPOS) continue;
        int n = n0 + tx*4;
        int h = n >> 6, d = n & 63;
        size_t idx = ((size_t)h*LPOS + l)*DHEAD + d;
        *(__half2*)&g_p[idx]   = __floats2half2_rn(acc[i][0], acc[i][1]);
        *(__half2*)&g_p[idx+2] = __floats2half2_rn(acc[i][2], acc[i][3]);
    }
}

// ============================================================================
// Fused attention (fp16 mma): 128-query block, 8 warps, circular P window,
// bit-packed mask, cp.async double-buffered K/V.
// smem bytes: K 2x9216 @0, V 2x9216 @18432, P 320x144 @36864,
//             BD f32 128x84 @82944, S half2 128x36u32 @125952 -> total 144384
// ============================================================================
#define ATTN_SMEM 144384

__global__ __launch_bounds__(256, 1)
void attn_h()
{
    extern __shared__ char smc[];
    float*    sBD = (float*)(smc + 82944);
    uint32_t* uS  = (uint32_t*)(smc + 125952);
    const uint32_t* uP = (const uint32_t*)(smc + 36864);

    const int tid = threadIdx.x, lane = tid & 31, warp = tid >> 5;
    const int g = lane >> 2, c = lane & 3;
    const int t0 = blockIdx.x * 128;
    const int bh = blockIdx.y;
    const int b = bh >> 3, h = bh & 7;
    const int rl = warp*16 + g;
    const int rh = rl + 8;
    const int tb = 14 - 2*warp;

    const __half* qu  = g_qu + ((size_t)bh * TT + t0) * DHEAD;
    const __half* qv  = g_qv + ((size_t)bh * TT + t0) * DHEAD;
    const __half* kp  = g_k  + (size_t)bh * TT * DHEAD;
    const __half* vtp = g_vt + (size_t)bh * DHEAD * TT;
    const __half* pp  = g_p  + (size_t)h * LPOS * DHEAD;
    const int l00 = 896 - t0;

    // prefill: P rows 0..254, K/V tile 0
    for (int e = tid; e < 255*8; e += 256) {
        int r = e >> 3, ch = (e & 7) * 8;
        cpa16(smc + 36864 + r*144 + ch*2, pp + (size_t)(l00 + r)*DHEAD + ch);
    }
    for (int e = tid; e < 512; e += 256) {
        int r = e >> 3, ch = (e & 7) * 8;
        cpa16(smc + r*144 + ch*2, kp + (size_t)r*DHEAD + ch);
        cpa16(smc + 18432 + r*144 + ch*2, vtp + (size_t)r*TT + ch);
    }
    CP_COMMIT();

    // Q fragments (half2-packed, 4 k16 steps)
    const uint32_t* qu32 = (const uint32_t*)qu;
    const uint32_t* qv32 = (const uint32_t*)qv;
    uint32_t quf[4][4], qvf[4][4];
#pragma unroll
    for (int kk = 0; kk < 4; kk++) {
        quf[kk][0] = qu32[rl*32 + kk*8 + c];
        quf[kk][1] = qu32[rh*32 + kk*8 + c];
        quf[kk][2] = qu32[rl*32 + kk*8 + c + 4];
        quf[kk][3] = qu32[rh*32 + kk*8 + c + 4];
        qvf[kk][0] = qv32[rl*32 + kk*8 + c];
        qvf[kk][1] = qv32[rh*32 + kk*8 + c];
        qvf[kk][2] = qv32[rl*32 + kk*8 + c + 4];
        qvf[kk][3] = qv32[rh*32 + kk*8 + c + 4];
    }

    float o[8][4] = {};
    float rmax_lo = -1e30f, rmax_hi = -1e30f;
    float rsum_lo = 0.f, rsum_hi = 0.f;

    for (int it = 0; it < 16; it++) {
        const int buf = it & 1;
        const int s0 = it * 64;

        if (it < 15) {
            char* bK = smc + (buf^1)*9216;
            char* bV = smc + 18432 + (buf^1)*9216;
            for (int e = tid; e < 512; e += 256) {
                int r = e >> 3, ch = (e & 7) * 8;
                cpa16(bK + r*144 + ch*2, kp + (size_t)(s0 + 64 + r)*DHEAD + ch);
                cpa16(bV + r*144 + ch*2, vtp + (size_t)r*TT + s0 + 64 + ch);
            }
            if (it <= 13) {
                int start = (it*64 + 255) % PROWS;
                for (int e = tid; e < 512; e += 256) {
                    int r = e >> 3, ch = (e & 7) * 8;
                    int slot = start + r; if (slot >= PROWS) slot -= PROWS;
                    cpa16(smc + 36864 + slot*144 + ch*2,
                          pp + (size_t)(l00 + it*64 + 255 + r)*DHEAD + ch);
                }
            }
            CP_COMMIT();
        }
        if (it < 15) asm volatile("cp.async.wait_group 1;");
        else         asm volatile("cp.async.wait_group 0;");
        __syncthreads();

        const uint32_t* uK = (const uint32_t*)(smc + buf*9216);
        const uint32_t* uV = (const uint32_t*)(smc + 18432 + buf*9216);

        // ---- BD band GEMM: 10 n8-tiles per warp, 4 k16 steps ----
        {
            int rowb[10];
            const int p5 = (it % 5) * 64;
#pragma unroll
            for (int j = 0; j < 10; j++) {
                int rb = p5 + (tb + j)*8;
                if (rb >= PROWS) rb -= PROWS;
                rowb[j] = rb;
            }
            float bd[10][4] = {};
#pragma unroll
            for (int kk = 0; kk < 4; kk++) {
#pragma unroll
                for (int j = 0; j < 10; j++) {
                    int nn = rowb[j] + g;
                    mma16(bd[j], qvf[kk], uP[nn*36 + kk*8 + c], uP[nn*36 + kk*8 + c + 4]);
                }
            }
#pragma unroll
            for (int j = 0; j < 10; j++) {
                int cb = j*8 + 2*c;
                sBD[rl*BDST + cb]   = bd[j][0];
                sBD[rl*BDST + cb+1] = bd[j][1];
                sBD[rh*BDST + cb]   = bd[j][2];
                sBD[rh*BDST + cb+1] = bd[j][3];
            }
        }
        __syncwarp();

        // ---- AC GEMM ----
        float acc[8][4] = {};
#pragma unroll
        for (int kk = 0; kk < 4; kk++) {
#pragma unroll
            for (int nt = 0; nt < 8; nt++) {
                int nn = nt*8 + g;
                mma16(acc[nt], quf[kk], uK[nn*36 + kk*8 + c], uK[nn*36 + kk*8 + c + 4]);
            }
        }

        // ---- mask bits ----
        uint2 mwl = *(const uint2*)(g_mb + ((size_t)b*TT + t0 + rl)*32 + (s0 >> 5));
        uint2 mwh = *(const uint2*)(g_mb + ((size_t)b*TT + t0 + rh)*32 + (s0 >> 5));

        // ---- combine ac + shifted bd, mask, scale, online softmax ----
        const int baseL = rl*BDST - g + 15;
        const int baseH = rh*BDST - g + 7;
        float mx_lo = -1e30f, mx_hi = -1e30f;
#pragma unroll
        for (int nt = 0; nt < 8; nt++) {
            int cb = nt*8 + 2*c;
            unsigned wl = (cb & 32) ? mwl.y : mwl.x;
            unsigned wh = (cb & 32) ? mwh.y : mwh.x;
            int sh = cb & 31;
            float v;
            v = (acc[nt][0] + sBD[baseL + cb])   * 0.125f;
            acc[nt][0] = ((wl >> sh)     & 1) ? v : -1e30f;
            v = (acc[nt][1] + sBD[baseL + cb+1]) * 0.125f;
            acc[nt][1] = ((wl >> (sh+1)) & 1) ? v : -1e30f;
            v = (acc[nt][2] + sBD[baseH + cb])   * 0.125f;
            acc[nt][2] = ((wh >> sh)     & 1) ? v : -1e30f;
            v = (acc[nt][3] + sBD[baseH + cb+1]) * 0.125f;
            acc[nt][3] = ((wh >> (sh+1)) & 1) ? v : -1e30f;
            mx_lo = fmaxf(mx_lo, fmaxf(acc[nt][0], acc[nt][1]));
            mx_hi = fmaxf(mx_hi, fmaxf(acc[nt][2], acc[nt][3]));
        }
        mx_lo = fmaxf(mx_lo, __shfl_xor_sync(0xffffffffu, mx_lo, 1));
        mx_lo = fmaxf(mx_lo, __shfl_xor_sync(0xffffffffu, mx_lo, 2));
        mx_hi = fmaxf(mx_hi, __shfl_xor_sync(0xffffffffu, mx_hi, 1));
        mx_hi = fmaxf(mx_hi, __shfl_xor_sync(0xffffffffu, mx_hi, 2));

        float nm_lo = fmaxf(rmax_lo, mx_lo);
        float nm_hi = fmaxf(rmax_hi, mx_hi);
        float corr_lo = __expf(rmax_lo - nm_lo);
        float corr_hi = __expf(rmax_hi - nm_hi);
        rmax_lo = nm_lo; rmax_hi = nm_hi;

        float ts_lo = 0.f, ts_hi = 0.f;
#pragma unroll
        for (int nt = 0; nt < 8; nt++) {
            float p0 = __expf(acc[nt][0] - nm_lo);
            float p1 = __expf(acc[nt][1] - nm_lo);
            float p2 = __expf(acc[nt][2] - nm_hi);
            float p3 = __expf(acc[nt][3] - nm_hi);
            ts_lo += p0 + p1; ts_hi += p2 + p3;
            __half2 hl = __floats2half2_rn(p0, p1);
            __half2 hh = __floats2half2_rn(p2, p3);
            uS[rl*36 + nt*4 + c] = *(uint32_t*)&hl;
            uS[rh*36 + nt*4 + c] = *(uint32_t*)&hh;
            o[nt][0] *= corr_lo; o[nt][1] *= corr_lo;
            o[nt][2] *= corr_hi; o[nt][3] *= corr_hi;
        }
        ts_lo += __shfl_xor_sync(0xffffffffu, ts_lo, 1);
        ts_lo += __shfl_xor_sync(0xffffffffu, ts_lo, 2);
        ts_hi += __shfl_xor_sync(0xffffffffu, ts_hi, 1);
        ts_hi += __shfl_xor_sync(0xffffffffu, ts_hi, 2);
        rsum_lo = rsum_lo * corr_lo + ts_lo;
        rsum_hi = rsum_hi * corr_hi + ts_hi;
        __syncwarp();

        // ---- PV GEMM: O += exp(S) @ V ----
#pragma unroll
        for (int kk = 0; kk < 4; kk++) {
            uint32_t a[4];
            a[0] = uS[rl*36 + kk*8 + c];
            a[1] = uS[rh*36 + kk*8 + c];
            a[2] = uS[rl*36 + kk*8 + c + 4];
            a[3] = uS[rh*36 + kk*8 + c + 4];
#pragma unroll
            for (int nt = 0; nt < 8; nt++) {
                int nn = nt*8 + g;
                mma16(o[nt], a, uV[nn*36 + kk*8 + c], uV[nn*36 + kk*8 + c + 4]);
            }
        }
        __syncthreads();
    }

    // ---- normalize + write z (B,T,H,dh) fp16 ----
    float inv_lo = 1.f / rsum_lo, inv_hi = 1.f / rsum_hi;
#pragma unroll
    for (int nt = 0; nt < 8; nt++) {
        int d = nt*8 + 2*c;
        *(__half2*)&g_z[(((size_t)b*TT + (t0+rl))*NH + h)*DHEAD + d] =
            __floats2half2_rn(o[nt][0]*inv_lo, o[nt][1]*inv_lo);
        *(__half2*)&g_z[(((size_t)b*TT + (t0+rh))*NH + h)*DHEAD + d] =
            __floats2half2_rn(o[nt][2]*inv_hi, o[nt][3]*inv_hi);
    }
}

// ============================================================================
extern "C" void kernel_launch(void* const* d_in, const int* in_sizes, int n_in,
                              void* d_out, int out_size)
{
    const float* xs   = (const float*)d_in[0];
    const int*   mask = (const int*)  d_in[1];
    const float* Wq   = (const float*)d_in[2];
    const float* Wk   = (const float*)d_in[3];
    const float* Wv   = (const float*)d_in[4];
    const float* Wpos = (const float*)d_in[5];
    const float* Wout = (const float*)d_in[6];
    const float* ub   = (const float*)d_in[7];
    const float* vb   = (const float*)d_in[8];
    float* out = (float*)d_out;

    cudaFuncSetAttribute(attn_h, cudaFuncAttributeMaxDynamicSharedMemorySize, ATTN_SMEM);
    cudaFuncSetAttribute(qkv_h,  cudaFuncAttributeMaxDynamicSharedMemorySize, PROJ_SMEM);
    cudaFuncSetAttribute(out_h,  cudaFuncAttributeMaxDynamicSharedMemorySize, PROJ_SMEM);

    prep_x<<<2048, 256>>>(xs);
    prep_wT<<<dim3(16, 16, 4), dim3(32, 8)>>>(Wq, Wk, Wv, Wout);
    bitpack<<<1024, 256>>>(mask);
    pos_kernel<<<dim3(32, 8), 256>>>(Wpos);
    qkv_h<<<dim3(64, 4, 3), 256, PROJ_SMEM>>>(ub, vb);
    attn_h<<<dim3(8, 64), 256, ATTN_SMEM>>>();
    out_h<<<dim3(64, 4), 256, PROJ_SMEM>>>(out);
}

// round 7
// speedup vs baseline: 6.9868x; 1.2024x over previous
#include <cuda_runtime.h>
#include <cuda_fp16.h>
#include <math.h>
#include <stdint.h>

#define BB     8
#define TT     1024
#define DMODEL 512
#define NH     8
#define DHEAD  64
#define HDIM   512
#define LPOS   2047   // 2T-1
#define BDST   84     // BD f32 row stride
#define PROWS  320    // circular P window rows (5 x 64)

// ------------------------- scratch (static device memory, fp16) -------------------------
__device__ __half g_qu[BB*NH*TT*DHEAD];   // q + u_bias, (B,H,T,dh)
__device__ __half g_qv[BB*NH*TT*DHEAD];   // q + v_bias
__device__ __half g_k [BB*NH*TT*DHEAD];
__device__ __half g_vt[BB*NH*DHEAD*TT];   // V transposed (B,H,dh,T)
__device__ __half g_p [NH*LPOS*DHEAD];    // (H, L, dh)
__device__ __half g_z [BB*TT*NH*DHEAD];   // (B, T, H, dh)
__device__ __half g_xr[BB*TT*DMODEL];     // xs
__device__ __half g_pe[2048*DMODEL];      // sinusoidal table (row 2047 = 0)
__device__ __half g_wq[HDIM*DMODEL];      // W^T [n][k]
__device__ __half g_wk[HDIM*DMODEL];
__device__ __half g_wv[HDIM*DMODEL];
__device__ __half g_wo[DMODEL*HDIM];      // Wout^T [n][k]
__device__ __half g_wp[HDIM*DMODEL];      // Wpos^T [n][k]
__device__ unsigned g_mb[BB*TT*(TT/32)];  // bit-packed mask

// ------------------------- helpers -------------------------
// D(16x8,f32) += A(16x16,f16) * B(16x8,f16)
__device__ __forceinline__ void mma16(float* c, const uint32_t* a, uint32_t b0, uint32_t b1) {
    asm volatile(
        "mma.sync.aligned.m16n8k16.row.col.f32.f16.f16.f32 "
        "{%0,%1,%2,%3}, {%4,%5,%6,%7}, {%8,%9}, {%0,%1,%2,%3};"
        : "+f"(c[0]), "+f"(c[1]), "+f"(c[2]), "+f"(c[3])
        : "r"(a[0]), "r"(a[1]), "r"(a[2]), "r"(a[3]), "r"(b0), "r"(b1));
}

__device__ __forceinline__ void cpa16(void* dst, const void* src) {
    uint32_t d = (uint32_t)__cvta_generic_to_shared(dst);
    asm volatile("cp.async.cg.shared.global [%0], [%1], 16;" :: "r"(d), "l"(src));
}
#define CP_COMMIT() asm volatile("cp.async.commit_group;")

// ============================================================================
// prep: xs -> fp16
// ============================================================================
__global__ void prep_x(const float* __restrict__ xs)
{
    int n4 = BB*TT*DMODEL/4;
    for (int i = blockIdx.x*blockDim.x + threadIdx.x; i < n4; i += gridDim.x*blockDim.x) {
        float4 v = ((const float4*)xs)[i];
        ((__half2*)g_xr)[i*2]   = __floats2half2_rn(v.x, v.y);
        ((__half2*)g_xr)[i*2+1] = __floats2half2_rn(v.z, v.w);
    }
}

// ============================================================================
// prep: sinusoidal table pe[l][d] fp16, computed ONCE (accurate sincosf).
// grid 2048, block 256 (one thread per (l, col-pair)).
// ============================================================================
__global__ void prep_pe()
{
    int l = blockIdx.x;
    int cp = threadIdx.x;           // column pair: d = 2*cp (sin), 2*cp+1 (cos)
    float freq = expf(-9.210340371976184f * (float)(2*cp) / (float)DMODEL);
    float s, c;
    sincosf((float)(l - (TT - 1)) * freq, &s, &c);
    __half2 v = (l < LPOS) ? __floats2half2_rn(s, c) : __floats2half2_rn(0.f, 0.f);
    ((__half2*)g_pe)[l*(DMODEL/2) + cp] = v;
}

// ============================================================================
// prep: transpose + cvt the 5 weight matrices to fp16 [n][k]
// ============================================================================
__global__ void prep_wT(const float* __restrict__ Wq, const float* __restrict__ Wk,
                        const float* __restrict__ Wv, const float* __restrict__ Wo,
                        const float* __restrict__ Wp)
{
    __shared__ float tile[32][33];
    int which = blockIdx.z;
    const float* src = (which == 0) ? Wq : (which == 1) ? Wk : (which == 2) ? Wv
                     : (which == 3) ? Wo : Wp;
    __half* dst = (which == 0) ? g_wq : (which == 1) ? g_wk : (which == 2) ? g_wv
                : (which == 3) ? g_wo : g_wp;
    int x0 = blockIdx.x*32, y0 = blockIdx.y*32;
    int tx = threadIdx.x, ty = threadIdx.y;
#pragma unroll
    for (int i = 0; i < 4; i++)
        tile[ty + 8*i][tx] = src[(size_t)(y0 + ty + 8*i)*512 + x0 + tx];
    __syncthreads();
#pragma unroll
    for (int i = 0; i < 4; i++)
        dst[(size_t)(x0 + ty + 8*i)*512 + y0 + tx] = __float2half_rn(tile[tx][ty + 8*i]);
}

// ============================================================================
// bitpack mask
// ============================================================================
__global__ void bitpack(const int* __restrict__ mask)
{
    int w = blockIdx.x*256 + threadIdx.x;
    const int* src = mask + (size_t)w * 32;
    unsigned bits = 0;
#pragma unroll
    for (int j = 0; j < 32; j += 4) {
        int4 v = *(const int4*)(src + j);
        bits |= (unsigned)(v.x != 0) << j;
        bits |= (unsigned)(v.y != 0) << (j+1);
        bits |= (unsigned)(v.z != 0) << (j+2);
        bits |= (unsigned)(v.w != 0) << (j+3);
    }
    g_mb[w] = bits;
}

// ============================================================================
// Projections (fp16 mma, cp.async 2-stage): C = A @ Bt^T, 128x128 tile, K=512.
// Layout (bytes): A0@0, A1@18432, B0@36864, B1@55296  (total 73728)
// ============================================================================
#define PROJ_SMEM 73728

__device__ __forceinline__ void proj_prefetch(char* smc, int buf, int tid,
        const __half* Ag, const __half* Bg, int m0, int n0, int k0)
{
    char* aB = smc + buf*18432;
    char* bB = smc + 36864 + buf*18432;
    for (int e = tid; e < 1024; e += 256) {
        int r = e >> 3, ch = (e & 7) * 8;
        cpa16(aB + r*144 + ch*2, Ag + (size_t)(m0 + r)*512 + k0 + ch);
        cpa16(bB + r*144 + ch*2, Bg + (size_t)(n0 + r)*512 + k0 + ch);
    }
}

__device__ __forceinline__ void proj_core(char* smc, int tid,
        const __half* Ag, const __half* Bg, int m0, int n0, float acc[2][8][4])
{
    const int lane = tid & 31, warp = tid >> 5;
    const int g = lane >> 2, c = lane & 3;
    const int wm = warp >> 1, wn = warp & 1;

    proj_prefetch(smc, 0, tid, Ag, Bg, m0, n0, 0); CP_COMMIT();

    for (int it = 0; it < 8; it++) {
        int buf = it & 1;
        if (it < 7) { proj_prefetch(smc, buf^1, tid, Ag, Bg, m0, n0, (it+1)*64); CP_COMMIT(); }
        if (it < 7) asm volatile("cp.async.wait_group 1;");
        else        asm volatile("cp.async.wait_group 0;");
        __syncthreads();

        const uint32_t* uA = (const uint32_t*)(smc + buf*18432);
        const uint32_t* uB = (const uint32_t*)(smc + 36864 + buf*18432);
#pragma unroll
        for (int kk = 0; kk < 4; kk++) {
            uint32_t a[2][4], b[8][2];
#pragma unroll
            for (int mt = 0; mt < 2; mt++) {
                int r = wm*32 + mt*16 + g;
                a[mt][0] = uA[r*36 + kk*8 + c];
                a[mt][1] = uA[(r+8)*36 + kk*8 + c];
                a[mt][2] = uA[r*36 + kk*8 + c + 4];
                a[mt][3] = uA[(r+8)*36 + kk*8 + c + 4];
            }
#pragma unroll
            for (int nt = 0; nt < 8; nt++) {
                int nn = wn*64 + nt*8 + g;
                b[nt][0] = uB[nn*36 + kk*8 + c];
                b[nt][1] = uB[nn*36 + kk*8 + c + 4];
            }
#pragma unroll
            for (int mt = 0; mt < 2; mt++)
#pragma unroll
                for (int nt = 0; nt < 8; nt++) mma16(acc[mt][nt], a[mt], b[nt][0], b[nt][1]);
        }
        __syncthreads();
    }
}

__global__ __launch_bounds__(256, 2)
void qkv_h(const float* __restrict__ ub, const float* __restrict__ vb)
{
    extern __shared__ char smc[];
    const int which = blockIdx.z;
    const __half* W = (which == 0) ? g_wq : (which == 1) ? g_wk : g_wv;
    const int m0 = blockIdx.x * 128;
    const int n0 = blockIdx.y * 128;
    const int tid = threadIdx.x, lane = tid & 31, warp = tid >> 5;
    const int g = lane >> 2, c = lane & 3;
    const int wm = warp >> 1, wn = warp & 1;

    float acc[2][8][4] = {};
    proj_core(smc, tid, g_xr, W, m0, n0, acc);

#pragma unroll
    for (int mt = 0; mt < 2; mt++) {
#pragma unroll
        for (int nt = 0; nt < 8; nt++) {
            int n = n0 + wn*64 + nt*8 + 2*c;
            int h = n >> 6, d = n & 63;
#pragma unroll
            for (int half = 0; half < 2; half++) {
                int m = m0 + wm*32 + mt*16 + g + half*8;
                int bidx = m >> 10, t = m & (TT-1);
                float v0 = acc[mt][nt][half*2+0], v1 = acc[mt][nt][half*2+1];
                if (which == 0) {
                    size_t o = (((size_t)bidx*NH + h)*TT + t)*DHEAD + d;
                    *(__half2*)&g_qu[o] = __floats2half2_rn(v0 + ub[n], v1 + ub[n+1]);
                    *(__half2*)&g_qv[o] = __floats2half2_rn(v0 + vb[n], v1 + vb[n+1]);
                } else if (which == 1) {
                    size_t o = (((size_t)bidx*NH + h)*TT + t)*DHEAD + d;
                    *(__half2*)&g_k[o] = __floats2half2_rn(v0, v1);
                } else {
                    size_t ob = (((size_t)bidx*NH + h)*DHEAD + d)*TT + t;
                    g_vt[ob]      = __float2half_rn(v0);
                    g_vt[ob + TT] = __float2half_rn(v1);
                }
            }
        }
    }
}

__global__ __launch_bounds__(256, 2)
void out_h(float* __restrict__ out)
{
    extern __shared__ char smc[];
    const int m0 = blockIdx.x * 128;
    const int n0 = blockIdx.y * 128;
    const int tid = threadIdx.x, lane = tid & 31, warp = tid >> 5;
    const int g = lane >> 2, c = lane & 3;
    const int wm = warp >> 1, wn = warp & 1;

    float acc[2][8][4] = {};
    proj_core(smc, tid, g_z, g_wo, m0, n0, acc);

#pragma unroll
    for (int mt = 0; mt < 2; mt++) {
#pragma unroll
        for (int nt = 0; nt < 8; nt++) {
            int n = n0 + wn*64 + nt*8 + 2*c;
#pragma unroll
            for (int half = 0; half < 2; half++) {
                int m = m0 + wm*32 + mt*16 + g + half*8;
                *(float2*)&out[(size_t)m*DMODEL + n] =
                    make_float2(acc[mt][nt][half*2+0], acc[mt][nt][half*2+1]);
            }
        }
    }
}

// ============================================================================
// Positional projection (fp16 mma): p = pe @ Wpos.  grid (16, 4).
// ============================================================================
__global__ __launch_bounds__(256, 2)
void pos_h()
{
    extern __shared__ char smc[];
    const int m0 = blockIdx.x * 128;
    const int n0 = blockIdx.y * 128;
    const int tid = threadIdx.x, lane = tid & 31, warp = tid >> 5;
    const int g = lane >> 2, c = lane & 3;
    const int wm = warp >> 1, wn = warp & 1;

    float acc[2][8][4] = {};
    proj_core(smc, tid, g_pe, g_wp, m0, n0, acc);

#pragma unroll
    for (int mt = 0; mt < 2; mt++) {
#pragma unroll
        for (int nt = 0; nt < 8; nt++) {
            int n = n0 + wn*64 + nt*8 + 2*c;
            int h = n >> 6, d = n & 63;
#pragma unroll
            for (int half = 0; half < 2; half++) {
                int l = m0 + wm*32 + mt*16 + g + half*8;
                if (l >= LPOS) continue;
                *(__half2*)&g_p[((size_t)h*LPOS + l)*DHEAD + d] =
                    __floats2half2_rn(acc[mt][nt][half*2+0], acc[mt][nt][half*2+1]);
            }
        }
    }
}

// ============================================================================
// Fused attention (fp16 mma): 128-query block, 8 warps, circular P window,
// bit-packed mask, cp.async double-buffered K/V, S kept in registers.
// smem bytes: K 2x9216 @0, V 2x9216 @18432, P 320x144 @36864,
//             BD f32 128x84 @82944 -> total 125952
// ============================================================================
#define ATTN_SMEM 125952

__global__ __launch_bounds__(256, 1)
void attn_h()
{
    extern __shared__ char smc[];
    float* sBD = (float*)(smc + 82944);
    const uint32_t* uP = (const uint32_t*)(smc + 36864);

    const int tid = threadIdx.x, lane = tid & 31, warp = tid >> 5;
    const int g = lane >> 2, c = lane & 3;
    const int t0 = blockIdx.x * 128;
    const int bh = blockIdx.y;
    const int b = bh >> 3, h = bh & 7;
    const int rl = warp*16 + g;
    const int rh = rl + 8;
    const int tb = 14 - 2*warp;

    const __half* qu  = g_qu + ((size_t)bh * TT + t0) * DHEAD;
    const __half* qv  = g_qv + ((size_t)bh * TT + t0) * DHEAD;
    const __half* kp  = g_k  + (size_t)bh * TT * DHEAD;
    const __half* vtp = g_vt + (size_t)bh * DHEAD * TT;
    const __half* pp  = g_p  + (size_t)h * LPOS * DHEAD;
    const int l00 = 896 - t0;

    // prefill: P rows 0..254, K/V tile 0
    for (int e = tid; e < 255*8; e += 256) {
        int r = e >> 3, ch = (e & 7) * 8;
        cpa16(smc + 36864 + r*144 + ch*2, pp + (size_t)(l00 + r)*DHEAD + ch);
    }
    for (int e = tid; e < 512; e += 256) {
        int r = e >> 3, ch = (e & 7) * 8;
        cpa16(smc + r*144 + ch*2, kp + (size_t)r*DHEAD + ch);
        cpa16(smc + 18432 + r*144 + ch*2, vtp + (size_t)r*TT + ch);
    }
    CP_COMMIT();

    // Q fragments (half2-packed, 4 k16 steps)
    const uint32_t* qu32 = (const uint32_t*)qu;
    const uint32_t* qv32 = (const uint32_t*)qv;
    uint32_t quf[4][4], qvf[4][4];
#pragma unroll
    for (int kk = 0; kk < 4; kk++) {
        quf[kk][0] = qu32[rl*32 + kk*8 + c];
        quf[kk][1] = qu32[rh*32 + kk*8 + c];
        quf[kk][2] = qu32[rl*32 + kk*8 + c + 4];
        quf[kk][3] = qu32[rh*32 + kk*8 + c + 4];
        qvf[kk][0] = qv32[rl*32 + kk*8 + c];
        qvf[kk][1] = qv32[rh*32 + kk*8 + c];
        qvf[kk][2] = qv32[rl*32 + kk*8 + c + 4];
        qvf[kk][3] = qv32[rh*32 + kk*8 + c + 4];
    }

    float o[8][4] = {};
    float rmax_lo = -1e30f, rmax_hi = -1e30f;
    float rsum_lo = 0.f, rsum_hi = 0.f;

    for (int it = 0; it < 16; it++) {
        const int buf = it & 1;
        const int s0 = it * 64;

        if (it < 15) {
            char* bK = smc + (buf^1)*9216;
            char* bV = smc + 18432 + (buf^1)*9216;
            for (int e = tid; e < 512; e += 256) {
                int r = e >> 3, ch = (e & 7) * 8;
                cpa16(bK + r*144 + ch*2, kp + (size_t)(s0 + 64 + r)*DHEAD + ch);
                cpa16(bV + r*144 + ch*2, vtp + (size_t)r*TT + s0 + 64 + ch);
            }
            if (it <= 13) {
                int start = (it*64 + 255) % PROWS;
                for (int e = tid; e < 512; e += 256) {
                    int r = e >> 3, ch = (e & 7) * 8;
                    int slot = start + r; if (slot >= PROWS) slot -= PROWS;
                    cpa16(smc + 36864 + slot*144 + ch*2,
                          pp + (size_t)(l00 + it*64 + 255 + r)*DHEAD + ch);
                }
            }
            CP_COMMIT();
        }
        if (it < 15) asm volatile("cp.async.wait_group 1;");
        else         asm volatile("cp.async.wait_group 0;");
        __syncthreads();

        const uint32_t* uK = (const uint32_t*)(smc + buf*9216);
        const uint32_t* uV = (const uint32_t*)(smc + 18432 + buf*9216);

        // ---- BD band GEMM: 10 n8-tiles per warp, 4 k16 steps ----
        {
            int rowb[10];
            const int p5 = (it % 5) * 64;
#pragma unroll
            for (int j = 0; j < 10; j++) {
                int rb = p5 + (tb + j)*8;
                if (rb >= PROWS) rb -= PROWS;
                rowb[j] = rb;
            }
            float bd[10][4] = {};
#pragma unroll
            for (int kk = 0; kk < 4; kk++) {
#pragma unroll
                for (int j = 0; j < 10; j++) {
                    int nn = rowb[j] + g;
                    mma16(bd[j], qvf[kk], uP[nn*36 + kk*8 + c], uP[nn*36 + kk*8 + c + 4]);
                }
            }
#pragma unroll
            for (int j = 0; j < 10; j++) {
                int cb = j*8 + 2*c;
                sBD[rl*BDST + cb]   = bd[j][0];
                sBD[rl*BDST + cb+1] = bd[j][1];
                sBD[rh*BDST + cb]   = bd[j][2];
                sBD[rh*BDST + cb+1] = bd[j][3];
            }
        }
        __syncwarp();

        // ---- AC GEMM ----
        float acc[8][4] = {};
#pragma unroll
        for (int kk = 0; kk < 4; kk++) {
#pragma unroll
            for (int nt = 0; nt < 8; nt++) {
                int nn = nt*8 + g;
                mma16(acc[nt], quf[kk], uK[nn*36 + kk*8 + c], uK[nn*36 + kk*8 + c + 4]);
            }
        }

        // ---- mask bits ----
        uint2 mwl = *(const uint2*)(g_mb + ((size_t)b*TT + t0 + rl)*32 + (s0 >> 5));
        uint2 mwh = *(const uint2*)(g_mb + ((size_t)b*TT + t0 + rh)*32 + (s0 >> 5));

        // ---- combine ac + shifted bd, mask, scale, online softmax ----
        const int baseL = rl*BDST - g + 15;
        const int baseH = rh*BDST - g + 7;
        float mx_lo = -1e30f, mx_hi = -1e30f;
#pragma unroll
        for (int nt = 0; nt < 8; nt++) {
            int cb = nt*8 + 2*c;
            unsigned wl = (cb & 32) ? mwl.y : mwl.x;
            unsigned wh = (cb & 32) ? mwh.y : mwh.x;
            int sh = cb & 31;
            float v;
            v = (acc[nt][0] + sBD[baseL + cb])   * 0.125f;
            acc[nt][0] = ((wl >> sh)     & 1) ? v : -1e30f;
            v = (acc[nt][1] + sBD[baseL + cb+1]) * 0.125f;
            acc[nt][1] = ((wl >> (sh+1)) & 1) ? v : -1e30f;
            v = (acc[nt][2] + sBD[baseH + cb])   * 0.125f;
            acc[nt][2] = ((wh >> sh)     & 1) ? v : -1e30f;
            v = (acc[nt][3] + sBD[baseH + cb+1]) * 0.125f;
            acc[nt][3] = ((wh >> (sh+1)) & 1) ? v : -1e30f;
            mx_lo = fmaxf(mx_lo, fmaxf(acc[nt][0], acc[nt][1]));
            mx_hi = fmaxf(mx_hi, fmaxf(acc[nt][2], acc[nt][3]));
        }
        mx_lo = fmaxf(mx_lo, __shfl_xor_sync(0xffffffffu, mx_lo, 1));
        mx_lo = fmaxf(mx_lo, __shfl_xor_sync(0xffffffffu, mx_lo, 2));
        mx_hi = fmaxf(mx_hi, __shfl_xor_sync(0xffffffffu, mx_hi, 1));
        mx_hi = fmaxf(mx_hi, __shfl_xor_sync(0xffffffffu, mx_hi, 2));

        float nm_lo = fmaxf(rmax_lo, mx_lo);
        float nm_hi = fmaxf(rmax_hi, mx_hi);
        float corr_lo = __expf(rmax_lo - nm_lo);
        float corr_hi = __expf(rmax_hi - nm_hi);
        rmax_lo = nm_lo; rmax_hi = nm_hi;

        // ---- exp + pack S fragments in registers (no smem round-trip) ----
        uint32_t sfl[8], sfh[8];   // per n8-tile: lo-rows pair, hi-rows pair
        float ts_lo = 0.f, ts_hi = 0.f;
#pragma unroll
        for (int nt = 0; nt < 8; nt++) {
            float p0 = __expf(acc[nt][0] - nm_lo);
            float p1 = __expf(acc[nt][1] - nm_lo);
            float p2 = __expf(acc[nt][2] - nm_hi);
            float p3 = __expf(acc[nt][3] - nm_hi);
            ts_lo += p0 + p1; ts_hi += p2 + p3;
            __half2 hl = __floats2half2_rn(p0, p1);
            __half2 hh = __floats2half2_rn(p2, p3);
            sfl[nt] = *(uint32_t*)&hl;
            sfh[nt] = *(uint32_t*)&hh;
            o[nt][0] *= corr_lo; o[nt][1] *= corr_lo;
            o[nt][2] *= corr_hi; o[nt][3] *= corr_hi;
        }
        ts_lo += __shfl_xor_sync(0xffffffffu, ts_lo, 1);
        ts_lo += __shfl_xor_sync(0xffffffffu, ts_lo, 2);
        ts_hi += __shfl_xor_sync(0xffffffffu, ts_hi, 1);
        ts_hi += __shfl_xor_sync(0xffffffffu, ts_hi, 2);
        rsum_lo = rsum_lo * corr_lo + ts_lo;
        rsum_hi = rsum_hi * corr_hi + ts_hi;

        // ---- PV GEMM: O += exp(S) @ V, A-fragments straight from registers ----
#pragma unroll
        for (int kk = 0; kk < 4; kk++) {
            uint32_t a[4] = { sfl[2*kk], sfh[2*kk], sfl[2*kk+1], sfh[2*kk+1] };
#pragma unroll
            for (int nt = 0; nt < 8; nt++) {
                int nn = nt*8 + g;
                mma16(o[nt], a, uV[nn*36 + kk*8 + c], uV[nn*36 + kk*8 + c + 4]);
            }
        }
        __syncthreads();
    }

    // ---- normalize + write z (B,T,H,dh) fp16 ----
    float inv_lo = 1.f / rsum_lo, inv_hi = 1.f / rsum_hi;
#pragma unroll
    for (int nt = 0; nt < 8; nt++) {
        int d = nt*8 + 2*c;
        *(__half2*)&g_z[(((size_t)b*TT + (t0+rl))*NH + h)*DHEAD + d] =
            __floats2half2_rn(o[nt][0]*inv_lo, o[nt][1]*inv_lo);
        *(__half2*)&g_z[(((size_t)b*TT + (t0+rh))*NH + h)*DHEAD + d] =
            __floats2half2_rn(o[nt][2]*inv_hi, o[nt][3]*inv_hi);
    }
}

// ============================================================================
extern "C" void kernel_launch(void* const* d_in, const int* in_sizes, int n_in,
                              void* d_out, int out_size)
{
    const float* xs   = (const float*)d_in[0];
    const int*   mask = (const int*)  d_in[1];
    const float* Wq   = (const float*)d_in[2];
    const float* Wk   = (const float*)d_in[3];
    const float* Wv   = (const float*)d_in[4];
    const float* Wpos = (const float*)d_in[5];
    const float* Wout = (const float*)d_in[6];
    const float* ub   = (const float*)d_in[7];
    const float* vb   = (const float*)d_in[8];
    float* out = (float*)d_out;

    cudaFuncSetAttribute(attn_h, cudaFuncAttributeMaxDynamicSharedMemorySize, ATTN_SMEM);
    cudaFuncSetAttribute(qkv_h,  cudaFuncAttributeMaxDynamicSharedMemorySize, PROJ_SMEM);
    cudaFuncSetAttribute(out_h,  cudaFuncAttributeMaxDynamicSharedMemorySize, PROJ_SMEM);
    cudaFuncSetAttribute(pos_h,  cudaFuncAttributeMaxDynamicSharedMemorySize, PROJ_SMEM);

    prep_x<<<2048, 256>>>(xs);
    prep_pe<<<2048, 256>>>();
    prep_wT<<<dim3(16, 16, 5), dim3(32, 8)>>>(Wq, Wk, Wv, Wout, Wpos);
    bitpack<<<1024, 256>>>(mask);
    pos_h<<<dim3(16, 4), 256, PROJ_SMEM>>>();
    qkv_h<<<dim3(64, 4, 3), 256, PROJ_SMEM>>>(ub, vb);
    attn_h<<<dim3(8, 64), 256, ATTN_SMEM>>>();
    out_h<<<dim3(64, 4), 256, PROJ_SMEM>>>(out);
}

// round 10
// speedup vs baseline: 7.5765x; 1.0844x over previous
#include <cuda_runtime.h>
#include <cuda_fp16.h>
#include <math.h>
#include <stdint.h>

#define BB     8
#define TT     1024
#define DMODEL 512
#define NH     8
#define DHEAD  64
#define HDIM   512
#define LPOS   2047   // 2T-1
#define BDST   84     // BD f32 row stride
#define PROWS  320    // circular P window rows (5 x 64)

// ------------------------- scratch (static device memory, fp16) -------------------------
__device__ __half g_qu[BB*NH*TT*DHEAD];   // q + u_bias, (B,H,T,dh)
__device__ __half g_qv[BB*NH*TT*DHEAD];   // q + v_bias
__device__ __half g_k [BB*NH*TT*DHEAD];
__device__ __half g_vt[BB*NH*DHEAD*TT];   // V transposed (B,H,dh,T)
__device__ __half g_p [NH*LPOS*DHEAD];    // (H, L, dh)
__device__ __half g_z [BB*TT*NH*DHEAD];   // (B, T, H, dh)
__device__ __half g_xr[BB*TT*DMODEL];     // xs
__device__ __half g_pe[2048*DMODEL];      // sinusoidal table (row 2047 = 0)
__device__ __half g_wq[HDIM*DMODEL];      // W^T [n][k]
__device__ __half g_wk[HDIM*DMODEL];
__device__ __half g_wv[HDIM*DMODEL];
__device__ __half g_wo[DMODEL*HDIM];      // Wout^T [n][k]
__device__ __half g_wp[HDIM*DMODEL];      // Wpos^T [n][k]
__device__ unsigned g_mb[BB*TT*(TT/32)];  // bit-packed mask

// ------------------------- helpers -------------------------
__device__ __forceinline__ void mma16(float* c, const uint32_t* a, uint32_t b0, uint32_t b1) {
    asm volatile(
        "mma.sync.aligned.m16n8k16.row.col.f32.f16.f16.f32 "
        "{%0,%1,%2,%3}, {%4,%5,%6,%7}, {%8,%9}, {%0,%1,%2,%3};"
        : "+f"(c[0]), "+f"(c[1]), "+f"(c[2]), "+f"(c[3])
        : "r"(a[0]), "r"(a[1]), "r"(a[2]), "r"(a[3]), "r"(b0), "r"(b1));
}

__device__ __forceinline__ void cpa16(void* dst, const void* src) {
    uint32_t d = (uint32_t)__cvta_generic_to_shared(dst);
    asm volatile("cp.async.cg.shared.global [%0], [%1], 16;" :: "r"(d), "l"(src));
}
#define CP_COMMIT() asm volatile("cp.async.commit_group;")

// ============================================================================
// prep_all: one launch does bitpack + xs->fp16 + pe table + 5 weight transposes.
// ============================================================================
__global__ void prep_all(const float* __restrict__ xs, const int* __restrict__ mask,
                         const float* __restrict__ Wq, const float* __restrict__ Wk,
                         const float* __restrict__ Wv, const float* __restrict__ Wo,
                         const float* __restrict__ Wp)
{
    __shared__ float tile[32][33];
    const int blk = blockIdx.x, tid = threadIdx.x;

    if (blk < 1024) {
        int w = blk*256 + tid;
        const int* src = mask + (size_t)w * 32;
        unsigned bits = 0;
#pragma unroll
        for (int j = 0; j < 32; j += 4) {
            int4 v = *(const int4*)(src + j);
            bits |= (unsigned)(v.x != 0) << j;
            bits |= (unsigned)(v.y != 0) << (j+1);
            bits |= (unsigned)(v.z != 0) << (j+2);
            bits |= (unsigned)(v.w != 0) << (j+3);
        }
        g_mb[w] = bits;
    } else if (blk < 1536) {
        const int n4 = BB*TT*DMODEL/4;
        for (int i = (blk-1024)*256 + tid; i < n4; i += 512*256) {
            float4 v = ((const float4*)xs)[i];
            ((__half2*)g_xr)[i*2]   = __floats2half2_rn(v.x, v.y);
            ((__half2*)g_xr)[i*2+1] = __floats2half2_rn(v.z, v.w);
        }
    } else if (blk < 1792) {
        for (int e = (blk-1536)*256 + tid; e < 2048*256; e += 256*256) {
            int l = e >> 8, cp = e & 255;
            float freq = expf(-9.210340371976184f * (float)(2*cp) / (float)DMODEL);
            float s, c;
            sincosf((float)(l - (TT - 1)) * freq, &s, &c);
            __half2 v = (l < LPOS) ? __floats2half2_rn(s, c) : __floats2half2_rn(0.f, 0.f);
            ((__half2*)g_pe)[l*(DMODEL/2) + cp] = v;
        }
    } else {
        int wblk = blk - 1792;
        int which = wblk >> 8, rem = wblk & 255;
        const float* src = (which == 0) ? Wq : (which == 1) ? Wk : (which == 2) ? Wv
                         : (which == 3) ? Wo : Wp;
        __half* dst = (which == 0) ? g_wq : (which == 1) ? g_wk : (which == 2) ? g_wv
                    : (which == 3) ? g_wo : g_wp;
        int x0 = (rem & 15)*32, y0 = (rem >> 4)*32;
        int tx = tid & 31, ty = tid >> 5;
#pragma unroll
        for (int i = 0; i < 4; i++)
            tile[ty + 8*i][tx] = src[(size_t)(y0 + ty + 8*i)*512 + x0 + tx];
        __syncthreads();
#pragma unroll
        for (int i = 0; i < 4; i++)
            dst[(size_t)(x0 + ty + 8*i)*512 + y0 + tx] = __float2half_rn(tile[tx][ty + 8*i]);
    }
}

// ============================================================================
// Projections (fp16 mma, cp.async 2-stage): C = A @ Bt^T, 128x128 tile, K=512.
// Layout (bytes): A0@0, A1@18432, B0@36864, B1@55296  (total 73728)
// ============================================================================
#define PROJ_SMEM 73728

__device__ __forceinline__ void proj_prefetch(char* smc, int buf, int tid,
        const __half* Ag, const __half* Bg, int m0, int n0, int k0)
{
    char* aB = smc + buf*18432;
    char* bB = smc + 36864 + buf*18432;
    for (int e = tid; e < 1024; e += 256) {
        int r = e >> 3, ch = (e & 7) * 8;
        cpa16(aB + r*144 + ch*2, Ag + (size_t)(m0 + r)*512 + k0 + ch);
        cpa16(bB + r*144 + ch*2, Bg + (size_t)(n0 + r)*512 + k0 + ch);
    }
}

__device__ __forceinline__ void proj_core(char* smc, int tid,
        const __half* Ag, const __half* Bg, int m0, int n0, float acc[2][8][4])
{
    const int lane = tid & 31, warp = tid >> 5;
    const int g = lane >> 2, c = lane & 3;
    const int wm = warp >> 1, wn = warp & 1;

    proj_prefetch(smc, 0, tid, Ag, Bg, m0, n0, 0); CP_COMMIT();

    for (int it = 0; it < 8; it++) {
        int buf = it & 1;
        if (it < 7) { proj_prefetch(smc, buf^1, tid, Ag, Bg, m0, n0, (it+1)*64); CP_COMMIT(); }
        if (it < 7) asm volatile("cp.async.wait_group 1;");
        else        asm volatile("cp.async.wait_group 0;");
        __syncthreads();

        const uint32_t* uA = (const uint32_t*)(smc + buf*18432);
        const uint32_t* uB = (const uint32_t*)(smc + 36864 + buf*18432);
#pragma unroll
        for (int kk = 0; kk < 4; kk++) {
            uint32_t a[2][4], b[8][2];
#pragma unroll
            for (int mt = 0; mt < 2; mt++) {
                int r = wm*32 + mt*16 + g;
                a[mt][0] = uA[r*36 + kk*8 + c];
                a[mt][1] = uA[(r+8)*36 + kk*8 + c];
                a[mt][2] = uA[r*36 + kk*8 + c + 4];
                a[mt][3] = uA[(r+8)*36 + kk*8 + c + 4];
            }
#pragma unroll
            for (int nt = 0; nt < 8; nt++) {
                int nn = wn*64 + nt*8 + g;
                b[nt][0] = uB[nn*36 + kk*8 + c];
                b[nt][1] = uB[nn*36 + kk*8 + c + 4];
            }
#pragma unroll
            for (int mt = 0; mt < 2; mt++)
#pragma unroll
                for (int nt = 0; nt < 8; nt++) mma16(acc[mt][nt], a[mt], b[nt][0], b[nt][1]);
        }
        __syncthreads();
    }
}

// ============================================================================
// QKV + positional projection in ONE launch.  grid (64, 4, 4).
// ============================================================================
__global__ __launch_bounds__(256, 2)
void qkvpos_h(const float* __restrict__ ub, const float* __restrict__ vb)
{
    extern __shared__ char smc[];
    const int z = blockIdx.z;
    const int tid = threadIdx.x, lane = tid & 31, warp = tid >> 5;
    const int g = lane >> 2, c = lane & 3;
    const int wm = warp >> 1, wn = warp & 1;

    if (z == 3) {
        if (blockIdx.y != 0) return;
        const int m0 = (blockIdx.x >> 2) * 128;
        const int n0 = (blockIdx.x & 3) * 128;
        float acc[2][8][4] = {};
        proj_core(smc, tid, g_pe, g_wp, m0, n0, acc);
#pragma unroll
        for (int mt = 0; mt < 2; mt++) {
#pragma unroll
            for (int nt = 0; nt < 8; nt++) {
                int n = n0 + wn*64 + nt*8 + 2*c;
                int h = n >> 6, d = n & 63;
#pragma unroll
                for (int half = 0; half < 2; half++) {
                    int l = m0 + wm*32 + mt*16 + g + half*8;
                    if (l >= LPOS) continue;
                    *(__half2*)&g_p[((size_t)h*LPOS + l)*DHEAD + d] =
                        __floats2half2_rn(acc[mt][nt][half*2+0], acc[mt][nt][half*2+1]);
                }
            }
        }
        return;
    }

    const int which = z;
    const __half* W = (which == 0) ? g_wq : (which == 1) ? g_wk : g_wv;
    const int m0 = blockIdx.x * 128;
    const int n0 = blockIdx.y * 128;

    float acc[2][8][4] = {};
    proj_core(smc, tid, g_xr, W, m0, n0, acc);

#pragma unroll
    for (int mt = 0; mt < 2; mt++) {
#pragma unroll
        for (int nt = 0; nt < 8; nt++) {
            int n = n0 + wn*64 + nt*8 + 2*c;
            int h = n >> 6, d = n & 63;
#pragma unroll
            for (int half = 0; half < 2; half++) {
                int m = m0 + wm*32 + mt*16 + g + half*8;
                int bidx = m >> 10, t = m & (TT-1);
                float v0 = acc[mt][nt][half*2+0], v1 = acc[mt][nt][half*2+1];
                if (which == 0) {
                    size_t o = (((size_t)bidx*NH + h)*TT + t)*DHEAD + d;
                    *(__half2*)&g_qu[o] = __floats2half2_rn(v0 + ub[n], v1 + ub[n+1]);
                    *(__half2*)&g_qv[o] = __floats2half2_rn(v0 + vb[n], v1 + vb[n+1]);
                } else if (which == 1) {
                    size_t o = (((size_t)bidx*NH + h)*TT + t)*DHEAD + d;
                    *(__half2*)&g_k[o] = __floats2half2_rn(v0, v1);
                } else {
                    size_t ob = (((size_t)bidx*NH + h)*DHEAD + d)*TT + t;
                    g_vt[ob]      = __float2half_rn(v0);
                    g_vt[ob + TT] = __float2half_rn(v1);
                }
            }
        }
    }
}

__global__ __launch_bounds__(256, 2)
void out_h(float* __restrict__ out)
{
    extern __shared__ char smc[];
    const int m0 = blockIdx.x * 128;
    const int n0 = blockIdx.y * 128;
    const int tid = threadIdx.x, lane = tid & 31, warp = tid >> 5;
    const int g = lane >> 2, c = lane & 3;
    const int wm = warp >> 1, wn = warp & 1;

    float acc[2][8][4] = {};
    proj_core(smc, tid, g_z, g_wo, m0, n0, acc);

#pragma unroll
    for (int mt = 0; mt < 2; mt++) {
#pragma unroll
        for (int nt = 0; nt < 8; nt++) {
            int n = n0 + wn*64 + nt*8 + 2*c;
#pragma unroll
            for (int half = 0; half < 2; half++) {
                int m = m0 + wm*32 + mt*16 + g + half*8;
                *(float2*)&out[(size_t)m*DMODEL + n] =
                    make_float2(acc[mt][nt][half*2+0], acc[mt][nt][half*2+1]);
            }
        }
    }
}

// ============================================================================
// Fused attention (fp16 mma): 128-query block, 8 warps, circular P window,
// bit-packed mask, cp.async double-buffered K/V, S in registers,
// 10-tile BD band (FULL coverage [0,80) — high rows read x down to 0),
// single shared running max per warp.
// smem bytes: K 2x9216 @0, V 2x9216 @18432, P 320x144 @36864,
//             BD f32 128x84 @82944 -> total 125952
// ============================================================================
#define ATTN_SMEM 125952

__global__ __launch_bounds__(256, 1)
void attn_h()
{
    extern __shared__ char smc[];
    float* sBD = (float*)(smc + 82944);
    const uint32_t* uP = (const uint32_t*)(smc + 36864);

    const int tid = threadIdx.x, lane = tid & 31, warp = tid >> 5;
    const int g = lane >> 2, c = lane & 3;
    const int t0 = blockIdx.x * 128;
    const int bh = blockIdx.y;
    const int b = bh >> 3, h = bh & 7;
    const int rl = warp*16 + g;
    const int rh = rl + 8;
    const int tb = 14 - 2*warp;   // first BD n8-tile for this warp (10 tiles)

    const __half* qu  = g_qu + ((size_t)bh * TT + t0) * DHEAD;
    const __half* qv  = g_qv + ((size_t)bh * TT + t0) * DHEAD;
    const __half* kp  = g_k  + (size_t)bh * TT * DHEAD;
    const __half* vtp = g_vt + (size_t)bh * DHEAD * TT;
    const __half* pp  = g_p  + (size_t)h * LPOS * DHEAD;
    const int l00 = 896 - t0;

    // prefill: P rows 0..254, K/V tile 0
    for (int e = tid; e < 255*8; e += 256) {
        int r = e >> 3, ch = (e & 7) * 8;
        cpa16(smc + 36864 + r*144 + ch*2, pp + (size_t)(l00 + r)*DHEAD + ch);
    }
    for (int e = tid; e < 512; e += 256) {
        int r = e >> 3, ch = (e & 7) * 8;
        cpa16(smc + r*144 + ch*2, kp + (size_t)r*DHEAD + ch);
        cpa16(smc + 18432 + r*144 + ch*2, vtp + (size_t)r*TT + ch);
    }
    CP_COMMIT();

    // Q fragments (half2-packed, 4 k16 steps)
    const uint32_t* qu32 = (const uint32_t*)qu;
    const uint32_t* qv32 = (const uint32_t*)qv;
    uint32_t quf[4][4], qvf[4][4];
#pragma unroll
    for (int kk = 0; kk < 4; kk++) {
        quf[kk][0] = qu32[rl*32 + kk*8 + c];
        quf[kk][1] = qu32[rh*32 + kk*8 + c];
        quf[kk][2] = qu32[rl*32 + kk*8 + c + 4];
        quf[kk][3] = qu32[rh*32 + kk*8 + c + 4];
        qvf[kk][0] = qv32[rl*32 + kk*8 + c];
        qvf[kk][1] = qv32[rh*32 + kk*8 + c];
        qvf[kk][2] = qv32[rl*32 + kk*8 + c + 4];
        qvf[kk][3] = qv32[rh*32 + kk*8 + c + 4];
    }

    float o[8][4] = {};
    float rmax = -1e30f;          // shared across the warp's 16 rows
    float rsum_lo = 0.f, rsum_hi = 0.f;

    for (int it = 0; it < 16; it++) {
        const int buf = it & 1;
        const int s0 = it * 64;

        if (it < 15) {
            char* bK = smc + (buf^1)*9216;
            char* bV = smc + 18432 + (buf^1)*9216;
            for (int e = tid; e < 512; e += 256) {
                int r = e >> 3, ch = (e & 7) * 8;
                cpa16(bK + r*144 + ch*2, kp + (size_t)(s0 + 64 + r)*DHEAD + ch);
                cpa16(bV + r*144 + ch*2, vtp + (size_t)r*TT + s0 + 64 + ch);
            }
            if (it <= 13) {
                int start = (it*64 + 255) % PROWS;
                for (int e = tid; e < 512; e += 256) {
                    int r = e >> 3, ch = (e & 7) * 8;
                    int slot = start + r; if (slot >= PROWS) slot -= PROWS;
                    cpa16(smc + 36864 + slot*144 + ch*2,
                          pp + (size_t)(l00 + it*64 + 255 + r)*DHEAD + ch);
                }
            }
            CP_COMMIT();
        }
        if (it < 15) asm volatile("cp.async.wait_group 1;");
        else         asm volatile("cp.async.wait_group 0;");
        __syncthreads();

        const uint32_t* uK = (const uint32_t*)(smc + buf*9216);
        const uint32_t* uV = (const uint32_t*)(smc + 18432 + buf*9216);

        // ---- BD band GEMM: 10 n8-tiles per warp, 4 k16 steps ----
        {
            int rowb[10];
            const int p5 = (it % 5) * 64;
#pragma unroll
            for (int j = 0; j < 10; j++) {
                int rb = p5 + (tb + j)*8;
                if (rb >= PROWS) rb -= PROWS;
                rowb[j] = rb;
            }
            float bd[10][4] = {};
#pragma unroll
            for (int kk = 0; kk < 4; kk++) {
#pragma unroll
                for (int j = 0; j < 10; j++) {
                    int nn = rowb[j] + g;
                    mma16(bd[j], qvf[kk], uP[nn*36 + kk*8 + c], uP[nn*36 + kk*8 + c + 4]);
                }
            }
#pragma unroll
            for (int j = 0; j < 10; j++) {
                int cb = j*8 + 2*c;
                sBD[rl*BDST + cb]   = bd[j][0];
                sBD[rl*BDST + cb+1] = bd[j][1];
                sBD[rh*BDST + cb]   = bd[j][2];
                sBD[rh*BDST + cb+1] = bd[j][3];
            }
        }
        __syncwarp();

        // ---- AC GEMM ----
        float acc[8][4] = {};
#pragma unroll
        for (int kk = 0; kk < 4; kk++) {
#pragma unroll
            for (int nt = 0; nt < 8; nt++) {
                int nn = nt*8 + g;
                mma16(acc[nt], quf[kk], uK[nn*36 + kk*8 + c], uK[nn*36 + kk*8 + c + 4]);
            }
        }

        // ---- mask bits ----
        uint2 mwl = *(const uint2*)(g_mb + ((size_t)b*TT + t0 + rl)*32 + (s0 >> 5));
        uint2 mwh = *(const uint2*)(g_mb + ((size_t)b*TT + t0 + rh)*32 + (s0 >> 5));

        // ---- combine ac + shifted bd, mask, scale, online softmax (shared max) ----
        const int baseL = rl*BDST - g + 15;
        const int baseH = rh*BDST - g + 7;
        float mx = -1e30f;
#pragma unroll
        for (int nt = 0; nt < 8; nt++) {
            int cb = nt*8 + 2*c;
            unsigned wl = (cb & 32) ? mwl.y : mwl.x;
            unsigned wh = (cb & 32) ? mwh.y : mwh.x;
            int sh = cb & 31;
            float v;
            v = (acc[nt][0] + sBD[baseL + cb])   * 0.125f;
            acc[nt][0] = ((wl >> sh)     & 1) ? v : -1e30f;
            v = (acc[nt][1] + sBD[baseL + cb+1]) * 0.125f;
            acc[nt][1] = ((wl >> (sh+1)) & 1) ? v : -1e30f;
            v = (acc[nt][2] + sBD[baseH + cb])   * 0.125f;
            acc[nt][2] = ((wh >> sh)     & 1) ? v : -1e30f;
            v = (acc[nt][3] + sBD[baseH + cb+1]) * 0.125f;
            acc[nt][3] = ((wh >> (sh+1)) & 1) ? v : -1e30f;
            mx = fmaxf(mx, fmaxf(fmaxf(acc[nt][0], acc[nt][1]),
                                 fmaxf(acc[nt][2], acc[nt][3])));
        }
        mx = fmaxf(mx, __shfl_xor_sync(0xffffffffu, mx, 1));
        mx = fmaxf(mx, __shfl_xor_sync(0xffffffffu, mx, 2));

        float nm = fmaxf(rmax, mx);
        float corr = __expf(rmax - nm);
        rmax = nm;

        // ---- exp + pack S fragments in registers ----
        uint32_t sfl[8], sfh[8];
        float ts_lo = 0.f, ts_hi = 0.f;
#pragma unroll
        for (int nt = 0; nt < 8; nt++) {
            float p0 = __expf(acc[nt][0] - nm);
            float p1 = __expf(acc[nt][1] - nm);
            float p2 = __expf(acc[nt][2] - nm);
            float p3 = __expf(acc[nt][3] - nm);
            ts_lo += p0 + p1; ts_hi += p2 + p3;
            __half2 hl = __floats2half2_rn(p0, p1);
            __half2 hh = __floats2half2_rn(p2, p3);
            sfl[nt] = *(uint32_t*)&hl;
            sfh[nt] = *(uint32_t*)&hh;
            o[nt][0] *= corr; o[nt][1] *= corr;
            o[nt][2] *= corr; o[nt][3] *= corr;
        }
        ts_lo += __shfl_xor_sync(0xffffffffu, ts_lo, 1);
        ts_lo += __shfl_xor_sync(0xffffffffu, ts_lo, 2);
        ts_hi += __shfl_xor_sync(0xffffffffu, ts_hi, 1);
        ts_hi += __shfl_xor_sync(0xffffffffu, ts_hi, 2);
        rsum_lo = rsum_lo * corr + ts_lo;
        rsum_hi = rsum_hi * corr + ts_hi;

        // ---- PV GEMM: O += exp(S) @ V ----
#pragma unroll
        for (int kk = 0; kk < 4; kk++) {
            uint32_t a[4] = { sfl[2*kk], sfh[2*kk], sfl[2*kk+1], sfh[2*kk+1] };
#pragma unroll
            for (int nt = 0; nt < 8; nt++) {
                int nn = nt*8 + g;
                mma16(o[nt], a, uV[nn*36 + kk*8 + c], uV[nn*36 + kk*8 + c + 4]);
            }
        }
        __syncthreads();
    }

    // ---- normalize + write z (B,T,H,dh) fp16 ----
    float inv_lo = 1.f / rsum_lo, inv_hi = 1.f / rsum_hi;
#pragma unroll
    for (int nt = 0; nt < 8; nt++) {
        int d = nt*8 + 2*c;
        *(__half2*)&g_z[(((size_t)b*TT + (t0+rl))*NH + h)*DHEAD + d] =
            __floats2half2_rn(o[nt][0]*inv_lo, o[nt][1]*inv_lo);
        *(__half2*)&g_z[(((size_t)b*TT + (t0+rh))*NH + h)*DHEAD + d] =
            __floats2half2_rn(o[nt][2]*inv_hi, o[nt][3]*inv_hi);
    }
}

// ============================================================================
extern "C" void kernel_launch(void* const* d_in, const int* in_sizes, int n_in,
                              void* d_out, int out_size)
{
    const float* xs   = (const float*)d_in[0];
    const int*   mask = (const int*)  d_in[1];
    const float* Wq   = (const float*)d_in[2];
    const float* Wk   = (const float*)d_in[3];
    const float* Wv   = (const float*)d_in[4];
    const float* Wpos = (const float*)d_in[5];
    const float* Wout = (const float*)d_in[6];
    const float* ub   = (const float*)d_in[7];
    const float* vb   = (const float*)d_in[8];
    float* out = (float*)d_out;

    cudaFuncSetAttribute(attn_h,   cudaFuncAttributeMaxDynamicSharedMemorySize, ATTN_SMEM);
    cudaFuncSetAttribute(qkvpos_h, cudaFuncAttributeMaxDynamicSharedMemorySize, PROJ_SMEM);
    cudaFuncSetAttribute(out_h,    cudaFuncAttributeMaxDynamicSharedMemorySize, PROJ_SMEM);

    prep_all<<<3072, 256>>>(xs, mask, Wq, Wk, Wv, Wout, Wpos);
    qkvpos_h<<<dim3(64, 4, 4), 256, PROJ_SMEM>>>(ub, vb);
    attn_h<<<dim3(8, 64), 256, ATTN_SMEM>>>();
    out_h<<<dim3(64, 4), 256, PROJ_SMEM>>>(out);
}

// round 16
// speedup vs baseline: 7.8142x; 1.0314x over previous
#include <cuda_runtime.h>
#include <cuda_fp16.h>
#include <math.h>
#include <stdint.h>

#define BB     8
#define TT     1024
#define DMODEL 512
#define NH     8
#define DHEAD  64
#define HDIM   512
#define LPOS   2047   // 2T-1
#define BDST   84     // BD f32 row stride
#define PROWS  320    // circular P window rows (5 x 64)
#define SCL    0.1803368801111204f   // 0.125 * log2(e)

// ------------------------- scratch (static device memory, fp16) -------------------------
__device__ __half g_qu[BB*NH*TT*DHEAD];   // q + u_bias, (B,H,T,dh)
__device__ __half g_qv[BB*NH*TT*DHEAD];   // q + v_bias
__device__ __half g_k [BB*NH*TT*DHEAD];
__device__ __half g_vt[BB*NH*DHEAD*TT];   // V transposed (B,H,dh,T)
__device__ __half g_p [NH*LPOS*DHEAD];    // (H, L, dh)
__device__ __half g_z [BB*TT*NH*DHEAD];   // (B, T, H, dh)
__device__ __half g_xr[BB*TT*DMODEL];     // xs
__device__ __half g_pe[2048*DMODEL];      // sinusoidal table (row 2047 = 0)
__device__ __half g_wq[HDIM*DMODEL];      // W^T [n][k]
__device__ __half g_wk[HDIM*DMODEL];
__device__ __half g_wv[HDIM*DMODEL];
__device__ __half g_wo[DMODEL*HDIM];      // Wout^T [n][k]
__device__ __half g_wp[HDIM*DMODEL];      // Wpos^T [n][k]
__device__ unsigned g_mb[BB*TT*(TT/32)];  // bit-packed mask

// ------------------------- helpers -------------------------
__device__ __forceinline__ void mma16(float* c, const uint32_t* a, uint32_t b0, uint32_t b1) {
    asm volatile(
        "mma.sync.aligned.m16n8k16.row.col.f32.f16.f16.f32 "
        "{%0,%1,%2,%3}, {%4,%5,%6,%7}, {%8,%9}, {%0,%1,%2,%3};"
        : "+f"(c[0]), "+f"(c[1]), "+f"(c[2]), "+f"(c[3])
        : "r"(a[0]), "r"(a[1]), "r"(a[2]), "r"(a[3]), "r"(b0), "r"(b1));
}

__device__ __forceinline__ void ldsm4(uint32_t& r0, uint32_t& r1, uint32_t& r2, uint32_t& r3,
                                      uint32_t addr) {
    asm volatile("ldmatrix.sync.aligned.m8n8.x4.shared.b16 {%0,%1,%2,%3}, [%4];"
        : "=r"(r0), "=r"(r1), "=r"(r2), "=r"(r3) : "r"(addr));
}

__device__ __forceinline__ uint32_t smem_u32(const void* p) {
    return (uint32_t)__cvta_generic_to_shared(p);
}

__device__ __forceinline__ void cpa16(void* dst, const void* src) {
    uint32_t d = (uint32_t)__cvta_generic_to_shared(dst);
    asm volatile("cp.async.cg.shared.global [%0], [%1], 16;" :: "r"(d), "l"(src));
}
#define CP_COMMIT() asm volatile("cp.async.commit_group;")

// ============================================================================
// prep_all: bitpack + xs->fp16 + pe table + 5 weight transposes, one launch.
// ============================================================================
__global__ void prep_all(const float* __restrict__ xs, const int* __restrict__ mask,
                         const float* __restrict__ Wq, const float* __restrict__ Wk,
                         const float* __restrict__ Wv, const float* __restrict__ Wo,
                         const float* __restrict__ Wp)
{
    __shared__ float tile[32][33];
    const int blk = blockIdx.x, tid = threadIdx.x;

    if (blk < 1024) {
        int w = blk*256 + tid;
        const int* src = mask + (size_t)w * 32;
        unsigned bits = 0;
#pragma unroll
        for (int j = 0; j < 32; j += 4) {
            int4 v = *(const int4*)(src + j);
            bits |= (unsigned)(v.x != 0) << j;
            bits |= (unsigned)(v.y != 0) << (j+1);
            bits |= (unsigned)(v.z != 0) << (j+2);
            bits |= (unsigned)(v.w != 0) << (j+3);
        }
        g_mb[w] = bits;
    } else if (blk < 1536) {
        const int n4 = BB*TT*DMODEL/4;
        for (int i = (blk-1024)*256 + tid; i < n4; i += 512*256) {
            float4 v = ((const float4*)xs)[i];
            ((__half2*)g_xr)[i*2]   = __floats2half2_rn(v.x, v.y);
            ((__half2*)g_xr)[i*2+1] = __floats2half2_rn(v.z, v.w);
        }
    } else if (blk < 1792) {
        for (int e = (blk-1536)*256 + tid; e < 2048*256; e += 256*256) {
            int l = e >> 8, cp = e & 255;
            float freq = expf(-9.210340371976184f * (float)(2*cp) / (float)DMODEL);
            float s, c;
            sincosf((float)(l - (TT - 1)) * freq, &s, &c);
            __half2 v = (l < LPOS) ? __floats2half2_rn(s, c) : __floats2half2_rn(0.f, 0.f);
            ((__half2*)g_pe)[l*(DMODEL/2) + cp] = v;
        }
    } else {
        int wblk = blk - 1792;
        int which = wblk >> 8, rem = wblk & 255;
        const float* src = (which == 0) ? Wq : (which == 1) ? Wk : (which == 2) ? Wv
                         : (which == 3) ? Wo : Wp;
        __half* dst = (which == 0) ? g_wq : (which == 1) ? g_wk : (which == 2) ? g_wv
                    : (which == 3) ? g_wo : g_wp;
        int x0 = (rem & 15)*32, y0 = (rem >> 4)*32;
        int tx = tid & 31, ty = tid >> 5;
#pragma unroll
        for (int i = 0; i < 4; i++)
            tile[ty + 8*i][tx] = src[(size_t)(y0 + ty + 8*i)*512 + x0 + tx];
        __syncthreads();
#pragma unroll
        for (int i = 0; i < 4; i++)
            dst[(size_t)(x0 + ty + 8*i)*512 + y0 + tx] = __float2half_rn(tile[tx][ty + 8*i]);
    }
}

// ============================================================================
// Projections (fp16 mma + ldmatrix, cp.async 2-stage): C = A @ Bt^T, 128x128.
// Layout (bytes): A0@0, A1@18432, B0@36864, B1@55296  (total 73728)
// ============================================================================
#define PROJ_SMEM 73728

__device__ __forceinline__ void proj_prefetch(char* smc, int buf, int tid,
        const __half* Ag, const __half* Bg, int m0, int n0, int k0)
{
    char* aB = smc + buf*18432;
    char* bB = smc + 36864 + buf*18432;
    for (int e = tid; e < 1024; e += 256) {
        int r = e >> 3, ch = (e & 7) * 8;
        cpa16(aB + r*144 + ch*2, Ag + (size_t)(m0 + r)*512 + k0 + ch);
        cpa16(bB + r*144 + ch*2, Bg + (size_t)(n0 + r)*512 + k0 + ch);
    }
}

__device__ __forceinline__ void proj_core(char* smc, int tid,
        const __half* Ag, const __half* Bg, int m0, int n0, float acc[2][8][4])
{
    const int lane = tid & 31, warp = tid >> 5;
    const int wm = warp >> 1, wn = warp & 1;
    const int r8 = lane & 7;
    // A-frag: m0=rows/k-lo, m1=rows+8/k-lo, m2=rows/k-hi, m3=rows+8/k-hi
    const uint32_t aoff = (uint32_t)((r8 + ((lane & 8) ? 8 : 0))*144 + ((lane & 16) ? 16 : 0))
                        + (uint32_t)(wm*32*144);
    // B-frag: m0=tile/k-lo, m1=tile/k-hi, m2=tile+1/k-lo, m3=tile+1/k-hi
    const uint32_t boff = (uint32_t)((r8 + ((lane & 16) ? 8 : 0))*144 + ((lane & 8) ? 16 : 0))
                        + (uint32_t)(wn*64*144);
    const uint32_t sa = smem_u32(smc), sb = smem_u32(smc + 36864);

    proj_prefetch(smc, 0, tid, Ag, Bg, m0, n0, 0); CP_COMMIT();

    for (int it = 0; it < 8; it++) {
        int buf = it & 1;
        if (it < 7) { proj_prefetch(smc, buf^1, tid, Ag, Bg, m0, n0, (it+1)*64); CP_COMMIT(); }
        if (it < 7) asm volatile("cp.async.wait_group 1;");
        else        asm volatile("cp.async.wait_group 0;");
        __syncthreads();

        const uint32_t aB = sa + buf*18432 + aoff;
        const uint32_t bB = sb + buf*18432 + boff;
#pragma unroll
        for (int kk = 0; kk < 4; kk++) {
            uint32_t a[2][4];
#pragma unroll
            for (int mt = 0; mt < 2; mt++)
                ldsm4(a[mt][0], a[mt][1], a[mt][2], a[mt][3], aB + mt*16*144 + kk*32);
#pragma unroll
            for (int ntp = 0; ntp < 4; ntp++) {
                uint32_t b0, b1, b2, b3;
                ldsm4(b0, b1, b2, b3, bB + ntp*16*144 + kk*32);
                mma16(acc[0][2*ntp],   a[0], b0, b1);
                mma16(acc[0][2*ntp+1], a[0], b2, b3);
                mma16(acc[1][2*ntp],   a[1], b0, b1);
                mma16(acc[1][2*ntp+1], a[1], b2, b3);
            }
        }
        __syncthreads();
    }
}

// ============================================================================
// QKV + positional projection in ONE launch.  grid (64, 4, 4).
// ============================================================================
__global__ __launch_bounds__(256, 2)
void qkvpos_h(const float* __restrict__ ub, const float* __restrict__ vb)
{
    extern __shared__ char smc[];
    const int z = blockIdx.z;
    const int tid = threadIdx.x, lane = tid & 31, warp = tid >> 5;
    const int g = lane >> 2, c = lane & 3;
    const int wm = warp >> 1, wn = warp & 1;

    if (z == 3) {
        if (blockIdx.y != 0) return;
        const int m0 = (blockIdx.x >> 2) * 128;
        const int n0 = (blockIdx.x & 3) * 128;
        float acc[2][8][4] = {};
        proj_core(smc, tid, g_pe, g_wp, m0, n0, acc);
#pragma unroll
        for (int mt = 0; mt < 2; mt++) {
#pragma unroll
            for (int nt = 0; nt < 8; nt++) {
                int n = n0 + wn*64 + nt*8 + 2*c;
                int h = n >> 6, d = n & 63;
#pragma unroll
                for (int half = 0; half < 2; half++) {
                    int l = m0 + wm*32 + mt*16 + g + half*8;
                    if (l >= LPOS) continue;
                    *(__half2*)&g_p[((size_t)h*LPOS + l)*DHEAD + d] =
                        __floats2half2_rn(acc[mt][nt][half*2+0], acc[mt][nt][half*2+1]);
                }
            }
        }
        return;
    }

    const int which = z;
    const __half* W = (which == 0) ? g_wq : (which == 1) ? g_wk : g_wv;
    const int m0 = blockIdx.x * 128;
    const int n0 = blockIdx.y * 128;

    float acc[2][8][4] = {};
    proj_core(smc, tid, g_xr, W, m0, n0, acc);

#pragma unroll
    for (int mt = 0; mt < 2; mt++) {
#pragma unroll
        for (int nt = 0; nt < 8; nt++) {
            int n = n0 + wn*64 + nt*8 + 2*c;
            int h = n >> 6, d = n & 63;
#pragma unroll
            for (int half = 0; half < 2; half++) {
                int m = m0 + wm*32 + mt*16 + g + half*8;
                int bidx = m >> 10, t = m & (TT-1);
                float v0 = acc[mt][nt][half*2+0], v1 = acc[mt][nt][half*2+1];
                if (which == 0) {
                    size_t o = (((size_t)bidx*NH + h)*TT + t)*DHEAD + d;
                    *(__half2*)&g_qu[o] = __floats2half2_rn(v0 + ub[n], v1 + ub[n+1]);
                    *(__half2*)&g_qv[o] = __floats2half2_rn(v0 + vb[n], v1 + vb[n+1]);
                } else if (which == 1) {
                    size_t o = (((size_t)bidx*NH + h)*TT + t)*DHEAD + d;
                    *(__half2*)&g_k[o] = __floats2half2_rn(v0, v1);
                } else {
                    size_t ob = (((size_t)bidx*NH + h)*DHEAD + d)*TT + t;
                    g_vt[ob]      = __float2half_rn(v0);
                    g_vt[ob + TT] = __float2half_rn(v1);
                }
            }
        }
    }
}

__global__ __launch_bounds__(256, 2)
void out_h(float* __restrict__ out)
{
    extern __shared__ char smc[];
    const int m0 = blockIdx.x * 128;
    const int n0 = blockIdx.y * 128;
    const int tid = threadIdx.x, lane = tid & 31, warp = tid >> 5;
    const int g = lane >> 2, c = lane & 3;
    const int wm = warp >> 1, wn = warp & 1;

    float acc[2][8][4] = {};
    proj_core(smc, tid, g_z, g_wo, m0, n0, acc);

#pragma unroll
    for (int mt = 0; mt < 2; mt++) {
#pragma unroll
        for (int nt = 0; nt < 8; nt++) {
            int n = n0 + wn*64 + nt*8 + 2*c;
#pragma unroll
            for (int half = 0; half < 2; half++) {
                int m = m0 + wm*32 + mt*16 + g + half*8;
                *(float2*)&out[(size_t)m*DMODEL + n] =
                    make_float2(acc[mt][nt][half*2+0], acc[mt][nt][half*2+1]);
            }
        }
    }
}

// ============================================================================
// Fused attention (fp16 mma + ldmatrix): 128-query block, 8 warps, circular
// P window, bit-packed mask, cp.async double-buffered K/V, S in registers,
// 10-tile BD band, shared running max, exp2-domain softmax.
// smem bytes: K 2x9216 @0, V 2x9216 @18432, P 320x144 @36864,
//             BD f32 128x84 @82944 -> total 125952
// ============================================================================
#define ATTN_SMEM 125952

__global__ __launch_bounds__(256, 1)
void attn_h()
{
    extern __shared__ char smc[];
    float* sBD = (float*)(smc + 82944);

    const int tid = threadIdx.x, lane = tid & 31, warp = tid >> 5;
    const int g = lane >> 2, c = lane & 3;
    const int t0 = blockIdx.x * 128;
    const int bh = blockIdx.y;
    const int b = bh >> 3, h = bh & 7;
    const int rl = warp*16 + g;
    const int rh = rl + 8;
    const int tb = 14 - 2*warp;   // first BD n8-tile for this warp (10 tiles)
    const int r8 = lane & 7;
    // B-frag ldmatrix lane offset for contiguous tiles (pair form)
    const uint32_t boff = (uint32_t)((r8 + ((lane & 16) ? 8 : 0))*144 + ((lane & 8) ? 16 : 0));
    // BD circular tiles: tile select via jsel ONLY; row add is r8 alone.
    const uint32_t pkoff = (lane & 8) ? 16u : 0u;
    const uint32_t sk = smem_u32(smc);
    const uint32_t sv = smem_u32(smc + 18432);
    const uint32_t sp = smem_u32(smc + 36864);

    const __half* qu  = g_qu + ((size_t)bh * TT + t0) * DHEAD;
    const __half* qv  = g_qv + ((size_t)bh * TT + t0) * DHEAD;
    const __half* kp  = g_k  + (size_t)bh * TT * DHEAD;
    const __half* vtp = g_vt + (size_t)bh * DHEAD * TT;
    const __half* pp  = g_p  + (size_t)h * LPOS * DHEAD;
    const int l00 = 896 - t0;

    // prefill: P rows 0..254, K/V tile 0
    for (int e = tid; e < 255*8; e += 256) {
        int r = e >> 3, ch = (e & 7) * 8;
        cpa16(smc + 36864 + r*144 + ch*2, pp + (size_t)(l00 + r)*DHEAD + ch);
    }
    for (int e = tid; e < 512; e += 256) {
        int r = e >> 3, ch = (e & 7) * 8;
        cpa16(smc + r*144 + ch*2, kp + (size_t)r*DHEAD + ch);
        cpa16(smc + 18432 + r*144 + ch*2, vtp + (size_t)r*TT + ch);
    }
    CP_COMMIT();

    // Q fragments (half2-packed, 4 k16 steps)
    const uint32_t* qu32 = (const uint32_t*)qu;
    const uint32_t* qv32 = (const uint32_t*)qv;
    uint32_t quf[4][4], qvf[4][4];
#pragma unroll
    for (int kk = 0; kk < 4; kk++) {
        quf[kk][0] = qu32[rl*32 + kk*8 + c];
        quf[kk][1] = qu32[rh*32 + kk*8 + c];
        quf[kk][2] = qu32[rl*32 + kk*8 + c + 4];
        quf[kk][3] = qu32[rh*32 + kk*8 + c + 4];
        qvf[kk][0] = qv32[rl*32 + kk*8 + c];
        qvf[kk][1] = qv32[rh*32 + kk*8 + c];
        qvf[kk][2] = qv32[rl*32 + kk*8 + c + 4];
        qvf[kk][3] = qv32[rh*32 + kk*8 + c + 4];
    }

    float o[8][4] = {};
    float rmax = -1e30f;
    float rsum_lo = 0.f, rsum_hi = 0.f;

    for (int it = 0; it < 16; it++) {
        const int buf = it & 1;
        const int s0 = it * 64;

        if (it < 15) {
            char* bK = smc + (buf^1)*9216;
            char* bV = smc + 18432 + (buf^1)*9216;
            for (int e = tid; e < 512; e += 256) {
                int r = e >> 3, ch = (e & 7) * 8;
                cpa16(bK + r*144 + ch*2, kp + (size_t)(s0 + 64 + r)*DHEAD + ch);
                cpa16(bV + r*144 + ch*2, vtp + (size_t)r*TT + s0 + 64 + ch);
            }
            if (it <= 13) {
                int start = (it*64 + 255) % PROWS;
                for (int e = tid; e < 512; e += 256) {
                    int r = e >> 3, ch = (e & 7) * 8;
                    int slot = start + r; if (slot >= PROWS) slot -= PROWS;
                    cpa16(smc + 36864 + slot*144 + ch*2,
                          pp + (size_t)(l00 + it*64 + 255 + r)*DHEAD + ch);
                }
            }
            CP_COMMIT();
        }
        if (it < 15) asm volatile("cp.async.wait_group 1;");
        else         asm volatile("cp.async.wait_group 0;");
        __syncthreads();

        // ---- BD band GEMM: 10 n8-tiles = 5 ldmatrix quads, 4 k16 steps ----
        {
            const int p5 = (it % 5) * 64;
            uint32_t prow[5];
#pragma unroll
            for (int ntp = 0; ntp < 5; ntp++) {
                int jsel = 2*ntp + ((lane & 16) ? 1 : 0);
                int rb = p5 + (tb + jsel)*8;
                if (rb >= PROWS) rb -= PROWS;
                prow[ntp] = sp + (uint32_t)(rb + r8)*144 + pkoff;   // row add = r8 ONLY
            }
            float bd[10][4] = {};
#pragma unroll
            for (int kk = 0; kk < 4; kk++) {
#pragma unroll
                for (int ntp = 0; ntp < 5; ntp++) {
                    uint32_t b0, b1, b2, b3;
                    ldsm4(b0, b1, b2, b3, prow[ntp] + kk*32);
                    mma16(bd[2*ntp],   qvf[kk], b0, b1);
                    mma16(bd[2*ntp+1], qvf[kk], b2, b3);
                }
            }
#pragma unroll
            for (int j = 0; j < 10; j++) {
                int cb = j*8 + 2*c;
                sBD[rl*BDST + cb]   = bd[j][0];
                sBD[rl*BDST + cb+1] = bd[j][1];
                sBD[rh*BDST + cb]   = bd[j][2];
                sBD[rh*BDST + cb+1] = bd[j][3];
            }
        }
        __syncwarp();

        // ---- AC GEMM via ldmatrix ----
        float acc[8][4] = {};
        const uint32_t kB = sk + buf*9216 + boff;
#pragma unroll
        for (int kk = 0; kk < 4; kk++) {
#pragma unroll
            for (int ntp = 0; ntp < 4; ntp++) {
                uint32_t b0, b1, b2, b3;
                ldsm4(b0, b1, b2, b3, kB + ntp*2304 + kk*32);
                mma16(acc[2*ntp],   quf[kk], b0, b1);
                mma16(acc[2*ntp+1], quf[kk], b2, b3);
            }
        }

        // ---- mask bits ----
        uint2 mwl = *(const uint2*)(g_mb + ((size_t)b*TT + t0 + rl)*32 + (s0 >> 5));
        uint2 mwh = *(const uint2*)(g_mb + ((size_t)b*TT + t0 + rh)*32 + (s0 >> 5));

        // ---- combine ac + shifted bd, mask, scale (exp2 domain), softmax ----
        const int baseL = rl*BDST - g + 15;
        const int baseH = rh*BDST - g + 7;
        float mx = -1e30f;
#pragma unroll
        for (int nt = 0; nt < 8; nt++) {
            int cb = nt*8 + 2*c;
            unsigned wl = (cb & 32) ? mwl.y : mwl.x;
            unsigned wh = (cb & 32) ? mwh.y : mwh.x;
            int sh = cb & 31;
            float v;
            v = (acc[nt][0] + sBD[baseL + cb])   * SCL;
            acc[nt][0] = ((wl >> sh)     & 1) ? v : -1e30f;
            v = (acc[nt][1] + sBD[baseL + cb+1]) * SCL;
            acc[nt][1] = ((wl >> (sh+1)) & 1) ? v : -1e30f;
            v = (acc[nt][2] + sBD[baseH + cb])   * SCL;
            acc[nt][2] = ((wh >> sh)     & 1) ? v : -1e30f;
            v = (acc[nt][3] + sBD[baseH + cb+1]) * SCL;
            acc[nt][3] = ((wh >> (sh+1)) & 1) ? v : -1e30f;
            mx = fmaxf(mx, fmaxf(fmaxf(acc[nt][0], acc[nt][1]),
                                 fmaxf(acc[nt][2], acc[nt][3])));
        }
        mx = fmaxf(mx, __shfl_xor_sync(0xffffffffu, mx, 1));
        mx = fmaxf(mx, __shfl_xor_sync(0xffffffffu, mx, 2));

        float nm = fmaxf(rmax, mx);
        float corr = exp2f(rmax - nm);
        rmax = nm;

        // ---- exp2 + pack S fragments in registers ----
        uint32_t sfl[8], sfh[8];
        float ts_lo = 0.f, ts_hi = 0.f;
#pragma unroll
        for (int nt = 0; nt < 8; nt++) {
            float p0 = exp2f(acc[nt][0] - nm);
            float p1 = exp2f(acc[nt][1] - nm);
            float p2 = exp2f(acc[nt][2] - nm);
            float p3 = exp2f(acc[nt][3] - nm);
            ts_lo += p0 + p1; ts_hi += p2 + p3;
            __half2 hl = __floats2half2_rn(p0, p1);
            __half2 hh = __floats2half2_rn(p2, p3);
            sfl[nt] = *(uint32_t*)&hl;
            sfh[nt] = *(uint32_t*)&hh;
            o[nt][0] *= corr; o[nt][1] *= corr;
            o[nt][2] *= corr; o[nt][3] *= corr;
        }
        ts_lo += __shfl_xor_sync(0xffffffffu, ts_lo, 1);
        ts_lo += __shfl_xor_sync(0xffffffffu, ts_lo, 2);
        ts_hi += __shfl_xor_sync(0xffffffffu, ts_hi, 1);
        ts_hi += __shfl_xor_sync(0xffffffffu, ts_hi, 2);
        rsum_lo = rsum_lo * corr + ts_lo;
        rsum_hi = rsum_hi * corr + ts_hi;

        // ---- PV GEMM via ldmatrix: O += exp(S) @ V ----
        const uint32_t vB = sv + buf*9216 + boff;
#pragma unroll
        for (int kk = 0; kk < 4; kk++) {
            uint32_t a[4] = { sfl[2*kk], sfh[2*kk], sfl[2*kk+1], sfh[2*kk+1] };
#pragma unroll
            for (int ntp = 0; ntp < 4; ntp++) {
                uint32_t b0, b1, b2, b3;
                ldsm4(b0, b1, b2, b3, vB + ntp*2304 + kk*32);
                mma16(o[2*ntp],   a, b0, b1);
                mma16(o[2*ntp+1], a, b2, b3);
            }
        }
        __syncthreads();
    }

    // ---- normalize + write z (B,T,H,dh) fp16 ----
    float inv_lo = 1.f / rsum_lo, inv_hi = 1.f / rsum_hi;
#pragma unroll
    for (int nt = 0; nt < 8; nt++) {
        int d = nt*8 + 2*c;
        *(__half2*)&g_z[(((size_t)b*TT + (t0+rl))*NH + h)*DHEAD + d] =
            __floats2half2_rn(o[nt][0]*inv_lo, o[nt][1]*inv_lo);
        *(__half2*)&g_z[(((size_t)b*TT + (t0+rh))*NH + h)*DHEAD + d] =
            __floats2half2_rn(o[nt][2]*inv_hi, o[nt][3]*inv_hi);
    }
}

// ============================================================================
extern "C" void kernel_launch(void* const* d_in, const int* in_sizes, int n_in,
                              void* d_out, int out_size)
{
    const float* xs   = (const float*)d_in[0];
    const int*   mask = (const int*)  d_in[1];
    const float* Wq   = (const float*)d_in[2];
    const float* Wk   = (const float*)d_in[3];
    const float* Wv   = (const float*)d_in[4];
    const float* Wpos = (const float*)d_in[5];
    const float* Wout = (const float*)d_in[6];
    const float* ub   = (const float*)d_in[7];
    const float* vb   = (const float*)d_in[8];
    float* out = (float*)d_out;

    cudaFuncSetAttribute(attn_h,   cudaFuncAttributeMaxDynamicSharedMemorySize, ATTN_SMEM);
    cudaFuncSetAttribute(qkvpos_h, cudaFuncAttributeMaxDynamicSharedMemorySize, PROJ_SMEM);
    cudaFuncSetAttribute(out_h,    cudaFuncAttributeMaxDynamicSharedMemorySize, PROJ_SMEM);

    prep_all<<<3072, 256>>>(xs, mask, Wq, Wk, Wv, Wout, Wpos);
    qkvpos_h<<<dim3(64, 4, 4), 256, PROJ_SMEM>>>(ub, vb);
    attn_h<<<dim3(8, 64), 256, ATTN_SMEM>>>();
    out_h<<<dim3(64, 4), 256, PROJ_SMEM>>>(out);
}

// round 17
// speedup vs baseline: 8.0582x; 1.0312x over previous
#include <cuda_runtime.h>
#include <cuda_fp16.h>
#include <math.h>
#include <stdint.h>

#define BB     8
#define TT     1024
#define DMODEL 512
#define NH     8
#define DHEAD  64
#define HDIM   512
#define LPOS   2047   // 2T-1
#define BDST   84     // BD f32 row stride (banks: 20g write / 19g read, both distinct)
#define SCL    0.1803368801111204f   // 0.125 * log2(e)

// ------------------------- scratch (static device memory, fp16) -------------------------
__device__ __half g_qu[BB*NH*TT*DHEAD];   // q + u_bias, (B,H,T,dh)
__device__ __half g_qv[BB*NH*TT*DHEAD];   // q + v_bias
__device__ __half g_k [BB*NH*TT*DHEAD];
__device__ __half g_vt[BB*NH*DHEAD*TT];   // V transposed (B,H,dh,T)
__device__ __half g_p [NH*LPOS*DHEAD];    // (H, L, dh)
__device__ __half g_z [BB*TT*NH*DHEAD];   // (B, T, H, dh)
__device__ __half g_xr[BB*TT*DMODEL];     // xs
__device__ __half g_pe[2048*DMODEL];      // sinusoidal table (row 2047 = 0)
__device__ __half g_wq[HDIM*DMODEL];      // W^T [n][k]
__device__ __half g_wk[HDIM*DMODEL];
__device__ __half g_wv[HDIM*DMODEL];
__device__ __half g_wo[DMODEL*HDIM];      // Wout^T [n][k]
__device__ __half g_wp[HDIM*DMODEL];      // Wpos^T [n][k]
__device__ unsigned g_mb[BB*TT*(TT/32)];  // bit-packed mask

// ------------------------- helpers -------------------------
__device__ __forceinline__ void mma16(float* c, const uint32_t* a, uint32_t b0, uint32_t b1) {
    asm volatile(
        "mma.sync.aligned.m16n8k16.row.col.f32.f16.f16.f32 "
        "{%0,%1,%2,%3}, {%4,%5,%6,%7}, {%8,%9}, {%0,%1,%2,%3};"
        : "+f"(c[0]), "+f"(c[1]), "+f"(c[2]), "+f"(c[3])
        : "r"(a[0]), "r"(a[1]), "r"(a[2]), "r"(a[3]), "r"(b0), "r"(b1));
}

__device__ __forceinline__ void ldsm4(uint32_t& r0, uint32_t& r1, uint32_t& r2, uint32_t& r3,
                                      uint32_t addr) {
    asm volatile("ldmatrix.sync.aligned.m8n8.x4.shared.b16 {%0,%1,%2,%3}, [%4];"
        : "=r"(r0), "=r"(r1), "=r"(r2), "=r"(r3) : "r"(addr));
}

__device__ __forceinline__ uint32_t smem_u32(const void* p) {
    return (uint32_t)__cvta_generic_to_shared(p);
}

__device__ __forceinline__ void cpa16(void* dst, const void* src) {
    uint32_t d = (uint32_t)__cvta_generic_to_shared(dst);
    asm volatile("cp.async.cg.shared.global [%0], [%1], 16;" :: "r"(d), "l"(src));
}
#define CP_COMMIT() asm volatile("cp.async.commit_group;")

// ============================================================================
// prep_all: bitpack + xs->fp16 + pe table + 5 weight transposes, one launch.
// ============================================================================
__global__ void prep_all(const float* __restrict__ xs, const int* __restrict__ mask,
                         const float* __restrict__ Wq, const float* __restrict__ Wk,
                         const float* __restrict__ Wv, const float* __restrict__ Wo,
                         const float* __restrict__ Wp)
{
    __shared__ float tile[32][33];
    const int blk = blockIdx.x, tid = threadIdx.x;

    if (blk < 1024) {
        int w = blk*256 + tid;
        const int* src = mask + (size_t)w * 32;
        unsigned bits = 0;
#pragma unroll
        for (int j = 0; j < 32; j += 4) {
            int4 v = *(const int4*)(src + j);
            bits |= (unsigned)(v.x != 0) << j;
            bits |= (unsigned)(v.y != 0) << (j+1);
            bits |= (unsigned)(v.z != 0) << (j+2);
            bits |= (unsigned)(v.w != 0) << (j+3);
        }
        g_mb[w] = bits;
    } else if (blk < 1536) {
        const int n4 = BB*TT*DMODEL/4;
        for (int i = (blk-1024)*256 + tid; i < n4; i += 512*256) {
            float4 v = ((const float4*)xs)[i];
            ((__half2*)g_xr)[i*2]   = __floats2half2_rn(v.x, v.y);
            ((__half2*)g_xr)[i*2+1] = __floats2half2_rn(v.z, v.w);
        }
    } else if (blk < 1792) {
        for (int e = (blk-1536)*256 + tid; e < 2048*256; e += 256*256) {
            int l = e >> 8, cp = e & 255;
            float freq = expf(-9.210340371976184f * (float)(2*cp) / (float)DMODEL);
            float s, c;
            sincosf((float)(l - (TT - 1)) * freq, &s, &c);
            __half2 v = (l < LPOS) ? __floats2half2_rn(s, c) : __floats2half2_rn(0.f, 0.f);
            ((__half2*)g_pe)[l*(DMODEL/2) + cp] = v;
        }
    } else {
        int wblk = blk - 1792;
        int which = wblk >> 8, rem = wblk & 255;
        const float* src = (which == 0) ? Wq : (which == 1) ? Wk : (which == 2) ? Wv
                         : (which == 3) ? Wo : Wp;
        __half* dst = (which == 0) ? g_wq : (which == 1) ? g_wk : (which == 2) ? g_wv
                    : (which == 3) ? g_wo : g_wp;
        int x0 = (rem & 15)*32, y0 = (rem >> 4)*32;
        int tx = tid & 31, ty = tid >> 5;
#pragma unroll
        for (int i = 0; i < 4; i++)
            tile[ty + 8*i][tx] = src[(size_t)(y0 + ty + 8*i)*512 + x0 + tx];
        __syncthreads();
#pragma unroll
        for (int i = 0; i < 4; i++)
            dst[(size_t)(x0 + ty + 8*i)*512 + y0 + tx] = __float2half_rn(tile[tx][ty + 8*i]);
    }
}

// ============================================================================
// Projections (fp16 mma + ldmatrix, cp.async 2-stage): C = A @ Bt^T, 128x128.
// Layout (bytes): A0@0, A1@18432, B0@36864, B1@55296  (total 73728)
// ============================================================================
#define PROJ_SMEM 73728

__device__ __forceinline__ void proj_prefetch(char* smc, int buf, int tid,
        const __half* Ag, const __half* Bg, int m0, int n0, int k0)
{
    char* aB = smc + buf*18432;
    char* bB = smc + 36864 + buf*18432;
    for (int e = tid; e < 1024; e += 256) {
        int r = e >> 3, ch = (e & 7) * 8;
        cpa16(aB + r*144 + ch*2, Ag + (size_t)(m0 + r)*512 + k0 + ch);
        cpa16(bB + r*144 + ch*2, Bg + (size_t)(n0 + r)*512 + k0 + ch);
    }
}

__device__ __forceinline__ void proj_core(char* smc, int tid,
        const __half* Ag, const __half* Bg, int m0, int n0, float acc[2][8][4])
{
    const int lane = tid & 31, warp = tid >> 5;
    const int wm = warp >> 1, wn = warp & 1;
    const int r8 = lane & 7;
    const uint32_t aoff = (uint32_t)((r8 + ((lane & 8) ? 8 : 0))*144 + ((lane & 16) ? 16 : 0))
                        + (uint32_t)(wm*32*144);
    const uint32_t boff = (uint32_t)((r8 + ((lane & 16) ? 8 : 0))*144 + ((lane & 8) ? 16 : 0))
                        + (uint32_t)(wn*64*144);
    const uint32_t sa = smem_u32(smc), sb = smem_u32(smc + 36864);

    proj_prefetch(smc, 0, tid, Ag, Bg, m0, n0, 0); CP_COMMIT();

    for (int it = 0; it < 8; it++) {
        int buf = it & 1;
        if (it < 7) { proj_prefetch(smc, buf^1, tid, Ag, Bg, m0, n0, (it+1)*64); CP_COMMIT(); }
        if (it < 7) asm volatile("cp.async.wait_group 1;");
        else        asm volatile("cp.async.wait_group 0;");
        __syncthreads();

        const uint32_t aB = sa + buf*18432 + aoff;
        const uint32_t bB = sb + buf*18432 + boff;
#pragma unroll
        for (int kk = 0; kk < 4; kk++) {
            uint32_t a[2][4];
#pragma unroll
            for (int mt = 0; mt < 2; mt++)
                ldsm4(a[mt][0], a[mt][1], a[mt][2], a[mt][3], aB + mt*16*144 + kk*32);
#pragma unroll
            for (int ntp = 0; ntp < 4; ntp++) {
                uint32_t b0, b1, b2, b3;
                ldsm4(b0, b1, b2, b3, bB + ntp*16*144 + kk*32);
                mma16(acc[0][2*ntp],   a[0], b0, b1);
                mma16(acc[0][2*ntp+1], a[0], b2, b3);
                mma16(acc[1][2*ntp],   a[1], b0, b1);
                mma16(acc[1][2*ntp+1], a[1], b2, b3);
            }
        }
        __syncthreads();
    }
}

// ============================================================================
// QKV + positional projection in ONE launch.  grid (64, 4, 4).
// ============================================================================
__global__ __launch_bounds__(256, 2)
void qkvpos_h(const float* __restrict__ ub, const float* __restrict__ vb)
{
    extern __shared__ char smc[];
    const int z = blockIdx.z;
    const int tid = threadIdx.x, lane = tid & 31, warp = tid >> 5;
    const int g = lane >> 2, c = lane & 3;
    const int wm = warp >> 1, wn = warp & 1;

    if (z == 3) {
        if (blockIdx.y != 0) return;
        const int m0 = (blockIdx.x >> 2) * 128;
        const int n0 = (blockIdx.x & 3) * 128;
        float acc[2][8][4] = {};
        proj_core(smc, tid, g_pe, g_wp, m0, n0, acc);
#pragma unroll
        for (int mt = 0; mt < 2; mt++) {
#pragma unroll
            for (int nt = 0; nt < 8; nt++) {
                int n = n0 + wn*64 + nt*8 + 2*c;
                int h = n >> 6, d = n & 63;
#pragma unroll
                for (int half = 0; half < 2; half++) {
                    int l = m0 + wm*32 + mt*16 + g + half*8;
                    if (l >= LPOS) continue;
                    *(__half2*)&g_p[((size_t)h*LPOS + l)*DHEAD + d] =
                        __floats2half2_rn(acc[mt][nt][half*2+0], acc[mt][nt][half*2+1]);
                }
            }
        }
        return;
    }

    const int which = z;
    const __half* W = (which == 0) ? g_wq : (which == 1) ? g_wk : g_wv;
    const int m0 = blockIdx.x * 128;
    const int n0 = blockIdx.y * 128;

    float acc[2][8][4] = {};
    proj_core(smc, tid, g_xr, W, m0, n0, acc);

#pragma unroll
    for (int mt = 0; mt < 2; mt++) {
#pragma unroll
        for (int nt = 0; nt < 8; nt++) {
            int n = n0 + wn*64 + nt*8 + 2*c;
            int h = n >> 6, d = n & 63;
#pragma unroll
            for (int half = 0; half < 2; half++) {
                int m = m0 + wm*32 + mt*16 + g + half*8;
                int bidx = m >> 10, t = m & (TT-1);
                float v0 = acc[mt][nt][half*2+0], v1 = acc[mt][nt][half*2+1];
                if (which == 0) {
                    size_t o = (((size_t)bidx*NH + h)*TT + t)*DHEAD + d;
                    *(__half2*)&g_qu[o] = __floats2half2_rn(v0 + ub[n], v1 + ub[n+1]);
                    *(__half2*)&g_qv[o] = __floats2half2_rn(v0 + vb[n], v1 + vb[n+1]);
                } else if (which == 1) {
                    size_t o = (((size_t)bidx*NH + h)*TT + t)*DHEAD + d;
                    *(__half2*)&g_k[o] = __floats2half2_rn(v0, v1);
                } else {
                    size_t ob = (((size_t)bidx*NH + h)*DHEAD + d)*TT + t;
                    g_vt[ob]      = __float2half_rn(v0);
                    g_vt[ob + TT] = __float2half_rn(v1);
                }
            }
        }
    }
}

__global__ __launch_bounds__(256, 2)
void out_h(float* __restrict__ out)
{
    extern __shared__ char smc[];
    const int m0 = blockIdx.x * 128;
    const int n0 = blockIdx.y * 128;
    const int tid = threadIdx.x, lane = tid & 31, warp = tid >> 5;
    const int g = lane >> 2, c = lane & 3;
    const int wm = warp >> 1, wn = warp & 1;

    float acc[2][8][4] = {};
    proj_core(smc, tid, g_z, g_wo, m0, n0, acc);

#pragma unroll
    for (int mt = 0; mt < 2; mt++) {
#pragma unroll
        for (int nt = 0; nt < 8; nt++) {
            int n = n0 + wn*64 + nt*8 + 2*c;
#pragma unroll
            for (int half = 0; half < 2; half++) {
                int m = m0 + wm*32 + mt*16 + g + half*8;
                *(float2*)&out[(size_t)m*DMODEL + n] =
                    make_float2(acc[mt][nt][half*2+0], acc[mt][nt][half*2+1]);
            }
        }
    }
}

// ============================================================================
// Fused attention v6: SWIZZLED 128B-row tiles, 256-row circular P window
// (prefetch distance 192), 2 CTAs/SM, ldmatrix, exp2 softmax.
// smem bytes: K 2x8192 @0, V 2x8192 @16384, P 256x128 @32768,
//             BD f32 128x84 @65536 -> total 108544  (2 CTAs/SM)
// Swizzle: 16B chunk at (row, ch) stored at row*128 + ((ch*16) ^ ((row&7)<<4)).
// ============================================================================
#define ATTN_SMEM 108544

__global__ __launch_bounds__(256, 2)
void attn_h()
{
    extern __shared__ char smc[];
    float* sBD = (float*)(smc + 65536);

    const int tid = threadIdx.x, lane = tid & 31, warp = tid >> 5;
    const int g = lane >> 2, c = lane & 3;
    const int t0 = blockIdx.x * 128;
    const int bh = blockIdx.y;
    const int b = bh >> 3, h = bh & 7;
    const int rl = warp*16 + g;
    const int rh = rl + 8;
    const int tb = 14 - 2*warp;   // first BD n8-tile for this warp (10 tiles)
    const int r8 = lane & 7;
    const uint32_t xr8 = (uint32_t)(r8 << 4);                 // swizzle per-lane XOR
    const uint32_t pk = (lane & 8) ? 16u : 0u;                // k-half select
    const uint32_t rowsel = (uint32_t)(r8 + ((lane & 16) ? 8 : 0)); // contiguous-tile row
    const uint32_t sk = smem_u32(smc);
    const uint32_t sv = smem_u32(smc + 16384);
    const uint32_t sp = smem_u32(smc + 32768);

    const __half* qu  = g_qu + ((size_t)bh * TT + t0) * DHEAD;
    const __half* qv  = g_qv + ((size_t)bh * TT + t0) * DHEAD;
    const __half* kp  = g_k  + (size_t)bh * TT * DHEAD;
    const __half* vtp = g_vt + (size_t)bh * DHEAD * TT;
    const __half* pp  = g_p  + (size_t)h * LPOS * DHEAD;
    const int l00 = 896 - t0;
    const int grmax = 1150 + t0;   // last valid relative P row (l00+gr <= 2046)

    // prefill: P rows 0..191 (slots 0..191), K/V tile 0 — all swizzled
    for (int e = tid; e < 192*8; e += 256) {
        int r = e >> 3, ch = e & 7;
        uint32_t woff = (uint32_t)(ch*16) ^ (uint32_t)((r & 7) << 4);
        cpa16(smc + 32768 + r*128 + woff, pp + (size_t)(l00 + r)*DHEAD + ch*8);
    }
    for (int e = tid; e < 512; e += 256) {
        int r = e >> 3, ch = e & 7;
        uint32_t woff = (uint32_t)(ch*16) ^ (uint32_t)((r & 7) << 4);
        cpa16(smc + r*128 + woff, kp + (size_t)r*DHEAD + ch*8);
        cpa16(smc + 16384 + r*128 + woff, vtp + (size_t)r*TT + ch*8);
    }
    CP_COMMIT();

    // Q fragments (half2-packed, 4 k16 steps)
    const uint32_t* qu32 = (const uint32_t*)qu;
    const uint32_t* qv32 = (const uint32_t*)qv;
    uint32_t quf[4][4], qvf[4][4];
#pragma unroll
    for (int kk = 0; kk < 4; kk++) {
        quf[kk][0] = qu32[rl*32 + kk*8 + c];
        quf[kk][1] = qu32[rh*32 + kk*8 + c];
        quf[kk][2] = qu32[rl*32 + kk*8 + c + 4];
        quf[kk][3] = qu32[rh*32 + kk*8 + c + 4];
        qvf[kk][0] = qv32[rl*32 + kk*8 + c];
        qvf[kk][1] = qv32[rh*32 + kk*8 + c];
        qvf[kk][2] = qv32[rl*32 + kk*8 + c + 4];
        qvf[kk][3] = qv32[rh*32 + kk*8 + c + 4];
    }

    float o[8][4] = {};
    float rmax = -1e30f;
    float rsum_lo = 0.f, rsum_hi = 0.f;

    for (int it = 0; it < 16; it++) {
        const int buf = it & 1;
        const int s0 = it * 64;

        if (it < 15) {
            char* bK = smc + (buf^1)*8192;
            char* bV = smc + 16384 + (buf^1)*8192;
            for (int e = tid; e < 512; e += 256) {
                int r = e >> 3, ch = e & 7;
                uint32_t woff = (uint32_t)(ch*16) ^ (uint32_t)((r & 7) << 4);
                cpa16(bK + r*128 + woff, kp + (size_t)(s0 + 64 + r)*DHEAD + ch*8);
                cpa16(bV + r*128 + woff, vtp + (size_t)r*TT + s0 + 64 + ch*8);
                // P rows it*64+192+r (64 rows), first used at it+1
                int gr = s0 + 192 + r;
                if (gr <= grmax) {
                    int slot = gr & 255;
                    uint32_t pwoff = (uint32_t)(ch*16) ^ (uint32_t)((slot & 7) << 4);
                    cpa16(smc + 32768 + slot*128 + pwoff,
                          pp + (size_t)(l00 + gr)*DHEAD + ch*8);
                }
            }
            CP_COMMIT();
        }
        if (it < 15) asm volatile("cp.async.wait_group 1;");
        else         asm volatile("cp.async.wait_group 0;");
        __syncthreads();

        // ---- BD band GEMM: 10 n8-tiles = 5 ldmatrix quads, 4 k16 steps ----
        {
            const int p5 = (it & 3) * 64;
            uint32_t prow[5];
#pragma unroll
            for (int ntp = 0; ntp < 5; ntp++) {
                int jsel = 2*ntp + ((lane & 16) ? 1 : 0);
                int rb = (p5 + (tb + jsel)*8) & 255;
                prow[ntp] = sp + (uint32_t)(rb + r8)*128;
            }
            float bd[10][4] = {};
#pragma unroll
            for (int kk = 0; kk < 4; kk++) {
                const uint32_t kx = ((uint32_t)(kk*32) + pk) ^ xr8;
#pragma unroll
                for (int ntp = 0; ntp < 5; ntp++) {
                    uint32_t b0, b1, b2, b3;
                    ldsm4(b0, b1, b2, b3, prow[ntp] + kx);
                    mma16(bd[2*ntp],   qvf[kk], b0, b1);
                    mma16(bd[2*ntp+1], qvf[kk], b2, b3);
                }
            }
#pragma unroll
            for (int j = 0; j < 10; j++) {
                int cb = j*8 + 2*c;
                sBD[rl*BDST + cb]   = bd[j][0];
                sBD[rl*BDST + cb+1] = bd[j][1];
                sBD[rh*BDST + cb]   = bd[j][2];
                sBD[rh*BDST + cb+1] = bd[j][3];
            }
        }
        __syncwarp();

        // ---- AC GEMM via ldmatrix (swizzled) ----
        float acc[8][4] = {};
        const uint32_t kB = sk + buf*8192 + rowsel*128;
#pragma unroll
        for (int kk = 0; kk < 4; kk++) {
            const uint32_t kx = ((uint32_t)(kk*32) + pk) ^ xr8;
#pragma unroll
            for (int ntp = 0; ntp < 4; ntp++) {
                uint32_t b0, b1, b2, b3;
                ldsm4(b0, b1, b2, b3, kB + ntp*2048 + kx);
                mma16(acc[2*ntp],   quf[kk], b0, b1);
                mma16(acc[2*ntp+1], quf[kk], b2, b3);
            }
        }

        // ---- mask bits ----
        uint2 mwl = *(const uint2*)(g_mb + ((size_t)b*TT + t0 + rl)*32 + (s0 >> 5));
        uint2 mwh = *(const uint2*)(g_mb + ((size_t)b*TT + t0 + rh)*32 + (s0 >> 5));

        // ---- combine ac + shifted bd, mask, scale (exp2 domain), softmax ----
        const int baseL = rl*BDST - g + 15;
        const int baseH = rh*BDST - g + 7;
        float mx = -1e30f;
#pragma unroll
        for (int nt = 0; nt < 8; nt++) {
            int cb = nt*8 + 2*c;
            unsigned wl = (cb & 32) ? mwl.y : mwl.x;
            unsigned wh = (cb & 32) ? mwh.y : mwh.x;
            int sh = cb & 31;
            float v;
            v = (acc[nt][0] + sBD[baseL + cb])   * SCL;
            acc[nt][0] = ((wl >> sh)     & 1) ? v : -1e30f;
            v = (acc[nt][1] + sBD[baseL + cb+1]) * SCL;
            acc[nt][1] = ((wl >> (sh+1)) & 1) ? v : -1e30f;
            v = (acc[nt][2] + sBD[baseH + cb])   * SCL;
            acc[nt][2] = ((wh >> sh)     & 1) ? v : -1e30f;
            v = (acc[nt][3] + sBD[baseH + cb+1]) * SCL;
            acc[nt][3] = ((wh >> (sh+1)) & 1) ? v : -1e30f;
            mx = fmaxf(mx, fmaxf(fmaxf(acc[nt][0], acc[nt][1]),
                                 fmaxf(acc[nt][2], acc[nt][3])));
        }
        mx = fmaxf(mx, __shfl_xor_sync(0xffffffffu, mx, 1));
        mx = fmaxf(mx, __shfl_xor_sync(0xffffffffu, mx, 2));

        float nm = fmaxf(rmax, mx);
        float corr = exp2f(rmax - nm);
        rmax = nm;

        // ---- exp2 + pack S fragments in registers ----
        uint32_t sfl[8], sfh[8];
        float ts_lo = 0.f, ts_hi = 0.f;
#pragma unroll
        for (int nt = 0; nt < 8; nt++) {
            float p0 = exp2f(acc[nt][0] - nm);
            float p1 = exp2f(acc[nt][1] - nm);
            float p2 = exp2f(acc[nt][2] - nm);
            float p3 = exp2f(acc[nt][3] - nm);
            ts_lo += p0 + p1; ts_hi += p2 + p3;
            __half2 hl = __floats2half2_rn(p0, p1);
            __half2 hh = __floats2half2_rn(p2, p3);
            sfl[nt] = *(uint32_t*)&hl;
            sfh[nt] = *(uint32_t*)&hh;
            o[nt][0] *= corr; o[nt][1] *= corr;
            o[nt][2] *= corr; o[nt][3] *= corr;
        }
        ts_lo += __shfl_xor_sync(0xffffffffu, ts_lo, 1);
        ts_lo += __shfl_xor_sync(0xffffffffu, ts_lo, 2);
        ts_hi += __shfl_xor_sync(0xffffffffu, ts_hi, 1);
        ts_hi += __shfl_xor_sync(0xffffffffu, ts_hi, 2);
        rsum_lo = rsum_lo * corr + ts_lo;
        rsum_hi = rsum_hi * corr + ts_hi;

        // ---- PV GEMM via ldmatrix (swizzled): O += exp(S) @ V ----
        const uint32_t vB = sv + buf*8192 + rowsel*128;
#pragma unroll
        for (int kk = 0; kk < 4; kk++) {
            uint32_t a[4] = { sfl[2*kk], sfh[2*kk], sfl[2*kk+1], sfh[2*kk+1] };
            const uint32_t kx = ((uint32_t)(kk*32) + pk) ^ xr8;
#pragma unroll
            for (int ntp = 0; ntp < 4; ntp++) {
                uint32_t b0, b1, b2, b3;
                ldsm4(b0, b1, b2, b3, vB + ntp*2048 + kx);
                mma16(o[2*ntp],   a, b0, b1);
                mma16(o[2*ntp+1], a, b2, b3);
            }
        }
        __syncthreads();
    }

    // ---- normalize + write z (B,T,H,dh) fp16 ----
    float inv_lo = 1.f / rsum_lo, inv_hi = 1.f / rsum_hi;
#pragma unroll
    for (int nt = 0; nt < 8; nt++) {
        int d = nt*8 + 2*c;
        *(__half2*)&g_z[(((size_t)b*TT + (t0+rl))*NH + h)*DHEAD + d] =
            __floats2half2_rn(o[nt][0]*inv_lo, o[nt][1]*inv_lo);
        *(__half2*)&g_z[(((size_t)b*TT + (t0+rh))*NH + h)*DHEAD + d] =
            __floats2half2_rn(o[nt][2]*inv_hi, o[nt][3]*inv_hi);
    }
}

// ============================================================================
extern "C" void kernel_launch(void* const* d_in, const int* in_sizes, int n_in,
                              void* d_out, int out_size)
{
    const float* xs   = (const float*)d_in[0];
    const int*   mask = (const int*)  d_in[1];
    const float* Wq   = (const float*)d_in[2];
    const float* Wk   = (const float*)d_in[3];
    const float* Wv   = (const float*)d_in[4];
    const float* Wpos = (const float*)d_in[5];
    const float* Wout = (const float*)d_in[6];
    const float* ub   = (const float*)d_in[7];
    const float* vb   = (const float*)d_in[8];
    float* out = (float*)d_out;

    cudaFuncSetAttribute(attn_h,   cudaFuncAttributeMaxDynamicSharedMemorySize, ATTN_SMEM);
    cudaFuncSetAttribute(qkvpos_h, cudaFuncAttributeMaxDynamicSharedMemorySize, PROJ_SMEM);
    cudaFuncSetAttribute(out_h,    cudaFuncAttributeMaxDynamicSharedMemorySize, PROJ_SMEM);

    prep_all<<<3072, 256>>>(xs, mask, Wq, Wk, Wv, Wout, Wpos);
    qkvpos_h<<<dim3(64, 4, 4), 256, PROJ_SMEM>>>(ub, vb);
    attn_h<<<dim3(8, 64), 256, ATTN_SMEM>>>();
    out_h<<<dim3(64, 4), 256, PROJ_SMEM>>>(out);
}